// round 8
// baseline (speedup 1.0000x reference)
#include <cuda_runtime.h>
#include <math.h>

// Problem constants
#define NB    4
#define DIMC  384
#define RES   56
#define NTOK  3136          // 56*56
#define TD    192
#define CSC   96

#define LOG2E 1.4426950408889634f
#define CS_SCALE 0.14433756729740643f   // 1/sqrt(48)
#define DN_SCALE 0.125f                 // 1/sqrt(64)

// ---------------------------------------------------------------------------
// Scratch (static device arrays; no allocation anywhere)
// ---------------------------------------------------------------------------
__device__ float g_wc[2][576 * 384];                 // combined (qkv_w @ proj_w), [line][j*384+c]
__device__ float g_qkv[2][NB * NTOK * 576];          // [line][((b*3136)+n)*576 + j]

// ---------------------------------------------------------------------------
// Kernel 1: combined weights  Wc[j][c] = sum_t qkv_w[j][t] * proj_w[t][c]
// grid (576, 2), block 384
// ---------------------------------------------------------------------------
__global__ void combine_w_kernel(const float* __restrict__ p1,
                                 const float* __restrict__ p2,
                                 const float* __restrict__ qu,
                                 const float* __restrict__ qd) {
    int j = blockIdx.x;
    int line = blockIdx.y;
    int c = threadIdx.x;                 // 0..383
    const float* qw = line ? qd : qu;    // [576][192]
    const float* pw = line ? p2 : p1;    // [192][384]
    const float* qrow = qw + j * 192;
    float s = 0.f;
#pragma unroll 8
    for (int t = 0; t < 192; t++)
        s += qrow[t] * pw[t * 384 + c];
    g_wc[line][j * 384 + c] = s;
}

// ---------------------------------------------------------------------------
// Kernel 2: qkv GEMM   out[b,n,j] = sum_c xa[b,c,n] * Wc[line][j,c]
// grid (49, 9, 8=b*2+line), block 256
// ---------------------------------------------------------------------------
__global__ void __launch_bounds__(256) qkv_gemm_kernel(const float* __restrict__ xa) {
    __shared__ float Ash[16][64];
    __shared__ float Wsh[64][17];

    int z = blockIdx.z;
    int bb = z >> 1, line = z & 1;
    int n0 = blockIdx.x * 64;
    int j0 = blockIdx.y * 64;
    const float* A = xa + (size_t)bb * DIMC * NTOK;   // A[c][n]
    const float* W = g_wc[line];                      // W[j][c]
    int tid = threadIdx.x;
    int tn = tid & 15, tj = tid >> 4;

    int la_c = tid >> 4;          // 0..15
    int la_n = (tid & 15) * 4;    // 0..60
    int lw_j = tid >> 2;          // 0..63
    int lw_c = (tid & 3) * 4;     // 0..12

    float acc[4][4] = {};

    for (int c0 = 0; c0 < 384; c0 += 16) {
        float4 av = *(const float4*)&A[(size_t)(c0 + la_c) * NTOK + n0 + la_n];
        *(float4*)&Ash[la_c][la_n] = av;
        float4 wv = *(const float4*)&W[(j0 + lw_j) * 384 + c0 + lw_c];
        Wsh[lw_j][lw_c + 0] = wv.x;
        Wsh[lw_j][lw_c + 1] = wv.y;
        Wsh[lw_j][lw_c + 2] = wv.z;
        Wsh[lw_j][lw_c + 3] = wv.w;
        __syncthreads();
#pragma unroll
        for (int cc = 0; cc < 16; cc++) {
            float4 a4 = *(const float4*)&Ash[cc][tn * 4];
            float b0 = Wsh[tj * 4 + 0][cc];
            float b1 = Wsh[tj * 4 + 1][cc];
            float b2 = Wsh[tj * 4 + 2][cc];
            float b3 = Wsh[tj * 4 + 3][cc];
            acc[0][0] += a4.x * b0; acc[0][1] += a4.x * b1; acc[0][2] += a4.x * b2; acc[0][3] += a4.x * b3;
            acc[1][0] += a4.y * b0; acc[1][1] += a4.y * b1; acc[1][2] += a4.y * b2; acc[1][3] += a4.y * b3;
            acc[2][0] += a4.z * b0; acc[2][1] += a4.z * b1; acc[2][2] += a4.z * b2; acc[2][3] += a4.z * b3;
            acc[3][0] += a4.w * b0; acc[3][1] += a4.w * b1; acc[3][2] += a4.w * b2; acc[3][3] += a4.w * b3;
        }
        __syncthreads();
    }

    float* out = g_qkv[line] + (size_t)bb * NTOK * 576;
#pragma unroll
    for (int i = 0; i < 4; i++) {
        float4 o = make_float4(acc[i][0], acc[i][1], acc[i][2], acc[i][3]);
        *(float4*)&out[(size_t)(n0 + tn * 4 + i) * 576 + j0 + tj * 4] = o;
    }
}

// ---------------------------------------------------------------------------
// Kernel 3: CSWin attention + LePE (upper line)
// grid (8, 2, 8=b*2+branch), block 256, dyn smem = 2*392*48*4
// ---------------------------------------------------------------------------
#define CS_SMEM (2 * 392 * 48 * 4)

__global__ void __launch_bounds__(256) cswin_kernel(const float* __restrict__ lw0,
                                                    const float* __restrict__ lb0,
                                                    const float* __restrict__ lw1,
                                                    const float* __restrict__ lb1,
                                                    float* __restrict__ out) {
    extern __shared__ float sh[];
    float* Ks = sh;                 // [392][48]
    float* Vs = sh + 392 * 48;      // [392][48]
    __shared__ float wsh[48][9];
    __shared__ float bsh[48];

    int win = blockIdx.x;
    int hh  = blockIdx.y;
    int z   = blockIdx.z;
    int bb  = z >> 1, br = z & 1;
    int SW = br ? 56 : 7;
    int SH = br ? 7 : 56;
    int choff = br * CSC + hh * 48;
    const float* qkv = g_qkv[0] + (size_t)bb * NTOK * 576;
    int tid = threadIdx.x;

    for (int e = tid; e < 392 * 12; e += 256) {
        int t = e / 12, d4 = (e % 12) * 4;
        int hl = t / SW, wl = t % SW;
        int h = br ? win * 7 + hl : hl;
        int w = br ? wl : win * 7 + wl;
        int n = h * RES + w;
        const float* row = qkv + (size_t)n * 576 + choff;
        *(float4*)&Ks[t * 48 + d4] = *(const float4*)&row[192 + d4];
        *(float4*)&Vs[t * 48 + d4] = *(const float4*)&row[384 + d4];
    }
    const float* lw = br ? lw1 : lw0;
    const float* lb = br ? lb1 : lb0;
    for (int e = tid; e < 48 * 9; e += 256) {
        int d = e / 9, k = e % 9;
        wsh[d][k] = lw[(hh * 48 + d) * 9 + k];
    }
    if (tid < 48) bsh[tid] = lb[hh * 48 + tid];
    __syncthreads();

    const float qscale = CS_SCALE * LOG2E;

    for (int r = tid; r < 392; r += 256) {
        int hl = r / SW, wl = r % SW;
        int h = br ? win * 7 + hl : hl;
        int w = br ? wl : win * 7 + wl;
        int n = h * RES + w;
        const float* qrow = qkv + (size_t)n * 576 + choff;

        float q[48];
#pragma unroll
        for (int d4 = 0; d4 < 48; d4 += 4) {
            float4 v = *(const float4*)&qrow[d4];
            q[d4 + 0] = v.x * qscale; q[d4 + 1] = v.y * qscale;
            q[d4 + 2] = v.z * qscale; q[d4 + 3] = v.w * qscale;
        }
        float m = -1e30f, l = 0.f;
        float acc[48];
#pragma unroll
        for (int d = 0; d < 48; d++) acc[d] = 0.f;

        for (int c0 = 0; c0 < 392; c0 += 14) {
            float s[14];
#pragma unroll
            for (int i = 0; i < 14; i++) {
                const float* kr = &Ks[(c0 + i) * 48];
                float sv = 0.f;
#pragma unroll
                for (int d4 = 0; d4 < 48; d4 += 4) {
                    float4 kv = *(const float4*)&kr[d4];
                    sv += q[d4] * kv.x + q[d4 + 1] * kv.y + q[d4 + 2] * kv.z + q[d4 + 3] * kv.w;
                }
                s[i] = sv;
            }
            float cm = s[0];
#pragma unroll
            for (int i = 1; i < 14; i++) cm = fmaxf(cm, s[i]);
            float mnew = fmaxf(m, cm);
            float rs = exp2f(m - mnew);
            l *= rs;
#pragma unroll
            for (int d = 0; d < 48; d++) acc[d] *= rs;
#pragma unroll
            for (int i = 0; i < 14; i++) {
                float p = exp2f(s[i] - mnew);
                l += p;
                const float* vr = &Vs[(c0 + i) * 48];
#pragma unroll
                for (int d4 = 0; d4 < 48; d4 += 4) {
                    float4 vv = *(const float4*)&vr[d4];
                    acc[d4 + 0] += p * vv.x; acc[d4 + 1] += p * vv.y;
                    acc[d4 + 2] += p * vv.z; acc[d4 + 3] += p * vv.w;
                }
            }
            m = mnew;
        }
        float inv = 1.f / l;

        float lep[48];
#pragma unroll
        for (int d = 0; d < 48; d++) lep[d] = bsh[d];
#pragma unroll
        for (int dy = -1; dy <= 1; dy++) {
#pragma unroll
            for (int dx = -1; dx <= 1; dx++) {
                int h2 = hl + dy, w2 = wl + dx;
                if (h2 < 0 || h2 >= SH || w2 < 0 || w2 >= SW) continue;
                const float* vr = &Vs[(h2 * SW + w2) * 48];
                int tap = (dy + 1) * 3 + (dx + 1);
#pragma unroll
                for (int d = 0; d < 48; d += 4) {
                    float4 vv = *(const float4*)&vr[d];
                    lep[d + 0] += vv.x * wsh[d + 0][tap];
                    lep[d + 1] += vv.y * wsh[d + 1][tap];
                    lep[d + 2] += vv.z * wsh[d + 2][tap];
                    lep[d + 3] += vv.w * wsh[d + 3][tap];
                }
            }
        }

        float* obase = out + ((size_t)bb * DIMC + br * CSC + hh * 48) * NTOK + n;
#pragma unroll
        for (int d = 0; d < 48; d++)
            obase[(size_t)d * NTOK] = acc[d] * inv + lep[d];
    }
}

// ---------------------------------------------------------------------------
// Kernel 4: global multi-head attention (lower line), flash-style.
// THREAD-PAIR d-SPLIT: 2 threads per query row, each owns 32 of 64 dims
// (q_half/acc_half in regs, QK dot combined via shfl_xor). Halves register
// pressure -> 2 CTAs x 256 thr / SM (16 warps, 25% occ vs 12.4% before).
// cp.async double-buffered K/V in dynamic smem.
// grid (25, 3, 4), block 256, dyn smem = 4*64*64*4 = 65536
// ---------------------------------------------------------------------------
#define DN_SMEM (4 * 64 * 64 * 4)

__device__ __forceinline__ void cp_async16(void* smem_dst, const void* gsrc) {
    unsigned s = (unsigned)__cvta_generic_to_shared(smem_dst);
    asm volatile("cp.async.cg.shared.global [%0], [%1], 16;\n" :: "r"(s), "l"(gsrc));
}

__global__ void __launch_bounds__(256, 2) attn_dn_kernel(float* __restrict__ out) {
    extern __shared__ float dnsh[];
    float* Ksb[2] = { dnsh,             dnsh + 64 * 64 };
    float* Vsb[2] = { dnsh + 2*64*64,   dnsh + 3*64*64 };

    int qt = blockIdx.x, hh = blockIdx.y, bb = blockIdx.z;
    const float* qkv = g_qkv[1] + (size_t)bb * NTOK * 576;
    int tid = threadIdx.x;
    int pair = tid >> 1;            // query row within tile (0..127)
    int half = tid & 1;             // which 32-dim half this thread owns
    int r = qt * 128 + pair;
    bool active = r < NTOK;         // whole warps are uniformly active/inactive

    const float qscale = DN_SCALE * LOG2E;
    float q[32], acc[32];
    float m = -1e30f, l = 0.f;
#pragma unroll
    for (int d = 0; d < 32; d++) acc[d] = 0.f;
    if (active) {
        const float* qrow = qkv + (size_t)r * 576 + hh * 64 + half * 32;
#pragma unroll
        for (int d4 = 0; d4 < 32; d4 += 4) {
            float4 v = *(const float4*)&qrow[d4];
            q[d4 + 0] = v.x * qscale; q[d4 + 1] = v.y * qscale;
            q[d4 + 2] = v.z * qscale; q[d4 + 3] = v.w * qscale;
        }
    }

    // --- async tile loader: 256 threads, each copies a quarter row of K and V
    int lt = tid >> 2;              // 0..63  token
    int ld = (tid & 3) * 16;        // quarter-row start
    auto load_tile = [&](int kt, int buf) {
        const float* row = qkv + (size_t)(kt * 64 + lt) * 576 + hh * 64 + ld;
        float* kdst = Ksb[buf] + lt * 64 + ld;
        float* vdst = Vsb[buf] + lt * 64 + ld;
#pragma unroll
        for (int i = 0; i < 4; i++) {
            cp_async16(kdst + i * 4, row + 192 + i * 4);
            cp_async16(vdst + i * 4, row + 384 + i * 4);
        }
        asm volatile("cp.async.commit_group;\n" ::: "memory");
    };

    load_tile(0, 0);

    for (int kt = 0; kt < 49; kt++) {
        int cur = kt & 1;
        if (kt < 48) {
            load_tile(kt + 1, cur ^ 1);
            asm volatile("cp.async.wait_group 1;\n" ::: "memory");
        } else {
            asm volatile("cp.async.wait_group 0;\n" ::: "memory");
        }
        __syncthreads();

        const float* Kcur = Ksb[cur] + half * 32;
        const float* Vcur = Vsb[cur] + half * 32;
        if (active) {
#pragma unroll 1
            for (int c0 = 0; c0 < 64; c0 += 16) {
                float s[16];
#pragma unroll
                for (int i = 0; i < 16; i++) {
                    const float* kr = Kcur + (c0 + i) * 64;
                    float sv = 0.f;
#pragma unroll
                    for (int d4 = 0; d4 < 32; d4 += 4) {
                        float4 kv = *(const float4*)&kr[d4];
                        sv += q[d4] * kv.x + q[d4 + 1] * kv.y + q[d4 + 2] * kv.z + q[d4 + 3] * kv.w;
                    }
                    // combine the two 32-dim partials within the pair
                    s[i] = sv + __shfl_xor_sync(0xffffffffu, sv, 1);
                }
                float cm = s[0];
#pragma unroll
                for (int i = 1; i < 16; i++) cm = fmaxf(cm, s[i]);
                float mnew = fmaxf(m, cm);
                float rs = exp2f(m - mnew);
                l *= rs;
#pragma unroll
                for (int d = 0; d < 32; d++) acc[d] *= rs;
#pragma unroll
                for (int i = 0; i < 16; i++) {
                    float p = exp2f(s[i] - mnew);
                    l += p;                       // duplicated in both pair threads
                    const float* vr = Vcur + (c0 + i) * 64;
#pragma unroll
                    for (int d4 = 0; d4 < 32; d4 += 4) {
                        float4 vv = *(const float4*)&vr[d4];
                        acc[d4 + 0] += p * vv.x; acc[d4 + 1] += p * vv.y;
                        acc[d4 + 2] += p * vv.z; acc[d4 + 3] += p * vv.w;
                    }
                }
                m = mnew;
            }
        }
        __syncthreads();   // all threads done reading buf `cur` before refill
    }

    if (active) {
        float inv = 1.f / l;
        float* ob = out + ((size_t)bb * DIMC + TD + hh * 64 + half * 32) * NTOK + r;
#pragma unroll
        for (int d = 0; d < 32; d++)
            ob[(size_t)d * NTOK] = acc[d] * inv;
    }
}

// ---------------------------------------------------------------------------
// Launch
// ---------------------------------------------------------------------------
extern "C" void kernel_launch(void* const* d_in, const int* in_sizes, int n_in,
                              void* d_out, int out_size) {
    const float* xa      = (const float*)d_in[0];
    const float* proj1_w = (const float*)d_in[1];
    const float* proj2_w = (const float*)d_in[2];
    const float* qkv_u_w = (const float*)d_in[3];
    const float* qkv_d_w = (const float*)d_in[4];
    const float* lepe_w0 = (const float*)d_in[5];
    const float* lepe_b0 = (const float*)d_in[6];
    const float* lepe_w1 = (const float*)d_in[7];
    const float* lepe_b1 = (const float*)d_in[8];
    float* out = (float*)d_out;

    // 1) combined weights (Wqkv @ Wproj)
    combine_w_kernel<<<dim3(576, 2), 384>>>(proj1_w, proj2_w, qkv_u_w, qkv_d_w);

    // 2) fused proj+qkv GEMM for both lines
    qkv_gemm_kernel<<<dim3(49, 9, 8), 256>>>(xa);

    // 3) CSWin upper line (writes channels [0,192))
    cudaFuncSetAttribute(cswin_kernel, cudaFuncAttributeMaxDynamicSharedMemorySize, CS_SMEM);
    cswin_kernel<<<dim3(8, 2, 8), 256, CS_SMEM>>>(lepe_w0, lepe_b0, lepe_w1, lepe_b1, out);

    // 4) global attention lower line (writes channels [192,384))
    cudaFuncSetAttribute(attn_dn_kernel, cudaFuncAttributeMaxDynamicSharedMemorySize, DN_SMEM);
    attn_dn_kernel<<<dim3(25, 3, 4), 256, DN_SMEM>>>(out);
}

// round 9
// speedup vs baseline: 5.1845x; 5.1845x over previous
#include <cuda_runtime.h>
#include <math.h>

// Problem constants
#define NB    4
#define DIMC  384
#define RES   56
#define NTOK  3136          // 56*56
#define TD    192
#define CSC   96

#define LOG2E 1.4426950408889634f
#define CS_SCALE 0.14433756729740643f   // 1/sqrt(48)
#define DN_SCALE 0.125f                 // 1/sqrt(64)

// ---------------------------------------------------------------------------
// Scratch (static device arrays; no allocation anywhere)
// ---------------------------------------------------------------------------
__device__ float g_wc[2][576 * 384];                 // combined (qkv_w @ proj_w)
__device__ float g_qkv[2][NB * NTOK * 576];          // [line][((b*3136)+n)*576 + j]

// ---------------------------------------------------------------------------
// Kernel 1: combined weights  Wc[j][c] = sum_t qkv_w[j][t] * proj_w[t][c]
// ---------------------------------------------------------------------------
__global__ void combine_w_kernel(const float* __restrict__ p1,
                                 const float* __restrict__ p2,
                                 const float* __restrict__ qu,
                                 const float* __restrict__ qd) {
    int j = blockIdx.x;
    int line = blockIdx.y;
    int c = threadIdx.x;
    const float* qw = line ? qd : qu;
    const float* pw = line ? p2 : p1;
    const float* qrow = qw + j * 192;
    float s = 0.f;
#pragma unroll 8
    for (int t = 0; t < 192; t++)
        s += qrow[t] * pw[t * 384 + c];
    g_wc[line][j * 384 + c] = s;
}

// ---------------------------------------------------------------------------
// Kernel 2: qkv GEMM  (unchanged from R7-passing version)
// ---------------------------------------------------------------------------
__global__ void __launch_bounds__(256) qkv_gemm_kernel(const float* __restrict__ xa) {
    __shared__ float Ash[16][64];
    __shared__ float Wsh[64][17];

    int z = blockIdx.z;
    int bb = z >> 1, line = z & 1;
    int n0 = blockIdx.x * 64;
    int j0 = blockIdx.y * 64;
    const float* A = xa + (size_t)bb * DIMC * NTOK;
    const float* W = g_wc[line];
    int tid = threadIdx.x;
    int tn = tid & 15, tj = tid >> 4;

    int la_c = tid >> 4;
    int la_n = (tid & 15) * 4;
    int lw_j = tid >> 2;
    int lw_c = (tid & 3) * 4;

    float acc[4][4] = {};

    for (int c0 = 0; c0 < 384; c0 += 16) {
        float4 av = *(const float4*)&A[(size_t)(c0 + la_c) * NTOK + n0 + la_n];
        *(float4*)&Ash[la_c][la_n] = av;
        float4 wv = *(const float4*)&W[(j0 + lw_j) * 384 + c0 + lw_c];
        Wsh[lw_j][lw_c + 0] = wv.x;
        Wsh[lw_j][lw_c + 1] = wv.y;
        Wsh[lw_j][lw_c + 2] = wv.z;
        Wsh[lw_j][lw_c + 3] = wv.w;
        __syncthreads();
#pragma unroll
        for (int cc = 0; cc < 16; cc++) {
            float4 a4 = *(const float4*)&Ash[cc][tn * 4];
            float b0 = Wsh[tj * 4 + 0][cc];
            float b1 = Wsh[tj * 4 + 1][cc];
            float b2 = Wsh[tj * 4 + 2][cc];
            float b3 = Wsh[tj * 4 + 3][cc];
            acc[0][0] += a4.x * b0; acc[0][1] += a4.x * b1; acc[0][2] += a4.x * b2; acc[0][3] += a4.x * b3;
            acc[1][0] += a4.y * b0; acc[1][1] += a4.y * b1; acc[1][2] += a4.y * b2; acc[1][3] += a4.y * b3;
            acc[2][0] += a4.z * b0; acc[2][1] += a4.z * b1; acc[2][2] += a4.z * b2; acc[2][3] += a4.z * b3;
            acc[3][0] += a4.w * b0; acc[3][1] += a4.w * b1; acc[3][2] += a4.w * b2; acc[3][3] += a4.w * b3;
        }
        __syncthreads();
    }

    float* out = g_qkv[line] + (size_t)bb * NTOK * 576;
#pragma unroll
    for (int i = 0; i < 4; i++) {
        float4 o = make_float4(acc[i][0], acc[i][1], acc[i][2], acc[i][3]);
        *(float4*)&out[(size_t)(n0 + tn * 4 + i) * 576 + j0 + tj * 4] = o;
    }
}

// ---------------------------------------------------------------------------
// Kernel 2b: round K/V channels of line 1 to tf32 (RN), in place.
// After this, HMMA's internal tf32 truncation is exact (low bits already 0).
// total NB*NTOK rows x 384 cols -> 1,204,224 float4
// ---------------------------------------------------------------------------
__device__ __forceinline__ unsigned f2tf32(float f) {
    unsigned u;
    asm("cvt.rna.tf32.f32 %0, %1;" : "=r"(u) : "f"(f));
    return u;
}

__global__ void __launch_bounds__(256) round_kv_kernel() {
    int idx = blockIdx.x * 256 + threadIdx.x;          // float4 index
    if (idx >= NB * NTOK * 96) return;
    int row = idx / 96, c4 = idx % 96;
    float4* p = (float4*)&g_qkv[1][(size_t)row * 576 + 192 + c4 * 4];
    float4 v = *p;
    v.x = __uint_as_float(f2tf32(v.x));
    v.y = __uint_as_float(f2tf32(v.y));
    v.z = __uint_as_float(f2tf32(v.z));
    v.w = __uint_as_float(f2tf32(v.w));
    *p = v;
}

// ---------------------------------------------------------------------------
// Kernel 3: CSWin attention + LePE (unchanged from R7-passing version)
// ---------------------------------------------------------------------------
#define CS_SMEM (2 * 392 * 48 * 4)

__global__ void __launch_bounds__(256) cswin_kernel(const float* __restrict__ lw0,
                                                    const float* __restrict__ lb0,
                                                    const float* __restrict__ lw1,
                                                    const float* __restrict__ lb1,
                                                    float* __restrict__ out) {
    extern __shared__ float sh[];
    float* Ks = sh;
    float* Vs = sh + 392 * 48;
    __shared__ float wsh[48][9];
    __shared__ float bsh[48];

    int win = blockIdx.x;
    int hh  = blockIdx.y;
    int z   = blockIdx.z;
    int bb  = z >> 1, br = z & 1;
    int SW = br ? 56 : 7;
    int SH = br ? 7 : 56;
    int choff = br * CSC + hh * 48;
    const float* qkv = g_qkv[0] + (size_t)bb * NTOK * 576;
    int tid = threadIdx.x;

    for (int e = tid; e < 392 * 12; e += 256) {
        int t = e / 12, d4 = (e % 12) * 4;
        int hl = t / SW, wl = t % SW;
        int h = br ? win * 7 + hl : hl;
        int w = br ? wl : win * 7 + wl;
        int n = h * RES + w;
        const float* row = qkv + (size_t)n * 576 + choff;
        *(float4*)&Ks[t * 48 + d4] = *(const float4*)&row[192 + d4];
        *(float4*)&Vs[t * 48 + d4] = *(const float4*)&row[384 + d4];
    }
    const float* lw = br ? lw1 : lw0;
    const float* lb = br ? lb1 : lb0;
    for (int e = tid; e < 48 * 9; e += 256) {
        int d = e / 9, k = e % 9;
        wsh[d][k] = lw[(hh * 48 + d) * 9 + k];
    }
    if (tid < 48) bsh[tid] = lb[hh * 48 + tid];
    __syncthreads();

    const float qscale = CS_SCALE * LOG2E;

    for (int r = tid; r < 392; r += 256) {
        int hl = r / SW, wl = r % SW;
        int h = br ? win * 7 + hl : hl;
        int w = br ? wl : win * 7 + wl;
        int n = h * RES + w;
        const float* qrow = qkv + (size_t)n * 576 + choff;

        float q[48];
#pragma unroll
        for (int d4 = 0; d4 < 48; d4 += 4) {
            float4 v = *(const float4*)&qrow[d4];
            q[d4 + 0] = v.x * qscale; q[d4 + 1] = v.y * qscale;
            q[d4 + 2] = v.z * qscale; q[d4 + 3] = v.w * qscale;
        }
        float m = -1e30f, l = 0.f;
        float acc[48];
#pragma unroll
        for (int d = 0; d < 48; d++) acc[d] = 0.f;

        for (int c0 = 0; c0 < 392; c0 += 14) {
            float s[14];
#pragma unroll
            for (int i = 0; i < 14; i++) {
                const float* kr = &Ks[(c0 + i) * 48];
                float sv = 0.f;
#pragma unroll
                for (int d4 = 0; d4 < 48; d4 += 4) {
                    float4 kv = *(const float4*)&kr[d4];
                    sv += q[d4] * kv.x + q[d4 + 1] * kv.y + q[d4 + 2] * kv.z + q[d4 + 3] * kv.w;
                }
                s[i] = sv;
            }
            float cm = s[0];
#pragma unroll
            for (int i = 1; i < 14; i++) cm = fmaxf(cm, s[i]);
            float mnew = fmaxf(m, cm);
            float rs = exp2f(m - mnew);
            l *= rs;
#pragma unroll
            for (int d = 0; d < 48; d++) acc[d] *= rs;
#pragma unroll
            for (int i = 0; i < 14; i++) {
                float p = exp2f(s[i] - mnew);
                l += p;
                const float* vr = &Vs[(c0 + i) * 48];
#pragma unroll
                for (int d4 = 0; d4 < 48; d4 += 4) {
                    float4 vv = *(const float4*)&vr[d4];
                    acc[d4 + 0] += p * vv.x; acc[d4 + 1] += p * vv.y;
                    acc[d4 + 2] += p * vv.z; acc[d4 + 3] += p * vv.w;
                }
            }
            m = mnew;
        }
        float inv = 1.f / l;

        float lep[48];
#pragma unroll
        for (int d = 0; d < 48; d++) lep[d] = bsh[d];
#pragma unroll
        for (int dy = -1; dy <= 1; dy++) {
#pragma unroll
            for (int dx = -1; dx <= 1; dx++) {
                int h2 = hl + dy, w2 = wl + dx;
                if (h2 < 0 || h2 >= SH || w2 < 0 || w2 >= SW) continue;
                const float* vr = &Vs[(h2 * SW + w2) * 48];
                int tap = (dy + 1) * 3 + (dx + 1);
#pragma unroll
                for (int d = 0; d < 48; d += 4) {
                    float4 vv = *(const float4*)&vr[d];
                    lep[d + 0] += vv.x * wsh[d + 0][tap];
                    lep[d + 1] += vv.y * wsh[d + 1][tap];
                    lep[d + 2] += vv.z * wsh[d + 2][tap];
                    lep[d + 3] += vv.w * wsh[d + 3][tap];
                }
            }
        }

        float* obase = out + ((size_t)bb * DIMC + br * CSC + hh * 48) * NTOK + n;
#pragma unroll
        for (int d = 0; d < 48; d++)
            obase[(size_t)d * NTOK] = acc[d] * inv + lep[d];
    }
}

// ---------------------------------------------------------------------------
// Kernel 4: global attention (lower line) -- tensor-core flash attention.
// mma.sync.m16n8k8 tf32. CTA = 4 warps x 16 query rows = 64 rows.
// Keys streamed in 32-wide tiles, cp.async double buffered.
// grid (49, 3, 4), block 128. Static smem ~46 KB.
// ---------------------------------------------------------------------------
#define KT 32
#define KSTRIDE 72      // 32 banks: row stride 72 floats -> conflict-free frags
#define PSTRIDE 36

__device__ __forceinline__ void cp_async16(void* smem_dst, const void* gsrc) {
    unsigned s = (unsigned)__cvta_generic_to_shared(smem_dst);
    asm volatile("cp.async.cg.shared.global [%0], [%1], 16;\n" :: "r"(s), "l"(gsrc));
}

__device__ __forceinline__ void mma_tf32(float* c, const unsigned* a, unsigned b0, unsigned b1) {
    asm volatile(
        "mma.sync.aligned.m16n8k8.row.col.f32.tf32.tf32.f32 "
        "{%0,%1,%2,%3}, {%4,%5,%6,%7}, {%8,%9}, {%0,%1,%2,%3};"
        : "+f"(c[0]), "+f"(c[1]), "+f"(c[2]), "+f"(c[3])
        : "r"(a[0]), "r"(a[1]), "r"(a[2]), "r"(a[3]), "r"(b0), "r"(b1));
}

__global__ void __launch_bounds__(128) attn_dn_kernel(float* __restrict__ out) {
    __shared__ float    Ksm[2][KT * KSTRIDE];
    __shared__ float    Vsm[2][KT * KSTRIDE];
    __shared__ unsigned Psm[4][16 * PSTRIDE];

    int qt = blockIdx.x, hh = blockIdx.y, bb = blockIdx.z;
    const float* qkv = g_qkv[1] + (size_t)bb * NTOK * 576;
    int tid = threadIdx.x;
    int warp = tid >> 5, lane = tid & 31;
    int g = lane >> 2, t = lane & 3;     // groupID, threadID-in-group
    int row0 = qt * 64 + warp * 16;

    // ---- Q A-fragments (tf32, scale folded in), register resident ----
    unsigned qa[8][4];
    {
        const float qscale = DN_SCALE * LOG2E;
        const float* q0 = qkv + (size_t)(row0 + g) * 576 + hh * 64;
        const float* q8 = qkv + (size_t)(row0 + g + 8) * 576 + hh * 64;
#pragma unroll
        for (int kc = 0; kc < 8; kc++) {
            qa[kc][0] = f2tf32(q0[kc * 8 + t] * qscale);
            qa[kc][1] = f2tf32(q8[kc * 8 + t] * qscale);
            qa[kc][2] = f2tf32(q0[kc * 8 + t + 4] * qscale);
            qa[kc][3] = f2tf32(q8[kc * 8 + t + 4] * qscale);
        }
    }

    float o[8][4];
#pragma unroll
    for (int nt = 0; nt < 8; nt++)
        o[nt][0] = o[nt][1] = o[nt][2] = o[nt][3] = 0.f;
    float m0 = -1e30f, m1 = -1e30f, l0 = 0.f, l1 = 0.f;

    // ---- cp.async tile loader: K tile 32x64 + V tile 32x64 (pre-rounded) ----
    auto load_tile = [&](int kt, int buf) {
#pragma unroll
        for (int i = 0; i < 4; i++) {
            int task = tid * 4 + i;               // 0..511
            int rrow = task >> 4, chunk = task & 15;
            const float* src = qkv + (size_t)(kt * KT + rrow) * 576 + hh * 64 + chunk * 4;
            cp_async16(&Ksm[buf][rrow * KSTRIDE + chunk * 4], src + 192);
            cp_async16(&Vsm[buf][rrow * KSTRIDE + chunk * 4], src + 384);
        }
        asm volatile("cp.async.commit_group;\n" ::: "memory");
    };

    load_tile(0, 0);

    for (int kt = 0; kt < 98; kt++) {
        int cur = kt & 1;
        if (kt < 97) {
            load_tile(kt + 1, cur ^ 1);
            asm volatile("cp.async.wait_group 1;\n" ::: "memory");
        } else {
            asm volatile("cp.async.wait_group 0;\n" ::: "memory");
        }
        __syncthreads();

        // ---- S = Q K^T : 4 n-tiles (8 keys each) x 8 k-chunks ----
        float s[4][4];
#pragma unroll
        for (int nt = 0; nt < 4; nt++) {
            s[nt][0] = s[nt][1] = s[nt][2] = s[nt][3] = 0.f;
            const float* kb = &Ksm[cur][(nt * 8 + g) * KSTRIDE];
#pragma unroll
            for (int kc = 0; kc < 8; kc++) {
                unsigned b0 = __float_as_uint(kb[kc * 8 + t]);
                unsigned b1 = __float_as_uint(kb[kc * 8 + t + 4]);
                mma_tf32(s[nt], qa[kc], b0, b1);
            }
        }

        // ---- online softmax on fragments (rows g and g+8) ----
        float rmax0 = fmaxf(fmaxf(s[0][0], s[0][1]), fmaxf(s[1][0], s[1][1]));
        rmax0 = fmaxf(rmax0, fmaxf(fmaxf(s[2][0], s[2][1]), fmaxf(s[3][0], s[3][1])));
        float rmax1 = fmaxf(fmaxf(s[0][2], s[0][3]), fmaxf(s[1][2], s[1][3]));
        rmax1 = fmaxf(rmax1, fmaxf(fmaxf(s[2][2], s[2][3]), fmaxf(s[3][2], s[3][3])));
        rmax0 = fmaxf(rmax0, __shfl_xor_sync(0xffffffffu, rmax0, 1));
        rmax0 = fmaxf(rmax0, __shfl_xor_sync(0xffffffffu, rmax0, 2));
        rmax1 = fmaxf(rmax1, __shfl_xor_sync(0xffffffffu, rmax1, 1));
        rmax1 = fmaxf(rmax1, __shfl_xor_sync(0xffffffffu, rmax1, 2));

        float mn0 = fmaxf(m0, rmax0), mn1 = fmaxf(m1, rmax1);
        float rs0 = exp2f(m0 - mn0),  rs1 = exp2f(m1 - mn1);
        l0 *= rs0; l1 *= rs1;

        unsigned* P = Psm[warp];
        float psum0 = 0.f, psum1 = 0.f;
#pragma unroll
        for (int nt = 0; nt < 4; nt++) {
            float p0 = exp2f(s[nt][0] - mn0);
            float p1 = exp2f(s[nt][1] - mn0);
            float p2 = exp2f(s[nt][2] - mn1);
            float p3 = exp2f(s[nt][3] - mn1);
            psum0 += p0 + p1; psum1 += p2 + p3;
            P[g * PSTRIDE + nt * 8 + 2 * t]           = f2tf32(p0);
            P[g * PSTRIDE + nt * 8 + 2 * t + 1]       = f2tf32(p1);
            P[(g + 8) * PSTRIDE + nt * 8 + 2 * t]     = f2tf32(p2);
            P[(g + 8) * PSTRIDE + nt * 8 + 2 * t + 1] = f2tf32(p3);
        }
        l0 += psum0; l1 += psum1;
#pragma unroll
        for (int nt = 0; nt < 8; nt++) {
            o[nt][0] *= rs0; o[nt][1] *= rs0;
            o[nt][2] *= rs1; o[nt][3] *= rs1;
        }
        m0 = mn0; m1 = mn1;
        __syncwarp();          // P tile is warp-private: STS -> LDS ordering

        // ---- O += P V : 4 k-chunks (8 keys) x 8 n-tiles (8 dims) ----
#pragma unroll
        for (int kc = 0; kc < 4; kc++) {
            unsigned pa[4];
            pa[0] = P[g * PSTRIDE + kc * 8 + t];
            pa[1] = P[(g + 8) * PSTRIDE + kc * 8 + t];
            pa[2] = P[g * PSTRIDE + kc * 8 + t + 4];
            pa[3] = P[(g + 8) * PSTRIDE + kc * 8 + t + 4];
            const float* vb0 = &Vsm[cur][(kc * 8 + t) * KSTRIDE];
            const float* vb1 = &Vsm[cur][(kc * 8 + t + 4) * KSTRIDE];
#pragma unroll
            for (int nt = 0; nt < 8; nt++) {
                unsigned b0 = __float_as_uint(vb0[nt * 8 + g]);
                unsigned b1 = __float_as_uint(vb1[nt * 8 + g]);
                mma_tf32(o[nt], pa, b0, b1);
            }
        }
        __syncthreads();       // done reading buf `cur` before next refill
    }

    // ---- finalize: reduce l across the 4-lane group, normalize, store ----
    l0 += __shfl_xor_sync(0xffffffffu, l0, 1);
    l0 += __shfl_xor_sync(0xffffffffu, l0, 2);
    l1 += __shfl_xor_sync(0xffffffffu, l1, 1);
    l1 += __shfl_xor_sync(0xffffffffu, l1, 2);
    float inv0 = 1.f / l0, inv1 = 1.f / l1;

    float* ob = out + ((size_t)bb * DIMC + TD + hh * 64) * NTOK;
    int tok0 = row0 + g, tok1 = row0 + g + 8;
#pragma unroll
    for (int nt = 0; nt < 8; nt++) {
        int d0 = nt * 8 + 2 * t;
        ob[(size_t)d0 * NTOK + tok0]       = o[nt][0] * inv0;
        ob[(size_t)(d0 + 1) * NTOK + tok0] = o[nt][1] * inv0;
        ob[(size_t)d0 * NTOK + tok1]       = o[nt][2] * inv1;
        ob[(size_t)(d0 + 1) * NTOK + tok1] = o[nt][3] * inv1;
    }
}

// ---------------------------------------------------------------------------
// Launch
// ---------------------------------------------------------------------------
extern "C" void kernel_launch(void* const* d_in, const int* in_sizes, int n_in,
                              void* d_out, int out_size) {
    const float* xa      = (const float*)d_in[0];
    const float* proj1_w = (const float*)d_in[1];
    const float* proj2_w = (const float*)d_in[2];
    const float* qkv_u_w = (const float*)d_in[3];
    const float* qkv_d_w = (const float*)d_in[4];
    const float* lepe_w0 = (const float*)d_in[5];
    const float* lepe_b0 = (const float*)d_in[6];
    const float* lepe_w1 = (const float*)d_in[7];
    const float* lepe_b1 = (const float*)d_in[8];
    float* out = (float*)d_out;

    // 1) combined weights (Wqkv @ Wproj)
    combine_w_kernel<<<dim3(576, 2), 384>>>(proj1_w, proj2_w, qkv_u_w, qkv_d_w);

    // 2) fused proj+qkv GEMM for both lines
    qkv_gemm_kernel<<<dim3(49, 9, 8), 256>>>(xa);

    // 2b) round line-1 K/V to tf32 (RN) in place for exact HMMA operands
    round_kv_kernel<<<(NB * NTOK * 96 + 255) / 256, 256>>>();

    // 3) CSWin upper line (writes channels [0,192))
    cudaFuncSetAttribute(cswin_kernel, cudaFuncAttributeMaxDynamicSharedMemorySize, CS_SMEM);
    cswin_kernel<<<dim3(8, 2, 8), 256, CS_SMEM>>>(lepe_w0, lepe_b0, lepe_w1, lepe_b1, out);

    // 4) global attention lower line (tensor cores, writes channels [192,384))
    attn_dn_kernel<<<dim3(49, 3, 4), 128>>>(out);
}

// round 10
// speedup vs baseline: 5.6590x; 1.0915x over previous
#include <cuda_runtime.h>
#include <math.h>

// Problem constants
#define NB    4
#define DIMC  384
#define RES   56
#define NTOK  3136          // 56*56
#define TD    192
#define CSC   96

#define LOG2E 1.4426950408889634f
#define CS_SCALE 0.14433756729740643f   // 1/sqrt(48)
#define DN_SCALE 0.125f                 // 1/sqrt(64)

// ---------------------------------------------------------------------------
// Scratch (static device arrays; no allocation anywhere)
// ---------------------------------------------------------------------------
__device__ float g_wc[2][576 * 384];                 // combined (qkv_w @ proj_w)
__device__ float g_qkv[2][NB * NTOK * 576];          // [line][((b*3136)+n)*576 + j]

// ---------------------------------------------------------------------------
// Shared helpers
// ---------------------------------------------------------------------------
__device__ __forceinline__ unsigned f2tf32(float f) {
    unsigned u;
    asm("cvt.rna.tf32.f32 %0, %1;" : "=r"(u) : "f"(f));
    return u;
}

__device__ __forceinline__ void cp_async16(void* smem_dst, const void* gsrc) {
    unsigned s = (unsigned)__cvta_generic_to_shared(smem_dst);
    asm volatile("cp.async.cg.shared.global [%0], [%1], 16;\n" :: "r"(s), "l"(gsrc));
}

__device__ __forceinline__ void mma_tf32(float* c, const unsigned* a, unsigned b0, unsigned b1) {
    asm volatile(
        "mma.sync.aligned.m16n8k8.row.col.f32.tf32.tf32.f32 "
        "{%0,%1,%2,%3}, {%4,%5,%6,%7}, {%8,%9}, {%0,%1,%2,%3};"
        : "+f"(c[0]), "+f"(c[1]), "+f"(c[2]), "+f"(c[3])
        : "r"(a[0]), "r"(a[1]), "r"(a[2]), "r"(a[3]), "r"(b0), "r"(b1));
}

// ---------------------------------------------------------------------------
// Kernel 1: combined weights  Wc[j][c] = sum_t qkv_w[j][t] * proj_w[t][c]
// ---------------------------------------------------------------------------
__global__ void combine_w_kernel(const float* __restrict__ p1,
                                 const float* __restrict__ p2,
                                 const float* __restrict__ qu,
                                 const float* __restrict__ qd) {
    int j = blockIdx.x;
    int line = blockIdx.y;
    int c = threadIdx.x;
    const float* qw = line ? qd : qu;
    const float* pw = line ? p2 : p1;
    const float* qrow = qw + j * 192;
    float s = 0.f;
#pragma unroll 8
    for (int t = 0; t < 192; t++)
        s += qrow[t] * pw[t * 384 + c];
    g_wc[line][j * 384 + c] = s;
}

// ---------------------------------------------------------------------------
// Kernel 2: qkv GEMM  (R7/R9-passing version, unchanged)
// ---------------------------------------------------------------------------
__global__ void __launch_bounds__(256) qkv_gemm_kernel(const float* __restrict__ xa) {
    __shared__ float Ash[16][64];
    __shared__ float Wsh[64][17];

    int z = blockIdx.z;
    int bb = z >> 1, line = z & 1;
    int n0 = blockIdx.x * 64;
    int j0 = blockIdx.y * 64;
    const float* A = xa + (size_t)bb * DIMC * NTOK;
    const float* W = g_wc[line];
    int tid = threadIdx.x;
    int tn = tid & 15, tj = tid >> 4;

    int la_c = tid >> 4;
    int la_n = (tid & 15) * 4;
    int lw_j = tid >> 2;
    int lw_c = (tid & 3) * 4;

    float acc[4][4] = {};

    for (int c0 = 0; c0 < 384; c0 += 16) {
        float4 av = *(const float4*)&A[(size_t)(c0 + la_c) * NTOK + n0 + la_n];
        *(float4*)&Ash[la_c][la_n] = av;
        float4 wv = *(const float4*)&W[(j0 + lw_j) * 384 + c0 + lw_c];
        Wsh[lw_j][lw_c + 0] = wv.x;
        Wsh[lw_j][lw_c + 1] = wv.y;
        Wsh[lw_j][lw_c + 2] = wv.z;
        Wsh[lw_j][lw_c + 3] = wv.w;
        __syncthreads();
#pragma unroll
        for (int cc = 0; cc < 16; cc++) {
            float4 a4 = *(const float4*)&Ash[cc][tn * 4];
            float b0 = Wsh[tj * 4 + 0][cc];
            float b1 = Wsh[tj * 4 + 1][cc];
            float b2 = Wsh[tj * 4 + 2][cc];
            float b3 = Wsh[tj * 4 + 3][cc];
            acc[0][0] += a4.x * b0; acc[0][1] += a4.x * b1; acc[0][2] += a4.x * b2; acc[0][3] += a4.x * b3;
            acc[1][0] += a4.y * b0; acc[1][1] += a4.y * b1; acc[1][2] += a4.y * b2; acc[1][3] += a4.y * b3;
            acc[2][0] += a4.z * b0; acc[2][1] += a4.z * b1; acc[2][2] += a4.z * b2; acc[2][3] += a4.z * b3;
            acc[3][0] += a4.w * b0; acc[3][1] += a4.w * b1; acc[3][2] += a4.w * b2; acc[3][3] += a4.w * b3;
        }
        __syncthreads();
    }

    float* out = g_qkv[line] + (size_t)bb * NTOK * 576;
#pragma unroll
    for (int i = 0; i < 4; i++) {
        float4 o = make_float4(acc[i][0], acc[i][1], acc[i][2], acc[i][3]);
        *(float4*)&out[(size_t)(n0 + tn * 4 + i) * 576 + j0 + tj * 4] = o;
    }
}

// ---------------------------------------------------------------------------
// Kernel 2b: round K/V channels of BOTH lines to tf32 (RN), in place.
// grid ((NB*NTOK*96+255)/256, 2)
// ---------------------------------------------------------------------------
__global__ void __launch_bounds__(256) round_kv_kernel() {
    int idx = blockIdx.x * 256 + threadIdx.x;          // float4 index
    int line = blockIdx.y;
    if (idx >= NB * NTOK * 96) return;
    int row = idx / 96, c4 = idx % 96;
    float4* p = (float4*)&g_qkv[line][(size_t)row * 576 + 192 + c4 * 4];
    float4 v = *p;
    v.x = __uint_as_float(f2tf32(v.x));
    v.y = __uint_as_float(f2tf32(v.y));
    v.z = __uint_as_float(f2tf32(v.z));
    v.w = __uint_as_float(f2tf32(v.w));
    *p = v;
}

// ---------------------------------------------------------------------------
// Kernel 3: CSWin attention (upper line) -- tensor-core flash attention.
// mma.m16n8k8 tf32. CTA = 4 warps x 16 q-rows = 64 rows of one stripe problem.
// Stripe = 392 tokens, d = 48. Keys streamed in 56-wide double-buffered tiles
// (392 = 7*56 exact). Last q-tile is padded (rows >= 392 computed, not stored).
// grid (7 qtiles, 16 = win*2+hh, 8 = bb*2+br), block 128, dyn smem 64 KB.
// ---------------------------------------------------------------------------
#define CSKT 56
#define CSSTRIDE 56       // 48 data + 8 pad
#define CSPSTRIDE 60
#define CSMMA_SMEM (4 * CSKT * CSSTRIDE * 4 + 4 * 16 * CSPSTRIDE * 4)   // 65536

__global__ void __launch_bounds__(128) cswin_mma_kernel(float* __restrict__ out) {
    extern __shared__ float csh[];
    float* Ksm[2] = { csh,                    csh + CSKT * CSSTRIDE };
    float* Vsm[2] = { csh + 2 * CSKT * CSSTRIDE, csh + 3 * CSKT * CSSTRIDE };
    unsigned* Pbase = (unsigned*)(csh + 4 * CSKT * CSSTRIDE);

    int qt = blockIdx.x;
    int win = blockIdx.y >> 1, hh = blockIdx.y & 1;
    int bb = blockIdx.z >> 1, br = blockIdx.z & 1;
    int choff = br * CSC + hh * 48;
    const float* qkv = g_qkv[0] + (size_t)bb * NTOK * 576;
    int tid = threadIdx.x;
    int warp = tid >> 5, lane = tid & 31;
    int g = lane >> 2, t = lane & 3;
    int row0 = qt * 64 + warp * 16;
    unsigned* P = Pbase + warp * 16 * CSPSTRIDE;

    // stripe-local token -> image token index
    auto tok2n = [&](int c) {
        int hl, wl;
        if (br) { hl = c / 56; wl = c - hl * 56; }
        else    { hl = c / 7;  wl = c - hl * 7;  }
        int h = br ? win * 7 + hl : hl;
        int w = br ? wl : win * 7 + wl;
        return h * RES + w;
    };

    // ---- Q A-fragments (tf32, scale folded), rows clamped for padded tile ----
    unsigned qa[6][4];
    {
        const float qscale = CS_SCALE * LOG2E;
        int r0c = min(row0 + g, 391), r1c = min(row0 + g + 8, 391);
        const float* q0 = qkv + (size_t)tok2n(r0c) * 576 + choff;
        const float* q8 = qkv + (size_t)tok2n(r1c) * 576 + choff;
#pragma unroll
        for (int kc = 0; kc < 6; kc++) {
            qa[kc][0] = f2tf32(q0[kc * 8 + t] * qscale);
            qa[kc][1] = f2tf32(q8[kc * 8 + t] * qscale);
            qa[kc][2] = f2tf32(q0[kc * 8 + t + 4] * qscale);
            qa[kc][3] = f2tf32(q8[kc * 8 + t + 4] * qscale);
        }
    }

    float o[6][4];
#pragma unroll
    for (int nt = 0; nt < 6; nt++)
        o[nt][0] = o[nt][1] = o[nt][2] = o[nt][3] = 0.f;
    float m0 = -1e30f, m1 = -1e30f, l0 = 0.f, l1 = 0.f;

    // ---- tile loader: 56 keys x 48 floats of K and V (pre-rounded tf32) ----
    auto load_tile = [&](int ti, int buf) {
        float* kd = Ksm[buf];
        float* vd = Vsm[buf];
        for (int i = tid; i < 56 * 12; i += 128) {
            int rr = i / 12, c4 = (i % 12) * 4;
            int n = tok2n(ti * CSKT + rr);
            const float* src = qkv + (size_t)n * 576 + choff + c4;
            cp_async16(kd + rr * CSSTRIDE + c4, src + 192);
            cp_async16(vd + rr * CSSTRIDE + c4, src + 384);
        }
        asm volatile("cp.async.commit_group;\n" ::: "memory");
    };

    load_tile(0, 0);

    for (int ti = 0; ti < 7; ti++) {
        int cur = ti & 1;
        if (ti < 6) {
            load_tile(ti + 1, cur ^ 1);
            asm volatile("cp.async.wait_group 1;\n" ::: "memory");
        } else {
            asm volatile("cp.async.wait_group 0;\n" ::: "memory");
        }
        __syncthreads();

        // ---- S = Q K^T : 7 n-tiles (8 keys) x 6 k-chunks ----
        float s[7][4];
#pragma unroll
        for (int nt = 0; nt < 7; nt++) {
            s[nt][0] = s[nt][1] = s[nt][2] = s[nt][3] = 0.f;
            const float* kb = &Ksm[cur][(nt * 8 + g) * CSSTRIDE];
#pragma unroll
            for (int kc = 0; kc < 6; kc++) {
                unsigned b0 = __float_as_uint(kb[kc * 8 + t]);
                unsigned b1 = __float_as_uint(kb[kc * 8 + t + 4]);
                mma_tf32(s[nt], qa[kc], b0, b1);
            }
        }

        // ---- online softmax on fragments ----
        float rmax0 = s[0][0], rmax1 = s[0][2];
#pragma unroll
        for (int nt = 0; nt < 7; nt++) {
            rmax0 = fmaxf(rmax0, fmaxf(s[nt][0], s[nt][1]));
            rmax1 = fmaxf(rmax1, fmaxf(s[nt][2], s[nt][3]));
        }
        rmax0 = fmaxf(rmax0, __shfl_xor_sync(0xffffffffu, rmax0, 1));
        rmax0 = fmaxf(rmax0, __shfl_xor_sync(0xffffffffu, rmax0, 2));
        rmax1 = fmaxf(rmax1, __shfl_xor_sync(0xffffffffu, rmax1, 1));
        rmax1 = fmaxf(rmax1, __shfl_xor_sync(0xffffffffu, rmax1, 2));

        float mn0 = fmaxf(m0, rmax0), mn1 = fmaxf(m1, rmax1);
        float rs0 = exp2f(m0 - mn0),  rs1 = exp2f(m1 - mn1);
        l0 *= rs0; l1 *= rs1;

        float psum0 = 0.f, psum1 = 0.f;
#pragma unroll
        for (int nt = 0; nt < 7; nt++) {
            float p0 = exp2f(s[nt][0] - mn0);
            float p1 = exp2f(s[nt][1] - mn0);
            float p2 = exp2f(s[nt][2] - mn1);
            float p3 = exp2f(s[nt][3] - mn1);
            psum0 += p0 + p1; psum1 += p2 + p3;
            P[g * CSPSTRIDE + nt * 8 + 2 * t]           = f2tf32(p0);
            P[g * CSPSTRIDE + nt * 8 + 2 * t + 1]       = f2tf32(p1);
            P[(g + 8) * CSPSTRIDE + nt * 8 + 2 * t]     = f2tf32(p2);
            P[(g + 8) * CSPSTRIDE + nt * 8 + 2 * t + 1] = f2tf32(p3);
        }
        l0 += psum0; l1 += psum1;
#pragma unroll
        for (int nt = 0; nt < 6; nt++) {
            o[nt][0] *= rs0; o[nt][1] *= rs0;
            o[nt][2] *= rs1; o[nt][3] *= rs1;
        }
        m0 = mn0; m1 = mn1;
        __syncwarp();

        // ---- O += P V : 7 k-chunks (8 keys) x 6 n-tiles (8 dims) ----
#pragma unroll
        for (int kc = 0; kc < 7; kc++) {
            unsigned pa[4];
            pa[0] = P[g * CSPSTRIDE + kc * 8 + t];
            pa[1] = P[(g + 8) * CSPSTRIDE + kc * 8 + t];
            pa[2] = P[g * CSPSTRIDE + kc * 8 + t + 4];
            pa[3] = P[(g + 8) * CSPSTRIDE + kc * 8 + t + 4];
            const float* vb0 = &Vsm[cur][(kc * 8 + t) * CSSTRIDE];
            const float* vb1 = &Vsm[cur][(kc * 8 + t + 4) * CSSTRIDE];
#pragma unroll
            for (int nt = 0; nt < 6; nt++) {
                unsigned b0 = __float_as_uint(vb0[nt * 8 + g]);
                unsigned b1 = __float_as_uint(vb1[nt * 8 + g]);
                mma_tf32(o[nt], pa, b0, b1);
            }
        }
        __syncthreads();
    }

    // ---- finalize ----
    l0 += __shfl_xor_sync(0xffffffffu, l0, 1);
    l0 += __shfl_xor_sync(0xffffffffu, l0, 2);
    l1 += __shfl_xor_sync(0xffffffffu, l1, 1);
    l1 += __shfl_xor_sync(0xffffffffu, l1, 2);
    float inv0 = 1.f / l0, inv1 = 1.f / l1;

    float* ob = out + ((size_t)bb * DIMC + choff) * NTOK;
    int tok0 = row0 + g, tok1 = row0 + g + 8;
    if (tok0 < 392) {
        int n = tok2n(tok0);
#pragma unroll
        for (int nt = 0; nt < 6; nt++) {
            int d0 = nt * 8 + 2 * t;
            ob[(size_t)d0 * NTOK + n]       = o[nt][0] * inv0;
            ob[(size_t)(d0 + 1) * NTOK + n] = o[nt][1] * inv0;
        }
    }
    if (tok1 < 392) {
        int n = tok2n(tok1);
#pragma unroll
        for (int nt = 0; nt < 6; nt++) {
            int d0 = nt * 8 + 2 * t;
            ob[(size_t)d0 * NTOK + n]       = o[nt][2] * inv1;
            ob[(size_t)(d0 + 1) * NTOK + n] = o[nt][3] * inv1;
        }
    }
}

// ---------------------------------------------------------------------------
// Kernel 3b: LePE (depthwise 3x3 on V, stripe-local zero pad) -- ADDS into out.
// grid (8 win, 2 hh, 8 = bb*2+br), block 256, dyn smem = 392*48*4
// ---------------------------------------------------------------------------
#define LEPE_SMEM (392 * 48 * 4)

__global__ void __launch_bounds__(256) lepe_kernel(const float* __restrict__ lw0,
                                                   const float* __restrict__ lb0,
                                                   const float* __restrict__ lw1,
                                                   const float* __restrict__ lb1,
                                                   float* __restrict__ out) {
    extern __shared__ float Vs[];   // [392][48]
    __shared__ float wsh[48][9];
    __shared__ float bsh[48];

    int win = blockIdx.x;
    int hh  = blockIdx.y;
    int bb  = blockIdx.z >> 1, br = blockIdx.z & 1;
    int SW = br ? 56 : 7;
    int SH = br ? 7 : 56;
    int choff = br * CSC + hh * 48;
    const float* qkv = g_qkv[0] + (size_t)bb * NTOK * 576;
    int tid = threadIdx.x;

    for (int e = tid; e < 392 * 12; e += 256) {
        int tk = e / 12, d4 = (e % 12) * 4;
        int hl, wl;
        if (br) { hl = tk / 56; wl = tk - hl * 56; }
        else    { hl = tk / 7;  wl = tk - hl * 7;  }
        int h = br ? win * 7 + hl : hl;
        int w = br ? wl : win * 7 + wl;
        int n = h * RES + w;
        *(float4*)&Vs[tk * 48 + d4] = *(const float4*)&qkv[(size_t)n * 576 + choff + 384 + d4];
    }
    const float* lw = br ? lw1 : lw0;
    const float* lb = br ? lb1 : lb0;
    for (int e = tid; e < 48 * 9; e += 256) {
        int d = e / 9, k = e % 9;
        wsh[d][k] = lw[(hh * 48 + d) * 9 + k];
    }
    if (tid < 48) bsh[tid] = lb[hh * 48 + tid];
    __syncthreads();

    for (int e = tid; e < 48 * 392; e += 256) {
        int d = e / 392, r = e - d * 392;
        int hl, wl;
        if (br) { hl = r / 56; wl = r - hl * 56; }
        else    { hl = r / 7;  wl = r - hl * 7;  }
        float lep = bsh[d];
#pragma unroll
        for (int dy = -1; dy <= 1; dy++) {
#pragma unroll
            for (int dx = -1; dx <= 1; dx++) {
                int h2 = hl + dy, w2 = wl + dx;
                if (h2 < 0 || h2 >= SH || w2 < 0 || w2 >= SW) continue;
                lep += Vs[(h2 * SW + w2) * 48 + d] * wsh[d][(dy + 1) * 3 + (dx + 1)];
            }
        }
        int h = br ? win * 7 + hl : hl;
        int w = br ? wl : win * 7 + wl;
        int n = h * RES + w;
        out[((size_t)bb * DIMC + choff + d) * NTOK + n] += lep;
    }
}

// ---------------------------------------------------------------------------
// Kernel 4: global attention (lower line) -- tensor-core flash (R9-passing)
// ---------------------------------------------------------------------------
#define KT 32
#define KSTRIDE 72
#define PSTRIDE 36

__global__ void __launch_bounds__(128) attn_dn_kernel(float* __restrict__ out) {
    __shared__ float    Ksm[2][KT * KSTRIDE];
    __shared__ float    Vsm[2][KT * KSTRIDE];
    __shared__ unsigned Psm[4][16 * PSTRIDE];

    int qt = blockIdx.x, hh = blockIdx.y, bb = blockIdx.z;
    const float* qkv = g_qkv[1] + (size_t)bb * NTOK * 576;
    int tid = threadIdx.x;
    int warp = tid >> 5, lane = tid & 31;
    int g = lane >> 2, t = lane & 3;
    int row0 = qt * 64 + warp * 16;

    unsigned qa[8][4];
    {
        const float qscale = DN_SCALE * LOG2E;
        const float* q0 = qkv + (size_t)(row0 + g) * 576 + hh * 64;
        const float* q8 = qkv + (size_t)(row0 + g + 8) * 576 + hh * 64;
#pragma unroll
        for (int kc = 0; kc < 8; kc++) {
            qa[kc][0] = f2tf32(q0[kc * 8 + t] * qscale);
            qa[kc][1] = f2tf32(q8[kc * 8 + t] * qscale);
            qa[kc][2] = f2tf32(q0[kc * 8 + t + 4] * qscale);
            qa[kc][3] = f2tf32(q8[kc * 8 + t + 4] * qscale);
        }
    }

    float o[8][4];
#pragma unroll
    for (int nt = 0; nt < 8; nt++)
        o[nt][0] = o[nt][1] = o[nt][2] = o[nt][3] = 0.f;
    float m0 = -1e30f, m1 = -1e30f, l0 = 0.f, l1 = 0.f;

    auto load_tile = [&](int kt, int buf) {
#pragma unroll
        for (int i = 0; i < 4; i++) {
            int task = tid * 4 + i;
            int rrow = task >> 4, chunk = task & 15;
            const float* src = qkv + (size_t)(kt * KT + rrow) * 576 + hh * 64 + chunk * 4;
            cp_async16(&Ksm[buf][rrow * KSTRIDE + chunk * 4], src + 192);
            cp_async16(&Vsm[buf][rrow * KSTRIDE + chunk * 4], src + 384);
        }
        asm volatile("cp.async.commit_group;\n" ::: "memory");
    };

    load_tile(0, 0);

    for (int kt = 0; kt < 98; kt++) {
        int cur = kt & 1;
        if (kt < 97) {
            load_tile(kt + 1, cur ^ 1);
            asm volatile("cp.async.wait_group 1;\n" ::: "memory");
        } else {
            asm volatile("cp.async.wait_group 0;\n" ::: "memory");
        }
        __syncthreads();

        float s[4][4];
#pragma unroll
        for (int nt = 0; nt < 4; nt++) {
            s[nt][0] = s[nt][1] = s[nt][2] = s[nt][3] = 0.f;
            const float* kb = &Ksm[cur][(nt * 8 + g) * KSTRIDE];
#pragma unroll
            for (int kc = 0; kc < 8; kc++) {
                unsigned b0 = __float_as_uint(kb[kc * 8 + t]);
                unsigned b1 = __float_as_uint(kb[kc * 8 + t + 4]);
                mma_tf32(s[nt], qa[kc], b0, b1);
            }
        }

        float rmax0 = fmaxf(fmaxf(s[0][0], s[0][1]), fmaxf(s[1][0], s[1][1]));
        rmax0 = fmaxf(rmax0, fmaxf(fmaxf(s[2][0], s[2][1]), fmaxf(s[3][0], s[3][1])));
        float rmax1 = fmaxf(fmaxf(s[0][2], s[0][3]), fmaxf(s[1][2], s[1][3]));
        rmax1 = fmaxf(rmax1, fmaxf(fmaxf(s[2][2], s[2][3]), fmaxf(s[3][2], s[3][3])));
        rmax0 = fmaxf(rmax0, __shfl_xor_sync(0xffffffffu, rmax0, 1));
        rmax0 = fmaxf(rmax0, __shfl_xor_sync(0xffffffffu, rmax0, 2));
        rmax1 = fmaxf(rmax1, __shfl_xor_sync(0xffffffffu, rmax1, 1));
        rmax1 = fmaxf(rmax1, __shfl_xor_sync(0xffffffffu, rmax1, 2));

        float mn0 = fmaxf(m0, rmax0), mn1 = fmaxf(m1, rmax1);
        float rs0 = exp2f(m0 - mn0),  rs1 = exp2f(m1 - mn1);
        l0 *= rs0; l1 *= rs1;

        unsigned* P = Psm[warp];
        float psum0 = 0.f, psum1 = 0.f;
#pragma unroll
        for (int nt = 0; nt < 4; nt++) {
            float p0 = exp2f(s[nt][0] - mn0);
            float p1 = exp2f(s[nt][1] - mn0);
            float p2 = exp2f(s[nt][2] - mn1);
            float p3 = exp2f(s[nt][3] - mn1);
            psum0 += p0 + p1; psum1 += p2 + p3;
            P[g * PSTRIDE + nt * 8 + 2 * t]           = f2tf32(p0);
            P[g * PSTRIDE + nt * 8 + 2 * t + 1]       = f2tf32(p1);
            P[(g + 8) * PSTRIDE + nt * 8 + 2 * t]     = f2tf32(p2);
            P[(g + 8) * PSTRIDE + nt * 8 + 2 * t + 1] = f2tf32(p3);
        }
        l0 += psum0; l1 += psum1;
#pragma unroll
        for (int nt = 0; nt < 8; nt++) {
            o[nt][0] *= rs0; o[nt][1] *= rs0;
            o[nt][2] *= rs1; o[nt][3] *= rs1;
        }
        m0 = mn0; m1 = mn1;
        __syncwarp();

#pragma unroll
        for (int kc = 0; kc < 4; kc++) {
            unsigned pa[4];
            pa[0] = P[g * PSTRIDE + kc * 8 + t];
            pa[1] = P[(g + 8) * PSTRIDE + kc * 8 + t];
            pa[2] = P[g * PSTRIDE + kc * 8 + t + 4];
            pa[3] = P[(g + 8) * PSTRIDE + kc * 8 + t + 4];
            const float* vb0 = &Vsm[cur][(kc * 8 + t) * KSTRIDE];
            const float* vb1 = &Vsm[cur][(kc * 8 + t + 4) * KSTRIDE];
#pragma unroll
            for (int nt = 0; nt < 8; nt++) {
                unsigned b0 = __float_as_uint(vb0[nt * 8 + g]);
                unsigned b1 = __float_as_uint(vb1[nt * 8 + g]);
                mma_tf32(o[nt], pa, b0, b1);
            }
        }
        __syncthreads();
    }

    l0 += __shfl_xor_sync(0xffffffffu, l0, 1);
    l0 += __shfl_xor_sync(0xffffffffu, l0, 2);
    l1 += __shfl_xor_sync(0xffffffffu, l1, 1);
    l1 += __shfl_xor_sync(0xffffffffu, l1, 2);
    float inv0 = 1.f / l0, inv1 = 1.f / l1;

    float* ob = out + ((size_t)bb * DIMC + TD + hh * 64) * NTOK;
    int tok0 = row0 + g, tok1 = row0 + g + 8;
#pragma unroll
    for (int nt = 0; nt < 8; nt++) {
        int d0 = nt * 8 + 2 * t;
        ob[(size_t)d0 * NTOK + tok0]       = o[nt][0] * inv0;
        ob[(size_t)(d0 + 1) * NTOK + tok0] = o[nt][1] * inv0;
        ob[(size_t)d0 * NTOK + tok1]       = o[nt][2] * inv1;
        ob[(size_t)(d0 + 1) * NTOK + tok1] = o[nt][3] * inv1;
    }
}

// ---------------------------------------------------------------------------
// Launch
// ---------------------------------------------------------------------------
extern "C" void kernel_launch(void* const* d_in, const int* in_sizes, int n_in,
                              void* d_out, int out_size) {
    const float* xa      = (const float*)d_in[0];
    const float* proj1_w = (const float*)d_in[1];
    const float* proj2_w = (const float*)d_in[2];
    const float* qkv_u_w = (const float*)d_in[3];
    const float* qkv_d_w = (const float*)d_in[4];
    const float* lepe_w0 = (const float*)d_in[5];
    const float* lepe_b0 = (const float*)d_in[6];
    const float* lepe_w1 = (const float*)d_in[7];
    const float* lepe_b1 = (const float*)d_in[8];
    float* out = (float*)d_out;

    // 1) combined weights (Wqkv @ Wproj)
    combine_w_kernel<<<dim3(576, 2), 384>>>(proj1_w, proj2_w, qkv_u_w, qkv_d_w);

    // 2) fused proj+qkv GEMM for both lines
    qkv_gemm_kernel<<<dim3(49, 9, 8), 256>>>(xa);

    // 2b) round K/V of BOTH lines to tf32 (RN) in place
    round_kv_kernel<<<dim3((NB * NTOK * 96 + 255) / 256, 2), 256>>>();

    // 3) CSWin upper line, tensor cores (writes channels [0,192))
    cudaFuncSetAttribute(cswin_mma_kernel, cudaFuncAttributeMaxDynamicSharedMemorySize, CSMMA_SMEM);
    cswin_mma_kernel<<<dim3(7, 16, 8), 128, CSMMA_SMEM>>>(out);

    // 3b) LePE adds into channels [0,192) (after cswin_mma)
    cudaFuncSetAttribute(lepe_kernel, cudaFuncAttributeMaxDynamicSharedMemorySize, LEPE_SMEM);
    lepe_kernel<<<dim3(8, 2, 8), 256, LEPE_SMEM>>>(lepe_w0, lepe_b0, lepe_w1, lepe_b1, out);

    // 4) global attention lower line, tensor cores (channels [192,384))
    attn_dn_kernel<<<dim3(49, 3, 4), 128>>>(out);
}

// round 11
// speedup vs baseline: 6.3645x; 1.1247x over previous
#include <cuda_runtime.h>
#include <math.h>

// Problem constants
#define NB    4
#define DIMC  384
#define RES   56
#define NTOK  3136          // 56*56
#define TD    192
#define CSC   96

#define LOG2E 1.4426950408889634f
#define CS_SCALE 0.14433756729740643f   // 1/sqrt(48)
#define DN_SCALE 0.125f                 // 1/sqrt(64)

// ---------------------------------------------------------------------------
// Scratch (static device arrays; no allocation anywhere)
// ---------------------------------------------------------------------------
__device__ float g_wchi[2][576 * 384];               // combined weights, tf32 hi
__device__ float g_wclo[2][576 * 384];               // combined weights, tf32 lo
__device__ float g_xhi[NB * DIMC * NTOK];            // xa tf32 hi  [b][c][n]
__device__ float g_xlo[NB * DIMC * NTOK];            // xa tf32 lo
__device__ float g_qkv[2][NB * NTOK * 576];          // [line][((b*3136)+n)*576 + j]

// ---------------------------------------------------------------------------
// Shared helpers
// ---------------------------------------------------------------------------
__device__ __forceinline__ unsigned f2tf32(float f) {
    unsigned u;
    asm("cvt.rna.tf32.f32 %0, %1;" : "=r"(u) : "f"(f));
    return u;
}

__device__ __forceinline__ void cp_async16(void* smem_dst, const void* gsrc) {
    unsigned s = (unsigned)__cvta_generic_to_shared(smem_dst);
    asm volatile("cp.async.cg.shared.global [%0], [%1], 16;\n" :: "r"(s), "l"(gsrc));
}

__device__ __forceinline__ void mma_tf32(float* c, const unsigned* a, unsigned b0, unsigned b1) {
    asm volatile(
        "mma.sync.aligned.m16n8k8.row.col.f32.tf32.tf32.f32 "
        "{%0,%1,%2,%3}, {%4,%5,%6,%7}, {%8,%9}, {%0,%1,%2,%3};"
        : "+f"(c[0]), "+f"(c[1]), "+f"(c[2]), "+f"(c[3])
        : "r"(a[0]), "r"(a[1]), "r"(a[2]), "r"(a[3]), "r"(b0), "r"(b1));
}

// ---------------------------------------------------------------------------
// Kernel 1: combined weights  Wc[j][c] = sum_t qkv_w[j][t] * proj_w[t][c],
// written as tf32 (hi, lo) pair.  grid (576, 2), block 384
// ---------------------------------------------------------------------------
__global__ void combine_w_kernel(const float* __restrict__ p1,
                                 const float* __restrict__ p2,
                                 const float* __restrict__ qu,
                                 const float* __restrict__ qd) {
    int j = blockIdx.x;
    int line = blockIdx.y;
    int c = threadIdx.x;
    const float* qw = line ? qd : qu;
    const float* pw = line ? p2 : p1;
    const float* qrow = qw + j * 192;
    float s = 0.f;
#pragma unroll 8
    for (int t = 0; t < 192; t++)
        s += qrow[t] * pw[t * 384 + c];
    float hi = __uint_as_float(f2tf32(s));
    float lo = __uint_as_float(f2tf32(s - hi));
    g_wchi[line][j * 384 + c] = hi;
    g_wclo[line][j * 384 + c] = lo;
}

// ---------------------------------------------------------------------------
// Kernel 1b: split xa into tf32 (hi, lo).  1,204,224 float4s.
// ---------------------------------------------------------------------------
__global__ void __launch_bounds__(256) split_xa_kernel(const float* __restrict__ xa) {
    int idx = blockIdx.x * 256 + threadIdx.x;
    if (idx >= NB * DIMC * NTOK / 4) return;
    float4 v = ((const float4*)xa)[idx];
    float4 h, l;
    h.x = __uint_as_float(f2tf32(v.x)); l.x = __uint_as_float(f2tf32(v.x - h.x));
    h.y = __uint_as_float(f2tf32(v.y)); l.y = __uint_as_float(f2tf32(v.y - h.y));
    h.z = __uint_as_float(f2tf32(v.z)); l.z = __uint_as_float(f2tf32(v.z - h.z));
    h.w = __uint_as_float(f2tf32(v.w)); l.w = __uint_as_float(f2tf32(v.w - h.w));
    ((float4*)g_xhi)[idx] = h;
    ((float4*)g_xlo)[idx] = l;
}

// ---------------------------------------------------------------------------
// Kernel 2: qkv GEMM on tensor cores, 3xTF32 (Ah*Bh + Ah*Bl + Al*Bh).
// out[b,n,j] = sum_c xa[b,c,n] * Wc[line][j,c]
// CTA = 64 tokens x 64 j, 4 warps (each 16 x 64). K chunks of 16, cp.async
// double buffered. grid (49, 9, 8=b*2+line), block 128. smem ~38 KB static.
// ---------------------------------------------------------------------------
#define GK    16
#define ASTR  72      // A smem [k=16][m=64] row stride (conflict-free frags)
#define BSTR  20      // B smem [j=64][k=16] row stride (conflict-free frags)

__global__ void __launch_bounds__(128) qkv_mma_kernel() {
    __shared__ float Ah[2][GK * ASTR], Al[2][GK * ASTR];
    __shared__ float Bh[2][64 * BSTR], Bl[2][64 * BSTR];

    int z = blockIdx.z;
    int bb = z >> 1, line = z & 1;
    int n0 = blockIdx.x * 64;
    int j0 = blockIdx.y * 64;
    const float* Xh = g_xhi + (size_t)bb * DIMC * NTOK;
    const float* Xl = g_xlo + (size_t)bb * DIMC * NTOK;
    const float* Wh = g_wchi[line];
    const float* Wl = g_wclo[line];

    int tid = threadIdx.x;
    int warp = tid >> 5, lane = tid & 31;
    int g = lane >> 2, t = lane & 3;
    int m0 = warp * 16;

    float o[8][4];
#pragma unroll
    for (int nt = 0; nt < 8; nt++)
        o[nt][0] = o[nt][1] = o[nt][2] = o[nt][3] = 0.f;

    auto load_chunk = [&](int ch, int buf) {
        int c0 = ch * GK;
        // A: 16 k-rows x 64 tokens (contiguous in n) for hi and lo
#pragma unroll
        for (int i = 0; i < 2; i++) {
            int task = tid + i * 128;               // 0..255
            int kr = task >> 4, c4 = (task & 15) * 4;
            const float* sh = &Xh[(size_t)(c0 + kr) * NTOK + n0 + c4];
            const float* sl = &Xl[(size_t)(c0 + kr) * NTOK + n0 + c4];
            cp_async16(&Ah[buf][kr * ASTR + c4], sh);
            cp_async16(&Al[buf][kr * ASTR + c4], sl);
        }
        // B: 64 j-rows x 16 channels (contiguous in c) for hi and lo
#pragma unroll
        for (int i = 0; i < 2; i++) {
            int task = tid + i * 128;               // 0..255
            int jr = task >> 2, c4 = (task & 3) * 4;
            cp_async16(&Bh[buf][jr * BSTR + c4], &Wh[(j0 + jr) * 384 + c0 + c4]);
            cp_async16(&Bl[buf][jr * BSTR + c4], &Wl[(j0 + jr) * 384 + c0 + c4]);
        }
        asm volatile("cp.async.commit_group;\n" ::: "memory");
    };

    load_chunk(0, 0);

    for (int ch = 0; ch < 24; ch++) {
        int cur = ch & 1;
        if (ch < 23) {
            load_chunk(ch + 1, cur ^ 1);
            asm volatile("cp.async.wait_group 1;\n" ::: "memory");
        } else {
            asm volatile("cp.async.wait_group 0;\n" ::: "memory");
        }
        __syncthreads();

#pragma unroll
        for (int kc = 0; kc < 2; kc++) {
            int kb = kc * 8;
            unsigned ah[4], al[4];
            ah[0] = __float_as_uint(Ah[cur][(kb + t) * ASTR + m0 + g]);
            ah[1] = __float_as_uint(Ah[cur][(kb + t) * ASTR + m0 + g + 8]);
            ah[2] = __float_as_uint(Ah[cur][(kb + t + 4) * ASTR + m0 + g]);
            ah[3] = __float_as_uint(Ah[cur][(kb + t + 4) * ASTR + m0 + g + 8]);
            al[0] = __float_as_uint(Al[cur][(kb + t) * ASTR + m0 + g]);
            al[1] = __float_as_uint(Al[cur][(kb + t) * ASTR + m0 + g + 8]);
            al[2] = __float_as_uint(Al[cur][(kb + t + 4) * ASTR + m0 + g]);
            al[3] = __float_as_uint(Al[cur][(kb + t + 4) * ASTR + m0 + g + 8]);
#pragma unroll
            for (int nt = 0; nt < 8; nt++) {
                const float* bph = &Bh[cur][(nt * 8 + g) * BSTR + kb];
                const float* bpl = &Bl[cur][(nt * 8 + g) * BSTR + kb];
                unsigned bh0 = __float_as_uint(bph[t]);
                unsigned bh1 = __float_as_uint(bph[t + 4]);
                unsigned bl0 = __float_as_uint(bpl[t]);
                unsigned bl1 = __float_as_uint(bpl[t + 4]);
                mma_tf32(o[nt], ah, bh0, bh1);
                mma_tf32(o[nt], ah, bl0, bl1);
                mma_tf32(o[nt], al, bh0, bh1);
            }
        }
        __syncthreads();
    }

    float* op = g_qkv[line] + (size_t)bb * NTOK * 576;
    int tok0 = n0 + m0 + g, tok1 = tok0 + 8;
#pragma unroll
    for (int nt = 0; nt < 8; nt++) {
        int j = j0 + nt * 8 + 2 * t;
        *(float2*)&op[(size_t)tok0 * 576 + j] = make_float2(o[nt][0], o[nt][1]);
        *(float2*)&op[(size_t)tok1 * 576 + j] = make_float2(o[nt][2], o[nt][3]);
    }
}

// ---------------------------------------------------------------------------
// Kernel 2b: round K/V channels of BOTH lines to tf32 (RN), in place.
// ---------------------------------------------------------------------------
__global__ void __launch_bounds__(256) round_kv_kernel() {
    int idx = blockIdx.x * 256 + threadIdx.x;          // float4 index
    int line = blockIdx.y;
    if (idx >= NB * NTOK * 96) return;
    int row = idx / 96, c4 = idx % 96;
    float4* p = (float4*)&g_qkv[line][(size_t)row * 576 + 192 + c4 * 4];
    float4 v = *p;
    v.x = __uint_as_float(f2tf32(v.x));
    v.y = __uint_as_float(f2tf32(v.y));
    v.z = __uint_as_float(f2tf32(v.z));
    v.w = __uint_as_float(f2tf32(v.w));
    *p = v;
}

// ---------------------------------------------------------------------------
// Kernel 3: CSWin attention (upper line) -- tensor-core flash (R10-passing)
// grid (7 qtiles, 16 = win*2+hh, 8 = bb*2+br), block 128, dyn smem 64 KB.
// ---------------------------------------------------------------------------
#define CSKT 56
#define CSSTRIDE 56
#define CSPSTRIDE 60
#define CSMMA_SMEM (4 * CSKT * CSSTRIDE * 4 + 4 * 16 * CSPSTRIDE * 4)   // 65536

__global__ void __launch_bounds__(128) cswin_mma_kernel(float* __restrict__ out) {
    extern __shared__ float csh[];
    float* Ksm[2] = { csh,                    csh + CSKT * CSSTRIDE };
    float* Vsm[2] = { csh + 2 * CSKT * CSSTRIDE, csh + 3 * CSKT * CSSTRIDE };
    unsigned* Pbase = (unsigned*)(csh + 4 * CSKT * CSSTRIDE);

    int qt = blockIdx.x;
    int win = blockIdx.y >> 1, hh = blockIdx.y & 1;
    int bb = blockIdx.z >> 1, br = blockIdx.z & 1;
    int choff = br * CSC + hh * 48;
    const float* qkv = g_qkv[0] + (size_t)bb * NTOK * 576;
    int tid = threadIdx.x;
    int warp = tid >> 5, lane = tid & 31;
    int g = lane >> 2, t = lane & 3;
    int row0 = qt * 64 + warp * 16;
    unsigned* P = Pbase + warp * 16 * CSPSTRIDE;

    auto tok2n = [&](int c) {
        int hl, wl;
        if (br) { hl = c / 56; wl = c - hl * 56; }
        else    { hl = c / 7;  wl = c - hl * 7;  }
        int h = br ? win * 7 + hl : hl;
        int w = br ? wl : win * 7 + wl;
        return h * RES + w;
    };

    unsigned qa[6][4];
    {
        const float qscale = CS_SCALE * LOG2E;
        int r0c = min(row0 + g, 391), r1c = min(row0 + g + 8, 391);
        const float* q0 = qkv + (size_t)tok2n(r0c) * 576 + choff;
        const float* q8 = qkv + (size_t)tok2n(r1c) * 576 + choff;
#pragma unroll
        for (int kc = 0; kc < 6; kc++) {
            qa[kc][0] = f2tf32(q0[kc * 8 + t] * qscale);
            qa[kc][1] = f2tf32(q8[kc * 8 + t] * qscale);
            qa[kc][2] = f2tf32(q0[kc * 8 + t + 4] * qscale);
            qa[kc][3] = f2tf32(q8[kc * 8 + t + 4] * qscale);
        }
    }

    float o[6][4];
#pragma unroll
    for (int nt = 0; nt < 6; nt++)
        o[nt][0] = o[nt][1] = o[nt][2] = o[nt][3] = 0.f;
    float m0 = -1e30f, m1 = -1e30f, l0 = 0.f, l1 = 0.f;

    auto load_tile = [&](int ti, int buf) {
        float* kd = Ksm[buf];
        float* vd = Vsm[buf];
        for (int i = tid; i < 56 * 12; i += 128) {
            int rr = i / 12, c4 = (i % 12) * 4;
            int n = tok2n(ti * CSKT + rr);
            const float* src = qkv + (size_t)n * 576 + choff + c4;
            cp_async16(kd + rr * CSSTRIDE + c4, src + 192);
            cp_async16(vd + rr * CSSTRIDE + c4, src + 384);
        }
        asm volatile("cp.async.commit_group;\n" ::: "memory");
    };

    load_tile(0, 0);

    for (int ti = 0; ti < 7; ti++) {
        int cur = ti & 1;
        if (ti < 6) {
            load_tile(ti + 1, cur ^ 1);
            asm volatile("cp.async.wait_group 1;\n" ::: "memory");
        } else {
            asm volatile("cp.async.wait_group 0;\n" ::: "memory");
        }
        __syncthreads();

        float s[7][4];
#pragma unroll
        for (int nt = 0; nt < 7; nt++) {
            s[nt][0] = s[nt][1] = s[nt][2] = s[nt][3] = 0.f;
            const float* kb = &Ksm[cur][(nt * 8 + g) * CSSTRIDE];
#pragma unroll
            for (int kc = 0; kc < 6; kc++) {
                unsigned b0 = __float_as_uint(kb[kc * 8 + t]);
                unsigned b1 = __float_as_uint(kb[kc * 8 + t + 4]);
                mma_tf32(s[nt], qa[kc], b0, b1);
            }
        }

        float rmax0 = s[0][0], rmax1 = s[0][2];
#pragma unroll
        for (int nt = 0; nt < 7; nt++) {
            rmax0 = fmaxf(rmax0, fmaxf(s[nt][0], s[nt][1]));
            rmax1 = fmaxf(rmax1, fmaxf(s[nt][2], s[nt][3]));
        }
        rmax0 = fmaxf(rmax0, __shfl_xor_sync(0xffffffffu, rmax0, 1));
        rmax0 = fmaxf(rmax0, __shfl_xor_sync(0xffffffffu, rmax0, 2));
        rmax1 = fmaxf(rmax1, __shfl_xor_sync(0xffffffffu, rmax1, 1));
        rmax1 = fmaxf(rmax1, __shfl_xor_sync(0xffffffffu, rmax1, 2));

        float mn0 = fmaxf(m0, rmax0), mn1 = fmaxf(m1, rmax1);
        float rs0 = exp2f(m0 - mn0),  rs1 = exp2f(m1 - mn1);
        l0 *= rs0; l1 *= rs1;

        float psum0 = 0.f, psum1 = 0.f;
#pragma unroll
        for (int nt = 0; nt < 7; nt++) {
            float p0 = exp2f(s[nt][0] - mn0);
            float p1 = exp2f(s[nt][1] - mn0);
            float p2 = exp2f(s[nt][2] - mn1);
            float p3 = exp2f(s[nt][3] - mn1);
            psum0 += p0 + p1; psum1 += p2 + p3;
            P[g * CSPSTRIDE + nt * 8 + 2 * t]           = f2tf32(p0);
            P[g * CSPSTRIDE + nt * 8 + 2 * t + 1]       = f2tf32(p1);
            P[(g + 8) * CSPSTRIDE + nt * 8 + 2 * t]     = f2tf32(p2);
            P[(g + 8) * CSPSTRIDE + nt * 8 + 2 * t + 1] = f2tf32(p3);
        }
        l0 += psum0; l1 += psum1;
#pragma unroll
        for (int nt = 0; nt < 6; nt++) {
            o[nt][0] *= rs0; o[nt][1] *= rs0;
            o[nt][2] *= rs1; o[nt][3] *= rs1;
        }
        m0 = mn0; m1 = mn1;
        __syncwarp();

#pragma unroll
        for (int kc = 0; kc < 7; kc++) {
            unsigned pa[4];
            pa[0] = P[g * CSPSTRIDE + kc * 8 + t];
            pa[1] = P[(g + 8) * CSPSTRIDE + kc * 8 + t];
            pa[2] = P[g * CSPSTRIDE + kc * 8 + t + 4];
            pa[3] = P[(g + 8) * CSPSTRIDE + kc * 8 + t + 4];
            const float* vb0 = &Vsm[cur][(kc * 8 + t) * CSSTRIDE];
            const float* vb1 = &Vsm[cur][(kc * 8 + t + 4) * CSSTRIDE];
#pragma unroll
            for (int nt = 0; nt < 6; nt++) {
                unsigned b0 = __float_as_uint(vb0[nt * 8 + g]);
                unsigned b1 = __float_as_uint(vb1[nt * 8 + g]);
                mma_tf32(o[nt], pa, b0, b1);
            }
        }
        __syncthreads();
    }

    l0 += __shfl_xor_sync(0xffffffffu, l0, 1);
    l0 += __shfl_xor_sync(0xffffffffu, l0, 2);
    l1 += __shfl_xor_sync(0xffffffffu, l1, 1);
    l1 += __shfl_xor_sync(0xffffffffu, l1, 2);
    float inv0 = 1.f / l0, inv1 = 1.f / l1;

    float* ob = out + ((size_t)bb * DIMC + choff) * NTOK;
    int tok0 = row0 + g, tok1 = row0 + g + 8;
    if (tok0 < 392) {
        int n = tok2n(tok0);
#pragma unroll
        for (int nt = 0; nt < 6; nt++) {
            int d0 = nt * 8 + 2 * t;
            ob[(size_t)d0 * NTOK + n]       = o[nt][0] * inv0;
            ob[(size_t)(d0 + 1) * NTOK + n] = o[nt][1] * inv0;
        }
    }
    if (tok1 < 392) {
        int n = tok2n(tok1);
#pragma unroll
        for (int nt = 0; nt < 6; nt++) {
            int d0 = nt * 8 + 2 * t;
            ob[(size_t)d0 * NTOK + n]       = o[nt][2] * inv1;
            ob[(size_t)(d0 + 1) * NTOK + n] = o[nt][3] * inv1;
        }
    }
}

// ---------------------------------------------------------------------------
// Kernel 3b: LePE (depthwise 3x3 on V) -- ADDS into out.  (R10-passing)
// ---------------------------------------------------------------------------
#define LEPE_SMEM (392 * 48 * 4)

__global__ void __launch_bounds__(256) lepe_kernel(const float* __restrict__ lw0,
                                                   const float* __restrict__ lb0,
                                                   const float* __restrict__ lw1,
                                                   const float* __restrict__ lb1,
                                                   float* __restrict__ out) {
    extern __shared__ float Vs[];   // [392][48]
    __shared__ float wsh[48][9];
    __shared__ float bsh[48];

    int win = blockIdx.x;
    int hh  = blockIdx.y;
    int bb  = blockIdx.z >> 1, br = blockIdx.z & 1;
    int SW = br ? 56 : 7;
    int SH = br ? 7 : 56;
    int choff = br * CSC + hh * 48;
    const float* qkv = g_qkv[0] + (size_t)bb * NTOK * 576;
    int tid = threadIdx.x;

    for (int e = tid; e < 392 * 12; e += 256) {
        int tk = e / 12, d4 = (e % 12) * 4;
        int hl, wl;
        if (br) { hl = tk / 56; wl = tk - hl * 56; }
        else    { hl = tk / 7;  wl = tk - hl * 7;  }
        int h = br ? win * 7 + hl : hl;
        int w = br ? wl : win * 7 + wl;
        int n = h * RES + w;
        *(float4*)&Vs[tk * 48 + d4] = *(const float4*)&qkv[(size_t)n * 576 + choff + 384 + d4];
    }
    const float* lw = br ? lw1 : lw0;
    const float* lb = br ? lb1 : lb0;
    for (int e = tid; e < 48 * 9; e += 256) {
        int d = e / 9, k = e % 9;
        wsh[d][k] = lw[(hh * 48 + d) * 9 + k];
    }
    if (tid < 48) bsh[tid] = lb[hh * 48 + tid];
    __syncthreads();

    for (int e = tid; e < 48 * 392; e += 256) {
        int d = e / 392, r = e - d * 392;
        int hl, wl;
        if (br) { hl = r / 56; wl = r - hl * 56; }
        else    { hl = r / 7;  wl = r - hl * 7;  }
        float lep = bsh[d];
#pragma unroll
        for (int dy = -1; dy <= 1; dy++) {
#pragma unroll
            for (int dx = -1; dx <= 1; dx++) {
                int h2 = hl + dy, w2 = wl + dx;
                if (h2 < 0 || h2 >= SH || w2 < 0 || w2 >= SW) continue;
                lep += Vs[(h2 * SW + w2) * 48 + d] * wsh[d][(dy + 1) * 3 + (dx + 1)];
            }
        }
        int h = br ? win * 7 + hl : hl;
        int w = br ? wl : win * 7 + wl;
        int n = h * RES + w;
        out[((size_t)bb * DIMC + choff + d) * NTOK + n] += lep;
    }
}

// ---------------------------------------------------------------------------
// Kernel 4: global attention (lower line) -- tensor-core flash (R9-passing)
// ---------------------------------------------------------------------------
#define KT 32
#define KSTRIDE 72
#define PSTRIDE 36

__global__ void __launch_bounds__(128) attn_dn_kernel(float* __restrict__ out) {
    __shared__ float    Ksm[2][KT * KSTRIDE];
    __shared__ float    Vsm[2][KT * KSTRIDE];
    __shared__ unsigned Psm[4][16 * PSTRIDE];

    int qt = blockIdx.x, hh = blockIdx.y, bb = blockIdx.z;
    const float* qkv = g_qkv[1] + (size_t)bb * NTOK * 576;
    int tid = threadIdx.x;
    int warp = tid >> 5, lane = tid & 31;
    int g = lane >> 2, t = lane & 3;
    int row0 = qt * 64 + warp * 16;

    unsigned qa[8][4];
    {
        const float qscale = DN_SCALE * LOG2E;
        const float* q0 = qkv + (size_t)(row0 + g) * 576 + hh * 64;
        const float* q8 = qkv + (size_t)(row0 + g + 8) * 576 + hh * 64;
#pragma unroll
        for (int kc = 0; kc < 8; kc++) {
            qa[kc][0] = f2tf32(q0[kc * 8 + t] * qscale);
            qa[kc][1] = f2tf32(q8[kc * 8 + t] * qscale);
            qa[kc][2] = f2tf32(q0[kc * 8 + t + 4] * qscale);
            qa[kc][3] = f2tf32(q8[kc * 8 + t + 4] * qscale);
        }
    }

    float o[8][4];
#pragma unroll
    for (int nt = 0; nt < 8; nt++)
        o[nt][0] = o[nt][1] = o[nt][2] = o[nt][3] = 0.f;
    float m0 = -1e30f, m1 = -1e30f, l0 = 0.f, l1 = 0.f;

    auto load_tile = [&](int kt, int buf) {
#pragma unroll
        for (int i = 0; i < 4; i++) {
            int task = tid * 4 + i;
            int rrow = task >> 4, chunk = task & 15;
            const float* src = qkv + (size_t)(kt * KT + rrow) * 576 + hh * 64 + chunk * 4;
            cp_async16(&Ksm[buf][rrow * KSTRIDE + chunk * 4], src + 192);
            cp_async16(&Vsm[buf][rrow * KSTRIDE + chunk * 4], src + 384);
        }
        asm volatile("cp.async.commit_group;\n" ::: "memory");
    };

    load_tile(0, 0);

    for (int kt = 0; kt < 98; kt++) {
        int cur = kt & 1;
        if (kt < 97) {
            load_tile(kt + 1, cur ^ 1);
            asm volatile("cp.async.wait_group 1;\n" ::: "memory");
        } else {
            asm volatile("cp.async.wait_group 0;\n" ::: "memory");
        }
        __syncthreads();

        float s[4][4];
#pragma unroll
        for (int nt = 0; nt < 4; nt++) {
            s[nt][0] = s[nt][1] = s[nt][2] = s[nt][3] = 0.f;
            const float* kb = &Ksm[cur][(nt * 8 + g) * KSTRIDE];
#pragma unroll
            for (int kc = 0; kc < 8; kc++) {
                unsigned b0 = __float_as_uint(kb[kc * 8 + t]);
                unsigned b1 = __float_as_uint(kb[kc * 8 + t + 4]);
                mma_tf32(s[nt], qa[kc], b0, b1);
            }
        }

        float rmax0 = fmaxf(fmaxf(s[0][0], s[0][1]), fmaxf(s[1][0], s[1][1]));
        rmax0 = fmaxf(rmax0, fmaxf(fmaxf(s[2][0], s[2][1]), fmaxf(s[3][0], s[3][1])));
        float rmax1 = fmaxf(fmaxf(s[0][2], s[0][3]), fmaxf(s[1][2], s[1][3]));
        rmax1 = fmaxf(rmax1, fmaxf(fmaxf(s[2][2], s[2][3]), fmaxf(s[3][2], s[3][3])));
        rmax0 = fmaxf(rmax0, __shfl_xor_sync(0xffffffffu, rmax0, 1));
        rmax0 = fmaxf(rmax0, __shfl_xor_sync(0xffffffffu, rmax0, 2));
        rmax1 = fmaxf(rmax1, __shfl_xor_sync(0xffffffffu, rmax1, 1));
        rmax1 = fmaxf(rmax1, __shfl_xor_sync(0xffffffffu, rmax1, 2));

        float mn0 = fmaxf(m0, rmax0), mn1 = fmaxf(m1, rmax1);
        float rs0 = exp2f(m0 - mn0),  rs1 = exp2f(m1 - mn1);
        l0 *= rs0; l1 *= rs1;

        unsigned* P = Psm[warp];
        float psum0 = 0.f, psum1 = 0.f;
#pragma unroll
        for (int nt = 0; nt < 4; nt++) {
            float p0 = exp2f(s[nt][0] - mn0);
            float p1 = exp2f(s[nt][1] - mn0);
            float p2 = exp2f(s[nt][2] - mn1);
            float p3 = exp2f(s[nt][3] - mn1);
            psum0 += p0 + p1; psum1 += p2 + p3;
            P[g * PSTRIDE + nt * 8 + 2 * t]           = f2tf32(p0);
            P[g * PSTRIDE + nt * 8 + 2 * t + 1]       = f2tf32(p1);
            P[(g + 8) * PSTRIDE + nt * 8 + 2 * t]     = f2tf32(p2);
            P[(g + 8) * PSTRIDE + nt * 8 + 2 * t + 1] = f2tf32(p3);
        }
        l0 += psum0; l1 += psum1;
#pragma unroll
        for (int nt = 0; nt < 8; nt++) {
            o[nt][0] *= rs0; o[nt][1] *= rs0;
            o[nt][2] *= rs1; o[nt][3] *= rs1;
        }
        m0 = mn0; m1 = mn1;
        __syncwarp();

#pragma unroll
        for (int kc = 0; kc < 4; kc++) {
            unsigned pa[4];
            pa[0] = P[g * PSTRIDE + kc * 8 + t];
            pa[1] = P[(g + 8) * PSTRIDE + kc * 8 + t];
            pa[2] = P[g * PSTRIDE + kc * 8 + t + 4];
            pa[3] = P[(g + 8) * PSTRIDE + kc * 8 + t + 4];
            const float* vb0 = &Vsm[cur][(kc * 8 + t) * KSTRIDE];
            const float* vb1 = &Vsm[cur][(kc * 8 + t + 4) * KSTRIDE];
#pragma unroll
            for (int nt = 0; nt < 8; nt++) {
                unsigned b0 = __float_as_uint(vb0[nt * 8 + g]);
                unsigned b1 = __float_as_uint(vb1[nt * 8 + g]);
                mma_tf32(o[nt], pa, b0, b1);
            }
        }
        __syncthreads();
    }

    l0 += __shfl_xor_sync(0xffffffffu, l0, 1);
    l0 += __shfl_xor_sync(0xffffffffu, l0, 2);
    l1 += __shfl_xor_sync(0xffffffffu, l1, 1);
    l1 += __shfl_xor_sync(0xffffffffu, l1, 2);
    float inv0 = 1.f / l0, inv1 = 1.f / l1;

    float* ob = out + ((size_t)bb * DIMC + TD + hh * 64) * NTOK;
    int tok0 = row0 + g, tok1 = row0 + g + 8;
#pragma unroll
    for (int nt = 0; nt < 8; nt++) {
        int d0 = nt * 8 + 2 * t;
        ob[(size_t)d0 * NTOK + tok0]       = o[nt][0] * inv0;
        ob[(size_t)(d0 + 1) * NTOK + tok0] = o[nt][1] * inv0;
        ob[(size_t)d0 * NTOK + tok1]       = o[nt][2] * inv1;
        ob[(size_t)(d0 + 1) * NTOK + tok1] = o[nt][3] * inv1;
    }
}

// ---------------------------------------------------------------------------
// Launch
// ---------------------------------------------------------------------------
extern "C" void kernel_launch(void* const* d_in, const int* in_sizes, int n_in,
                              void* d_out, int out_size) {
    const float* xa      = (const float*)d_in[0];
    const float* proj1_w = (const float*)d_in[1];
    const float* proj2_w = (const float*)d_in[2];
    const float* qkv_u_w = (const float*)d_in[3];
    const float* qkv_d_w = (const float*)d_in[4];
    const float* lepe_w0 = (const float*)d_in[5];
    const float* lepe_b0 = (const float*)d_in[6];
    const float* lepe_w1 = (const float*)d_in[7];
    const float* lepe_b1 = (const float*)d_in[8];
    float* out = (float*)d_out;

    // 1) combined weights (Wqkv @ Wproj), tf32 hi/lo
    combine_w_kernel<<<dim3(576, 2), 384>>>(proj1_w, proj2_w, qkv_u_w, qkv_d_w);

    // 1b) split xa into tf32 hi/lo
    split_xa_kernel<<<(NB * DIMC * NTOK / 4 + 255) / 256, 256>>>(xa);

    // 2) fused proj+qkv GEMM, tensor cores, 3xTF32
    qkv_mma_kernel<<<dim3(49, 9, 8), 128>>>();

    // 2b) round K/V of BOTH lines to tf32 (RN) in place
    round_kv_kernel<<<dim3((NB * NTOK * 96 + 255) / 256, 2), 256>>>();

    // 3) CSWin upper line, tensor cores (writes channels [0,192))
    cudaFuncSetAttribute(cswin_mma_kernel, cudaFuncAttributeMaxDynamicSharedMemorySize, CSMMA_SMEM);
    cswin_mma_kernel<<<dim3(7, 16, 8), 128, CSMMA_SMEM>>>(out);

    // 3b) LePE adds into channels [0,192)
    cudaFuncSetAttribute(lepe_kernel, cudaFuncAttributeMaxDynamicSharedMemorySize, LEPE_SMEM);
    lepe_kernel<<<dim3(8, 2, 8), 256, LEPE_SMEM>>>(lepe_w0, lepe_b0, lepe_w1, lepe_b1, out);

    // 4) global attention lower line, tensor cores (channels [192,384))
    attn_dn_kernel<<<dim3(49, 3, 4), 128>>>(out);
}

// round 12
// speedup vs baseline: 6.3997x; 1.0055x over previous
#include <cuda_runtime.h>
#include <math.h>

// Problem constants
#define NB    4
#define DIMC  384
#define RES   56
#define NTOK  3136          // 56*56
#define TD    192
#define CSC   96

#define LOG2E 1.4426950408889634f
#define CS_SCALE 0.14433756729740643f   // 1/sqrt(48)
#define DN_SCALE 0.125f                 // 1/sqrt(64)

// ---------------------------------------------------------------------------
// Scratch (static device arrays; no allocation anywhere)
// ---------------------------------------------------------------------------
__device__ float g_wchi[2][576 * 384];               // combined weights, tf32 hi
__device__ float g_wclo[2][576 * 384];               // combined weights, tf32 lo
__device__ float g_xhi[NB * DIMC * NTOK];            // xa tf32 hi  [b][c][n]
__device__ float g_xlo[NB * DIMC * NTOK];            // xa tf32 lo
__device__ float g_qkv[2][NB * NTOK * 576];          // [line][((b*3136)+n)*576 + j]

// ---------------------------------------------------------------------------
// Shared helpers
// ---------------------------------------------------------------------------
__device__ __forceinline__ unsigned f2tf32(float f) {
    unsigned u;
    asm("cvt.rna.tf32.f32 %0, %1;" : "=r"(u) : "f"(f));
    return u;
}

__device__ __forceinline__ void cp_async16(void* smem_dst, const void* gsrc) {
    unsigned s = (unsigned)__cvta_generic_to_shared(smem_dst);
    asm volatile("cp.async.cg.shared.global [%0], [%1], 16;\n" :: "r"(s), "l"(gsrc));
}

__device__ __forceinline__ void mma_tf32(float* c, const unsigned* a, unsigned b0, unsigned b1) {
    asm volatile(
        "mma.sync.aligned.m16n8k8.row.col.f32.tf32.tf32.f32 "
        "{%0,%1,%2,%3}, {%4,%5,%6,%7}, {%8,%9}, {%0,%1,%2,%3};"
        : "+f"(c[0]), "+f"(c[1]), "+f"(c[2]), "+f"(c[3])
        : "r"(a[0]), "r"(a[1]), "r"(a[2]), "r"(a[3]), "r"(b0), "r"(b1));
}

// ---------------------------------------------------------------------------
// Kernel 1: combined weights  Wc[j][c] = sum_t qkv_w[j][t] * proj_w[t][c],
// written as tf32 (hi, lo) pair.  grid (576, 2), block 384
// ---------------------------------------------------------------------------
__global__ void combine_w_kernel(const float* __restrict__ p1,
                                 const float* __restrict__ p2,
                                 const float* __restrict__ qu,
                                 const float* __restrict__ qd) {
    int j = blockIdx.x;
    int line = blockIdx.y;
    int c = threadIdx.x;
    const float* qw = line ? qd : qu;
    const float* pw = line ? p2 : p1;
    const float* qrow = qw + j * 192;
    float s = 0.f;
#pragma unroll 8
    for (int t = 0; t < 192; t++)
        s += qrow[t] * pw[t * 384 + c];
    float hi = __uint_as_float(f2tf32(s));
    float lo = __uint_as_float(f2tf32(s - hi));
    g_wchi[line][j * 384 + c] = hi;
    g_wclo[line][j * 384 + c] = lo;
}

// ---------------------------------------------------------------------------
// Kernel 1b: split xa into tf32 (hi, lo).
// ---------------------------------------------------------------------------
__global__ void __launch_bounds__(256) split_xa_kernel(const float* __restrict__ xa) {
    int idx = blockIdx.x * 256 + threadIdx.x;
    if (idx >= NB * DIMC * NTOK / 4) return;
    float4 v = ((const float4*)xa)[idx];
    float4 h, l;
    h.x = __uint_as_float(f2tf32(v.x)); l.x = __uint_as_float(f2tf32(v.x - h.x));
    h.y = __uint_as_float(f2tf32(v.y)); l.y = __uint_as_float(f2tf32(v.y - h.y));
    h.z = __uint_as_float(f2tf32(v.z)); l.z = __uint_as_float(f2tf32(v.z - h.z));
    h.w = __uint_as_float(f2tf32(v.w)); l.w = __uint_as_float(f2tf32(v.w - h.w));
    ((float4*)g_xhi)[idx] = h;
    ((float4*)g_xlo)[idx] = l;
}

// ---------------------------------------------------------------------------
// Kernel 2: qkv GEMM, tensor cores, 3xTF32, BIG TILES (64 tokens x 192 j).
// 8 warps in 4m x 2n grid; each warp 16 x 96 (12 n-frags). K chunks of 16,
// cp.async double buffered. K/V tf32 rounding FUSED into epilogue
// (j-tile 0 = Q exactly; tiles 1,2 = K,V).
// grid (49, 3, 8=b*2+line), block 256, dyn smem 79872 B (2 CTAs/SM).
// ---------------------------------------------------------------------------
#define GK    16
#define ASTR  72      // A smem [k=16][m=64] row stride
#define BSTR  20      // B smem [j=192][k=16] row stride
#define QKV_SMEM ((2 * GK * ASTR * 2 + 2 * 192 * BSTR * 2) * 4)   // 79872

__global__ void __launch_bounds__(256) qkv_mma_kernel() {
    extern __shared__ float qsh[];
    float* Ah = qsh;                          // [2][16*72]
    float* Al = Ah + 2 * GK * ASTR;
    float* Bh = Al + 2 * GK * ASTR;           // [2][192*20]
    float* Bl = Bh + 2 * 192 * BSTR;

    int z = blockIdx.z;
    int bb = z >> 1, line = z & 1;
    int n0 = blockIdx.x * 64;
    int j0 = blockIdx.y * 192;
    const float* Xh = g_xhi + (size_t)bb * DIMC * NTOK;
    const float* Xl = g_xlo + (size_t)bb * DIMC * NTOK;
    const float* Wh = g_wchi[line];
    const float* Wl = g_wclo[line];

    int tid = threadIdx.x;
    int warp = tid >> 5, lane = tid & 31;
    int g = lane >> 2, t = lane & 3;
    int mrow = (warp & 3) * 16;        // warp's token-row block within 64
    int jbase = (warp >> 2) * 96;      // warp's j block within 192

    float o[12][4];
#pragma unroll
    for (int nt = 0; nt < 12; nt++)
        o[nt][0] = o[nt][1] = o[nt][2] = o[nt][3] = 0.f;

    auto load_chunk = [&](int ch, int buf) {
        int c0 = ch * GK;
        // A: 16 k-rows x 64 tokens, hi+lo  (256 float4 each)
        {
            int kr = tid >> 4, c4 = (tid & 15) * 4;
            cp_async16(&Ah[(buf * GK + kr) * ASTR + c4], &Xh[(size_t)(c0 + kr) * NTOK + n0 + c4]);
            cp_async16(&Al[(buf * GK + kr) * ASTR + c4], &Xl[(size_t)(c0 + kr) * NTOK + n0 + c4]);
        }
        // B: 192 j-rows x 16 channels, hi+lo (768 float4 each)
#pragma unroll
        for (int i = 0; i < 3; i++) {
            int task = tid + i * 256;               // 0..767
            int jr = task >> 2, c4 = (task & 3) * 4;
            cp_async16(&Bh[(buf * 192 + jr) * BSTR + c4], &Wh[(j0 + jr) * 384 + c0 + c4]);
            cp_async16(&Bl[(buf * 192 + jr) * BSTR + c4], &Wl[(j0 + jr) * 384 + c0 + c4]);
        }
        asm volatile("cp.async.commit_group;\n" ::: "memory");
    };

    load_chunk(0, 0);

    for (int ch = 0; ch < 24; ch++) {
        int cur = ch & 1;
        if (ch < 23) {
            load_chunk(ch + 1, cur ^ 1);
            asm volatile("cp.async.wait_group 1;\n" ::: "memory");
        } else {
            asm volatile("cp.async.wait_group 0;\n" ::: "memory");
        }
        __syncthreads();

        const float* Ahc = &Ah[cur * GK * ASTR];
        const float* Alc = &Al[cur * GK * ASTR];
        const float* Bhc = &Bh[cur * 192 * BSTR];
        const float* Blc = &Bl[cur * 192 * BSTR];

#pragma unroll
        for (int kc = 0; kc < 2; kc++) {
            int kb = kc * 8;
            unsigned ah[4], al[4];
            ah[0] = __float_as_uint(Ahc[(kb + t) * ASTR + mrow + g]);
            ah[1] = __float_as_uint(Ahc[(kb + t) * ASTR + mrow + g + 8]);
            ah[2] = __float_as_uint(Ahc[(kb + t + 4) * ASTR + mrow + g]);
            ah[3] = __float_as_uint(Ahc[(kb + t + 4) * ASTR + mrow + g + 8]);
            al[0] = __float_as_uint(Alc[(kb + t) * ASTR + mrow + g]);
            al[1] = __float_as_uint(Alc[(kb + t) * ASTR + mrow + g + 8]);
            al[2] = __float_as_uint(Alc[(kb + t + 4) * ASTR + mrow + g]);
            al[3] = __float_as_uint(Alc[(kb + t + 4) * ASTR + mrow + g + 8]);
#pragma unroll
            for (int nt = 0; nt < 12; nt++) {
                const float* bph = &Bhc[(jbase + nt * 8 + g) * BSTR + kb];
                const float* bpl = &Blc[(jbase + nt * 8 + g) * BSTR + kb];
                unsigned bh0 = __float_as_uint(bph[t]);
                unsigned bh1 = __float_as_uint(bph[t + 4]);
                unsigned bl0 = __float_as_uint(bpl[t]);
                unsigned bl1 = __float_as_uint(bpl[t + 4]);
                mma_tf32(o[nt], ah, bh0, bh1);
                mma_tf32(o[nt], ah, bl0, bl1);
                mma_tf32(o[nt], al, bh0, bh1);
            }
        }
        __syncthreads();
    }

    // epilogue: j-tile 0 is Q (store raw); tiles 1,2 are K,V (round to tf32)
    bool doRound = (blockIdx.y > 0);
    float* op = g_qkv[line] + (size_t)bb * NTOK * 576;
    int tok0 = n0 + mrow + g, tok1 = tok0 + 8;
#pragma unroll
    for (int nt = 0; nt < 12; nt++) {
        int j = j0 + jbase + nt * 8 + 2 * t;
        float v0 = o[nt][0], v1 = o[nt][1], v2 = o[nt][2], v3 = o[nt][3];
        if (doRound) {
            v0 = __uint_as_float(f2tf32(v0));
            v1 = __uint_as_float(f2tf32(v1));
            v2 = __uint_as_float(f2tf32(v2));
            v3 = __uint_as_float(f2tf32(v3));
        }
        *(float2*)&op[(size_t)tok0 * 576 + j] = make_float2(v0, v1);
        *(float2*)&op[(size_t)tok1 * 576 + j] = make_float2(v2, v3);
    }
}

// ---------------------------------------------------------------------------
// Kernel 3: CSWin attention (upper line) -- tensor-core flash (R10/R11-passing)
// grid (7 qtiles, 16 = win*2+hh, 8 = bb*2+br), block 128, dyn smem 64 KB.
// ---------------------------------------------------------------------------
#define CSKT 56
#define CSSTRIDE 56
#define CSPSTRIDE 60
#define CSMMA_SMEM (4 * CSKT * CSSTRIDE * 4 + 4 * 16 * CSPSTRIDE * 4)   // 65536

__global__ void __launch_bounds__(128) cswin_mma_kernel(float* __restrict__ out) {
    extern __shared__ float csh[];
    float* Ksm[2] = { csh,                    csh + CSKT * CSSTRIDE };
    float* Vsm[2] = { csh + 2 * CSKT * CSSTRIDE, csh + 3 * CSKT * CSSTRIDE };
    unsigned* Pbase = (unsigned*)(csh + 4 * CSKT * CSSTRIDE);

    int qt = blockIdx.x;
    int win = blockIdx.y >> 1, hh = blockIdx.y & 1;
    int bb = blockIdx.z >> 1, br = blockIdx.z & 1;
    int choff = br * CSC + hh * 48;
    const float* qkv = g_qkv[0] + (size_t)bb * NTOK * 576;
    int tid = threadIdx.x;
    int warp = tid >> 5, lane = tid & 31;
    int g = lane >> 2, t = lane & 3;
    int row0 = qt * 64 + warp * 16;
    unsigned* P = Pbase + warp * 16 * CSPSTRIDE;

    auto tok2n = [&](int c) {
        int hl, wl;
        if (br) { hl = c / 56; wl = c - hl * 56; }
        else    { hl = c / 7;  wl = c - hl * 7;  }
        int h = br ? win * 7 + hl : hl;
        int w = br ? wl : win * 7 + wl;
        return h * RES + w;
    };

    unsigned qa[6][4];
    {
        const float qscale = CS_SCALE * LOG2E;
        int r0c = min(row0 + g, 391), r1c = min(row0 + g + 8, 391);
        const float* q0 = qkv + (size_t)tok2n(r0c) * 576 + choff;
        const float* q8 = qkv + (size_t)tok2n(r1c) * 576 + choff;
#pragma unroll
        for (int kc = 0; kc < 6; kc++) {
            qa[kc][0] = f2tf32(q0[kc * 8 + t] * qscale);
            qa[kc][1] = f2tf32(q8[kc * 8 + t] * qscale);
            qa[kc][2] = f2tf32(q0[kc * 8 + t + 4] * qscale);
            qa[kc][3] = f2tf32(q8[kc * 8 + t + 4] * qscale);
        }
    }

    float o[6][4];
#pragma unroll
    for (int nt = 0; nt < 6; nt++)
        o[nt][0] = o[nt][1] = o[nt][2] = o[nt][3] = 0.f;
    float m0 = -1e30f, m1 = -1e30f, l0 = 0.f, l1 = 0.f;

    auto load_tile = [&](int ti, int buf) {
        float* kd = Ksm[buf];
        float* vd = Vsm[buf];
        for (int i = tid; i < 56 * 12; i += 128) {
            int rr = i / 12, c4 = (i % 12) * 4;
            int n = tok2n(ti * CSKT + rr);
            const float* src = qkv + (size_t)n * 576 + choff + c4;
            cp_async16(kd + rr * CSSTRIDE + c4, src + 192);
            cp_async16(vd + rr * CSSTRIDE + c4, src + 384);
        }
        asm volatile("cp.async.commit_group;\n" ::: "memory");
    };

    load_tile(0, 0);

    for (int ti = 0; ti < 7; ti++) {
        int cur = ti & 1;
        if (ti < 6) {
            load_tile(ti + 1, cur ^ 1);
            asm volatile("cp.async.wait_group 1;\n" ::: "memory");
        } else {
            asm volatile("cp.async.wait_group 0;\n" ::: "memory");
        }
        __syncthreads();

        float s[7][4];
#pragma unroll
        for (int nt = 0; nt < 7; nt++) {
            s[nt][0] = s[nt][1] = s[nt][2] = s[nt][3] = 0.f;
            const float* kb = &Ksm[cur][(nt * 8 + g) * CSSTRIDE];
#pragma unroll
            for (int kc = 0; kc < 6; kc++) {
                unsigned b0 = __float_as_uint(kb[kc * 8 + t]);
                unsigned b1 = __float_as_uint(kb[kc * 8 + t + 4]);
                mma_tf32(s[nt], qa[kc], b0, b1);
            }
        }

        float rmax0 = s[0][0], rmax1 = s[0][2];
#pragma unroll
        for (int nt = 0; nt < 7; nt++) {
            rmax0 = fmaxf(rmax0, fmaxf(s[nt][0], s[nt][1]));
            rmax1 = fmaxf(rmax1, fmaxf(s[nt][2], s[nt][3]));
        }
        rmax0 = fmaxf(rmax0, __shfl_xor_sync(0xffffffffu, rmax0, 1));
        rmax0 = fmaxf(rmax0, __shfl_xor_sync(0xffffffffu, rmax0, 2));
        rmax1 = fmaxf(rmax1, __shfl_xor_sync(0xffffffffu, rmax1, 1));
        rmax1 = fmaxf(rmax1, __shfl_xor_sync(0xffffffffu, rmax1, 2));

        float mn0 = fmaxf(m0, rmax0), mn1 = fmaxf(m1, rmax1);
        float rs0 = exp2f(m0 - mn0),  rs1 = exp2f(m1 - mn1);
        l0 *= rs0; l1 *= rs1;

        float psum0 = 0.f, psum1 = 0.f;
#pragma unroll
        for (int nt = 0; nt < 7; nt++) {
            float p0 = exp2f(s[nt][0] - mn0);
            float p1 = exp2f(s[nt][1] - mn0);
            float p2 = exp2f(s[nt][2] - mn1);
            float p3 = exp2f(s[nt][3] - mn1);
            psum0 += p0 + p1; psum1 += p2 + p3;
            P[g * CSPSTRIDE + nt * 8 + 2 * t]           = f2tf32(p0);
            P[g * CSPSTRIDE + nt * 8 + 2 * t + 1]       = f2tf32(p1);
            P[(g + 8) * CSPSTRIDE + nt * 8 + 2 * t]     = f2tf32(p2);
            P[(g + 8) * CSPSTRIDE + nt * 8 + 2 * t + 1] = f2tf32(p3);
        }
        l0 += psum0; l1 += psum1;
#pragma unroll
        for (int nt = 0; nt < 6; nt++) {
            o[nt][0] *= rs0; o[nt][1] *= rs0;
            o[nt][2] *= rs1; o[nt][3] *= rs1;
        }
        m0 = mn0; m1 = mn1;
        __syncwarp();

#pragma unroll
        for (int kc = 0; kc < 7; kc++) {
            unsigned pa[4];
            pa[0] = P[g * CSPSTRIDE + kc * 8 + t];
            pa[1] = P[(g + 8) * CSPSTRIDE + kc * 8 + t];
            pa[2] = P[g * CSPSTRIDE + kc * 8 + t + 4];
            pa[3] = P[(g + 8) * CSPSTRIDE + kc * 8 + t + 4];
            const float* vb0 = &Vsm[cur][(kc * 8 + t) * CSSTRIDE];
            const float* vb1 = &Vsm[cur][(kc * 8 + t + 4) * CSSTRIDE];
#pragma unroll
            for (int nt = 0; nt < 6; nt++) {
                unsigned b0 = __float_as_uint(vb0[nt * 8 + g]);
                unsigned b1 = __float_as_uint(vb1[nt * 8 + g]);
                mma_tf32(o[nt], pa, b0, b1);
            }
        }
        __syncthreads();
    }

    l0 += __shfl_xor_sync(0xffffffffu, l0, 1);
    l0 += __shfl_xor_sync(0xffffffffu, l0, 2);
    l1 += __shfl_xor_sync(0xffffffffu, l1, 1);
    l1 += __shfl_xor_sync(0xffffffffu, l1, 2);
    float inv0 = 1.f / l0, inv1 = 1.f / l1;

    float* ob = out + ((size_t)bb * DIMC + choff) * NTOK;
    int tok0 = row0 + g, tok1 = row0 + g + 8;
    if (tok0 < 392) {
        int n = tok2n(tok0);
#pragma unroll
        for (int nt = 0; nt < 6; nt++) {
            int d0 = nt * 8 + 2 * t;
            ob[(size_t)d0 * NTOK + n]       = o[nt][0] * inv0;
            ob[(size_t)(d0 + 1) * NTOK + n] = o[nt][1] * inv0;
        }
    }
    if (tok1 < 392) {
        int n = tok2n(tok1);
#pragma unroll
        for (int nt = 0; nt < 6; nt++) {
            int d0 = nt * 8 + 2 * t;
            ob[(size_t)d0 * NTOK + n]       = o[nt][2] * inv1;
            ob[(size_t)(d0 + 1) * NTOK + n] = o[nt][3] * inv1;
        }
    }
}

// ---------------------------------------------------------------------------
// Kernel 3b: LePE (depthwise 3x3 on V) -- ADDS into out.  (R10/R11-passing)
// ---------------------------------------------------------------------------
#define LEPE_SMEM (392 * 48 * 4)

__global__ void __launch_bounds__(256) lepe_kernel(const float* __restrict__ lw0,
                                                   const float* __restrict__ lb0,
                                                   const float* __restrict__ lw1,
                                                   const float* __restrict__ lb1,
                                                   float* __restrict__ out) {
    extern __shared__ float Vs[];   // [392][48]
    __shared__ float wsh[48][9];
    __shared__ float bsh[48];

    int win = blockIdx.x;
    int hh  = blockIdx.y;
    int bb  = blockIdx.z >> 1, br = blockIdx.z & 1;
    int SW = br ? 56 : 7;
    int SH = br ? 7 : 56;
    int choff = br * CSC + hh * 48;
    const float* qkv = g_qkv[0] + (size_t)bb * NTOK * 576;
    int tid = threadIdx.x;

    for (int e = tid; e < 392 * 12; e += 256) {
        int tk = e / 12, d4 = (e % 12) * 4;
        int hl, wl;
        if (br) { hl = tk / 56; wl = tk - hl * 56; }
        else    { hl = tk / 7;  wl = tk - hl * 7;  }
        int h = br ? win * 7 + hl : hl;
        int w = br ? wl : win * 7 + wl;
        int n = h * RES + w;
        *(float4*)&Vs[tk * 48 + d4] = *(const float4*)&qkv[(size_t)n * 576 + choff + 384 + d4];
    }
    const float* lw = br ? lw1 : lw0;
    const float* lb = br ? lb1 : lb0;
    for (int e = tid; e < 48 * 9; e += 256) {
        int d = e / 9, k = e % 9;
        wsh[d][k] = lw[(hh * 48 + d) * 9 + k];
    }
    if (tid < 48) bsh[tid] = lb[hh * 48 + tid];
    __syncthreads();

    for (int e = tid; e < 48 * 392; e += 256) {
        int d = e / 392, r = e - d * 392;
        int hl, wl;
        if (br) { hl = r / 56; wl = r - hl * 56; }
        else    { hl = r / 7;  wl = r - hl * 7;  }
        float lep = bsh[d];
#pragma unroll
        for (int dy = -1; dy <= 1; dy++) {
#pragma unroll
            for (int dx = -1; dx <= 1; dx++) {
                int h2 = hl + dy, w2 = wl + dx;
                if (h2 < 0 || h2 >= SH || w2 < 0 || w2 >= SW) continue;
                lep += Vs[(h2 * SW + w2) * 48 + d] * wsh[d][(dy + 1) * 3 + (dx + 1)];
            }
        }
        int h = br ? win * 7 + hl : hl;
        int w = br ? wl : win * 7 + wl;
        int n = h * RES + w;
        out[((size_t)bb * DIMC + choff + d) * NTOK + n] += lep;
    }
}

// ---------------------------------------------------------------------------
// Kernel 4: global attention (lower line) -- tensor-core flash (R9-passing)
// ---------------------------------------------------------------------------
#define KT 32
#define KSTRIDE 72
#define PSTRIDE 36

__global__ void __launch_bounds__(128) attn_dn_kernel(float* __restrict__ out) {
    __shared__ float    Ksm[2][KT * KSTRIDE];
    __shared__ float    Vsm[2][KT * KSTRIDE];
    __shared__ unsigned Psm[4][16 * PSTRIDE];

    int qt = blockIdx.x, hh = blockIdx.y, bb = blockIdx.z;
    const float* qkv = g_qkv[1] + (size_t)bb * NTOK * 576;
    int tid = threadIdx.x;
    int warp = tid >> 5, lane = tid & 31;
    int g = lane >> 2, t = lane & 3;
    int row0 = qt * 64 + warp * 16;

    unsigned qa[8][4];
    {
        const float qscale = DN_SCALE * LOG2E;
        const float* q0 = qkv + (size_t)(row0 + g) * 576 + hh * 64;
        const float* q8 = qkv + (size_t)(row0 + g + 8) * 576 + hh * 64;
#pragma unroll
        for (int kc = 0; kc < 8; kc++) {
            qa[kc][0] = f2tf32(q0[kc * 8 + t] * qscale);
            qa[kc][1] = f2tf32(q8[kc * 8 + t] * qscale);
            qa[kc][2] = f2tf32(q0[kc * 8 + t + 4] * qscale);
            qa[kc][3] = f2tf32(q8[kc * 8 + t + 4] * qscale);
        }
    }

    float o[8][4];
#pragma unroll
    for (int nt = 0; nt < 8; nt++)
        o[nt][0] = o[nt][1] = o[nt][2] = o[nt][3] = 0.f;
    float m0 = -1e30f, m1 = -1e30f, l0 = 0.f, l1 = 0.f;

    auto load_tile = [&](int kt, int buf) {
#pragma unroll
        for (int i = 0; i < 4; i++) {
            int task = tid * 4 + i;
            int rrow = task >> 4, chunk = task & 15;
            const float* src = qkv + (size_t)(kt * KT + rrow) * 576 + hh * 64 + chunk * 4;
            cp_async16(&Ksm[buf][rrow * KSTRIDE + chunk * 4], src + 192);
            cp_async16(&Vsm[buf][rrow * KSTRIDE + chunk * 4], src + 384);
        }
        asm volatile("cp.async.commit_group;\n" ::: "memory");
    };

    load_tile(0, 0);

    for (int kt = 0; kt < 98; kt++) {
        int cur = kt & 1;
        if (kt < 97) {
            load_tile(kt + 1, cur ^ 1);
            asm volatile("cp.async.wait_group 1;\n" ::: "memory");
        } else {
            asm volatile("cp.async.wait_group 0;\n" ::: "memory");
        }
        __syncthreads();

        float s[4][4];
#pragma unroll
        for (int nt = 0; nt < 4; nt++) {
            s[nt][0] = s[nt][1] = s[nt][2] = s[nt][3] = 0.f;
            const float* kb = &Ksm[cur][(nt * 8 + g) * KSTRIDE];
#pragma unroll
            for (int kc = 0; kc < 8; kc++) {
                unsigned b0 = __float_as_uint(kb[kc * 8 + t]);
                unsigned b1 = __float_as_uint(kb[kc * 8 + t + 4]);
                mma_tf32(s[nt], qa[kc], b0, b1);
            }
        }

        float rmax0 = fmaxf(fmaxf(s[0][0], s[0][1]), fmaxf(s[1][0], s[1][1]));
        rmax0 = fmaxf(rmax0, fmaxf(fmaxf(s[2][0], s[2][1]), fmaxf(s[3][0], s[3][1])));
        float rmax1 = fmaxf(fmaxf(s[0][2], s[0][3]), fmaxf(s[1][2], s[1][3]));
        rmax1 = fmaxf(rmax1, fmaxf(fmaxf(s[2][2], s[2][3]), fmaxf(s[3][2], s[3][3])));
        rmax0 = fmaxf(rmax0, __shfl_xor_sync(0xffffffffu, rmax0, 1));
        rmax0 = fmaxf(rmax0, __shfl_xor_sync(0xffffffffu, rmax0, 2));
        rmax1 = fmaxf(rmax1, __shfl_xor_sync(0xffffffffu, rmax1, 1));
        rmax1 = fmaxf(rmax1, __shfl_xor_sync(0xffffffffu, rmax1, 2));

        float mn0 = fmaxf(m0, rmax0), mn1 = fmaxf(m1, rmax1);
        float rs0 = exp2f(m0 - mn0),  rs1 = exp2f(m1 - mn1);
        l0 *= rs0; l1 *= rs1;

        unsigned* P = Psm[warp];
        float psum0 = 0.f, psum1 = 0.f;
#pragma unroll
        for (int nt = 0; nt < 4; nt++) {
            float p0 = exp2f(s[nt][0] - mn0);
            float p1 = exp2f(s[nt][1] - mn0);
            float p2 = exp2f(s[nt][2] - mn1);
            float p3 = exp2f(s[nt][3] - mn1);
            psum0 += p0 + p1; psum1 += p2 + p3;
            P[g * PSTRIDE + nt * 8 + 2 * t]           = f2tf32(p0);
            P[g * PSTRIDE + nt * 8 + 2 * t + 1]       = f2tf32(p1);
            P[(g + 8) * PSTRIDE + nt * 8 + 2 * t]     = f2tf32(p2);
            P[(g + 8) * PSTRIDE + nt * 8 + 2 * t + 1] = f2tf32(p3);
        }
        l0 += psum0; l1 += psum1;
#pragma unroll
        for (int nt = 0; nt < 8; nt++) {
            o[nt][0] *= rs0; o[nt][1] *= rs0;
            o[nt][2] *= rs1; o[nt][3] *= rs1;
        }
        m0 = mn0; m1 = mn1;
        __syncwarp();

#pragma unroll
        for (int kc = 0; kc < 4; kc++) {
            unsigned pa[4];
            pa[0] = P[g * PSTRIDE + kc * 8 + t];
            pa[1] = P[(g + 8) * PSTRIDE + kc * 8 + t];
            pa[2] = P[g * PSTRIDE + kc * 8 + t + 4];
            pa[3] = P[(g + 8) * PSTRIDE + kc * 8 + t + 4];
            const float* vb0 = &Vsm[cur][(kc * 8 + t) * KSTRIDE];
            const float* vb1 = &Vsm[cur][(kc * 8 + t + 4) * KSTRIDE];
#pragma unroll
            for (int nt = 0; nt < 8; nt++) {
                unsigned b0 = __float_as_uint(vb0[nt * 8 + g]);
                unsigned b1 = __float_as_uint(vb1[nt * 8 + g]);
                mma_tf32(o[nt], pa, b0, b1);
            }
        }
        __syncthreads();
    }

    l0 += __shfl_xor_sync(0xffffffffu, l0, 1);
    l0 += __shfl_xor_sync(0xffffffffu, l0, 2);
    l1 += __shfl_xor_sync(0xffffffffu, l1, 1);
    l1 += __shfl_xor_sync(0xffffffffu, l1, 2);
    float inv0 = 1.f / l0, inv1 = 1.f / l1;

    float* ob = out + ((size_t)bb * DIMC + TD + hh * 64) * NTOK;
    int tok0 = row0 + g, tok1 = row0 + g + 8;
#pragma unroll
    for (int nt = 0; nt < 8; nt++) {
        int d0 = nt * 8 + 2 * t;
        ob[(size_t)d0 * NTOK + tok0]       = o[nt][0] * inv0;
        ob[(size_t)(d0 + 1) * NTOK + tok0] = o[nt][1] * inv0;
        ob[(size_t)d0 * NTOK + tok1]       = o[nt][2] * inv1;
        ob[(size_t)(d0 + 1) * NTOK + tok1] = o[nt][3] * inv1;
    }
}

// ---------------------------------------------------------------------------
// Launch
// ---------------------------------------------------------------------------
extern "C" void kernel_launch(void* const* d_in, const int* in_sizes, int n_in,
                              void* d_out, int out_size) {
    const float* xa      = (const float*)d_in[0];
    const float* proj1_w = (const float*)d_in[1];
    const float* proj2_w = (const float*)d_in[2];
    const float* qkv_u_w = (const float*)d_in[3];
    const float* qkv_d_w = (const float*)d_in[4];
    const float* lepe_w0 = (const float*)d_in[5];
    const float* lepe_b0 = (const float*)d_in[6];
    const float* lepe_w1 = (const float*)d_in[7];
    const float* lepe_b1 = (const float*)d_in[8];
    float* out = (float*)d_out;

    // 1) combined weights (Wqkv @ Wproj), tf32 hi/lo
    combine_w_kernel<<<dim3(576, 2), 384>>>(proj1_w, proj2_w, qkv_u_w, qkv_d_w);

    // 1b) split xa into tf32 hi/lo
    split_xa_kernel<<<(NB * DIMC * NTOK / 4 + 255) / 256, 256>>>(xa);

    // 2) fused proj+qkv GEMM, tensor cores, 3xTF32, big tiles,
    //    K/V tf32 rounding fused into epilogue
    cudaFuncSetAttribute(qkv_mma_kernel, cudaFuncAttributeMaxDynamicSharedMemorySize, QKV_SMEM);
    qkv_mma_kernel<<<dim3(49, 3, 8), 256, QKV_SMEM>>>();

    // 3) CSWin upper line, tensor cores (writes channels [0,192))
    cudaFuncSetAttribute(cswin_mma_kernel, cudaFuncAttributeMaxDynamicSharedMemorySize, CSMMA_SMEM);
    cswin_mma_kernel<<<dim3(7, 16, 8), 128, CSMMA_SMEM>>>(out);

    // 3b) LePE adds into channels [0,192)
    cudaFuncSetAttribute(lepe_kernel, cudaFuncAttributeMaxDynamicSharedMemorySize, LEPE_SMEM);
    lepe_kernel<<<dim3(8, 2, 8), 256, LEPE_SMEM>>>(lepe_w0, lepe_b0, lepe_w1, lepe_b1, out);

    // 4) global attention lower line, tensor cores (channels [192,384))
    attn_dn_kernel<<<dim3(49, 3, 4), 128>>>(out);
}

// round 14
// speedup vs baseline: 6.4697x; 1.0109x over previous
#include <cuda_runtime.h>
#include <math.h>

// Problem constants
#define NB    4
#define DIMC  384
#define RES   56
#define NTOK  3136          // 56*56
#define TD    192
#define CSC   96

#define LOG2E 1.4426950408889634f
#define CS_SCALE 0.14433756729740643f   // 1/sqrt(48)
#define DN_SCALE 0.125f                 // 1/sqrt(64)

// ---------------------------------------------------------------------------
// Scratch (static device arrays; no allocation anywhere)
// ---------------------------------------------------------------------------
__device__ float g_wchi[2][576 * 384];               // combined weights, tf32 hi
__device__ float g_wclo[2][576 * 384];               // combined weights, tf32 lo
__device__ float g_xhi[NB * DIMC * NTOK];            // xa tf32 hi  [b][c][n]
__device__ float g_xlo[NB * DIMC * NTOK];            // xa tf32 lo
__device__ float g_qkv[2][NB * NTOK * 576];          // [line][((b*3136)+n)*576 + j]

// ---------------------------------------------------------------------------
// Shared helpers
// ---------------------------------------------------------------------------
__device__ __forceinline__ unsigned f2tf32(float f) {
    unsigned u;
    asm("cvt.rna.tf32.f32 %0, %1;" : "=r"(u) : "f"(f));
    return u;
}

__device__ __forceinline__ void cp_async16(void* smem_dst, const void* gsrc) {
    unsigned s = (unsigned)__cvta_generic_to_shared(smem_dst);
    asm volatile("cp.async.cg.shared.global [%0], [%1], 16;\n" :: "r"(s), "l"(gsrc));
}

__device__ __forceinline__ void mma_tf32(float* c, const unsigned* a, unsigned b0, unsigned b1) {
    asm volatile(
        "mma.sync.aligned.m16n8k8.row.col.f32.tf32.tf32.f32 "
        "{%0,%1,%2,%3}, {%4,%5,%6,%7}, {%8,%9}, {%0,%1,%2,%3};"
        : "+f"(c[0]), "+f"(c[1]), "+f"(c[2]), "+f"(c[3])
        : "r"(a[0]), "r"(a[1]), "r"(a[2]), "r"(a[3]), "r"(b0), "r"(b1));
}

// ---------------------------------------------------------------------------
// Kernel 1: combined weights  Wc[j][c] = sum_t qkv_w[j][t] * proj_w[t][c],
// written as tf32 (hi, lo) pair.  grid (576, 2), block 384
// ---------------------------------------------------------------------------
__global__ void combine_w_kernel(const float* __restrict__ p1,
                                 const float* __restrict__ p2,
                                 const float* __restrict__ qu,
                                 const float* __restrict__ qd) {
    int j = blockIdx.x;
    int line = blockIdx.y;
    int c = threadIdx.x;
    const float* qw = line ? qd : qu;
    const float* pw = line ? p2 : p1;
    const float* qrow = qw + j * 192;
    float s = 0.f;
#pragma unroll 8
    for (int t = 0; t < 192; t++)
        s += qrow[t] * pw[t * 384 + c];
    float hi = __uint_as_float(f2tf32(s));
    float lo = __uint_as_float(f2tf32(s - hi));
    g_wchi[line][j * 384 + c] = hi;
    g_wclo[line][j * 384 + c] = lo;
}

// ---------------------------------------------------------------------------
// Kernel 1b: split xa into tf32 (hi, lo).
// ---------------------------------------------------------------------------
__global__ void __launch_bounds__(256) split_xa_kernel(const float* __restrict__ xa) {
    int idx = blockIdx.x * 256 + threadIdx.x;
    if (idx >= NB * DIMC * NTOK / 4) return;
    float4 v = ((const float4*)xa)[idx];
    float4 h, l;
    h.x = __uint_as_float(f2tf32(v.x)); l.x = __uint_as_float(f2tf32(v.x - h.x));
    h.y = __uint_as_float(f2tf32(v.y)); l.y = __uint_as_float(f2tf32(v.y - h.y));
    h.z = __uint_as_float(f2tf32(v.z)); l.z = __uint_as_float(f2tf32(v.z - h.z));
    h.w = __uint_as_float(f2tf32(v.w)); l.w = __uint_as_float(f2tf32(v.w - h.w));
    ((float4*)g_xhi)[idx] = h;
    ((float4*)g_xlo)[idx] = l;
}

// ---------------------------------------------------------------------------
// Kernel 2: qkv GEMM, tensor cores, 3xTF32.
// OCCUPANCY-SHAPED: 128 threads / 4 warps, CTA tile 64 tokens x 96 j
// (each warp 16 x 96, 12 n-frags). regs ~15.4K/CTA, smem 48KB ->
// 4 CTAs/SM = 16 warps/SM. K chunks of 16, cp.async double buffered.
// K/V tf32 rounding fused into epilogue.
// grid (49, 6, 8=b*2+line), block 128, dyn smem 49152 B.
// ---------------------------------------------------------------------------
#define GK    16
#define ASTR  72      // A smem [k=16][m=64] row stride
#define BSTR  20      // B smem [j=96][k=16] row stride
#define QKV_SMEM ((2 * GK * ASTR * 2 + 2 * 96 * BSTR * 2) * 4)   // 49152

__global__ void __launch_bounds__(128, 4) qkv_mma_kernel() {
    extern __shared__ float qsh[];
    float* Ah = qsh;                          // [2][16*72]
    float* Al = Ah + 2 * GK * ASTR;
    float* Bh = Al + 2 * GK * ASTR;           // [2][96*20]
    float* Bl = Bh + 2 * 96 * BSTR;

    int z = blockIdx.z;
    int bb = z >> 1, line = z & 1;
    int n0 = blockIdx.x * 64;
    int j0 = blockIdx.y * 96;
    const float* Xh = g_xhi + (size_t)bb * DIMC * NTOK;
    const float* Xl = g_xlo + (size_t)bb * DIMC * NTOK;
    const float* Wh = g_wchi[line];
    const float* Wl = g_wclo[line];

    int tid = threadIdx.x;
    int warp = tid >> 5, lane = tid & 31;
    int g = lane >> 2, t = lane & 3;
    int mrow = warp * 16;              // warp's token-row block within 64

    float o[12][4];
#pragma unroll
    for (int nt = 0; nt < 12; nt++)
        o[nt][0] = o[nt][1] = o[nt][2] = o[nt][3] = 0.f;

    auto load_chunk = [&](int ch, int buf) {
        int c0 = ch * GK;
        // A: 16 k-rows x 64 tokens, hi+lo (256 float4 each -> 2 per thread)
#pragma unroll
        for (int i = 0; i < 2; i++) {
            int task = tid + i * 128;               // 0..255
            int kr = task >> 4, c4 = (task & 15) * 4;
            cp_async16(&Ah[(buf * GK + kr) * ASTR + c4], &Xh[(size_t)(c0 + kr) * NTOK + n0 + c4]);
            cp_async16(&Al[(buf * GK + kr) * ASTR + c4], &Xl[(size_t)(c0 + kr) * NTOK + n0 + c4]);
        }
        // B: 96 j-rows x 16 channels, hi+lo (384 float4 each -> 3 per thread)
#pragma unroll
        for (int i = 0; i < 3; i++) {
            int task = tid + i * 128;               // 0..383
            int jr = task >> 2, c4 = (task & 3) * 4;
            cp_async16(&Bh[(buf * 96 + jr) * BSTR + c4], &Wh[(j0 + jr) * 384 + c0 + c4]);
            cp_async16(&Bl[(buf * 96 + jr) * BSTR + c4], &Wl[(j0 + jr) * 384 + c0 + c4]);
        }
        asm volatile("cp.async.commit_group;\n" ::: "memory");
    };

    load_chunk(0, 0);

    for (int ch = 0; ch < 24; ch++) {
        int cur = ch & 1;
        if (ch < 23) {
            load_chunk(ch + 1, cur ^ 1);
            asm volatile("cp.async.wait_group 1;\n" ::: "memory");
        } else {
            asm volatile("cp.async.wait_group 0;\n" ::: "memory");
        }
        __syncthreads();

        const float* Ahc = &Ah[cur * GK * ASTR];
        const float* Alc = &Al[cur * GK * ASTR];
        const float* Bhc = &Bh[cur * 96 * BSTR];
        const float* Blc = &Bl[cur * 96 * BSTR];

#pragma unroll
        for (int kc = 0; kc < 2; kc++) {
            int kb = kc * 8;
            unsigned ah[4], al[4];
            ah[0] = __float_as_uint(Ahc[(kb + t) * ASTR + mrow + g]);
            ah[1] = __float_as_uint(Ahc[(kb + t) * ASTR + mrow + g + 8]);
            ah[2] = __float_as_uint(Ahc[(kb + t + 4) * ASTR + mrow + g]);
            ah[3] = __float_as_uint(Ahc[(kb + t + 4) * ASTR + mrow + g + 8]);
            al[0] = __float_as_uint(Alc[(kb + t) * ASTR + mrow + g]);
            al[1] = __float_as_uint(Alc[(kb + t) * ASTR + mrow + g + 8]);
            al[2] = __float_as_uint(Alc[(kb + t + 4) * ASTR + mrow + g]);
            al[3] = __float_as_uint(Alc[(kb + t + 4) * ASTR + mrow + g + 8]);
#pragma unroll
            for (int nt = 0; nt < 12; nt++) {
                const float* bph = &Bhc[(nt * 8 + g) * BSTR + kb];
                const float* bpl = &Blc[(nt * 8 + g) * BSTR + kb];
                unsigned bh0 = __float_as_uint(bph[t]);
                unsigned bh1 = __float_as_uint(bph[t + 4]);
                unsigned bl0 = __float_as_uint(bpl[t]);
                unsigned bl1 = __float_as_uint(bpl[t + 4]);
                mma_tf32(o[nt], ah, bh0, bh1);
                mma_tf32(o[nt], ah, bl0, bl1);
                mma_tf32(o[nt], al, bh0, bh1);
            }
        }
        __syncthreads();
    }

    // epilogue: j < 192 is Q (store raw); j >= 192 is K/V (round to tf32)
    bool doRound = (j0 >= 192);
    float* op = g_qkv[line] + (size_t)bb * NTOK * 576;
    int tok0 = n0 + mrow + g, tok1 = tok0 + 8;
#pragma unroll
    for (int nt = 0; nt < 12; nt++) {
        int j = j0 + nt * 8 + 2 * t;
        float v0 = o[nt][0], v1 = o[nt][1], v2 = o[nt][2], v3 = o[nt][3];
        if (doRound) {
            v0 = __uint_as_float(f2tf32(v0));
            v1 = __uint_as_float(f2tf32(v1));
            v2 = __uint_as_float(f2tf32(v2));
            v3 = __uint_as_float(f2tf32(v3));
        }
        *(float2*)&op[(size_t)tok0 * 576 + j] = make_float2(v0, v1);
        *(float2*)&op[(size_t)tok1 * 576 + j] = make_float2(v2, v3);
    }
}

// ---------------------------------------------------------------------------
// Kernel 3: CSWin attention (upper line) -- tensor-core flash (R10-passing)
// grid (7 qtiles, 16 = win*2+hh, 8 = bb*2+br), block 128, dyn smem 64 KB.
// ---------------------------------------------------------------------------
#define CSKT 56
#define CSSTRIDE 56
#define CSPSTRIDE 60
#define CSMMA_SMEM (4 * CSKT * CSSTRIDE * 4 + 4 * 16 * CSPSTRIDE * 4)   // 65536

__global__ void __launch_bounds__(128) cswin_mma_kernel(float* __restrict__ out) {
    extern __shared__ float csh[];
    float* Ksm[2] = { csh,                    csh + CSKT * CSSTRIDE };
    float* Vsm[2] = { csh + 2 * CSKT * CSSTRIDE, csh + 3 * CSKT * CSSTRIDE };
    unsigned* Pbase = (unsigned*)(csh + 4 * CSKT * CSSTRIDE);

    int qt = blockIdx.x;
    int win = blockIdx.y >> 1, hh = blockIdx.y & 1;
    int bb = blockIdx.z >> 1, br = blockIdx.z & 1;
    int choff = br * CSC + hh * 48;
    const float* qkv = g_qkv[0] + (size_t)bb * NTOK * 576;
    int tid = threadIdx.x;
    int warp = tid >> 5, lane = tid & 31;
    int g = lane >> 2, t = lane & 3;
    int row0 = qt * 64 + warp * 16;
    unsigned* P = Pbase + warp * 16 * CSPSTRIDE;

    auto tok2n = [&](int c) {
        int hl, wl;
        if (br) { hl = c / 56; wl = c - hl * 56; }
        else    { hl = c / 7;  wl = c - hl * 7;  }
        int h = br ? win * 7 + hl : hl;
        int w = br ? wl : win * 7 + wl;
        return h * RES + w;
    };

    unsigned qa[6][4];
    {
        const float qscale = CS_SCALE * LOG2E;
        int r0c = min(row0 + g, 391), r1c = min(row0 + g + 8, 391);
        const float* q0 = qkv + (size_t)tok2n(r0c) * 576 + choff;
        const float* q8 = qkv + (size_t)tok2n(r1c) * 576 + choff;
#pragma unroll
        for (int kc = 0; kc < 6; kc++) {
            qa[kc][0] = f2tf32(q0[kc * 8 + t] * qscale);
            qa[kc][1] = f2tf32(q8[kc * 8 + t] * qscale);
            qa[kc][2] = f2tf32(q0[kc * 8 + t + 4] * qscale);
            qa[kc][3] = f2tf32(q8[kc * 8 + t + 4] * qscale);
        }
    }

    float o[6][4];
#pragma unroll
    for (int nt = 0; nt < 6; nt++)
        o[nt][0] = o[nt][1] = o[nt][2] = o[nt][3] = 0.f;
    float m0 = -1e30f, m1 = -1e30f, l0 = 0.f, l1 = 0.f;

    auto load_tile = [&](int ti, int buf) {
        float* kd = Ksm[buf];
        float* vd = Vsm[buf];
        for (int i = tid; i < 56 * 12; i += 128) {
            int rr = i / 12, c4 = (i % 12) * 4;
            int n = tok2n(ti * CSKT + rr);
            const float* src = qkv + (size_t)n * 576 + choff + c4;
            cp_async16(kd + rr * CSSTRIDE + c4, src + 192);
            cp_async16(vd + rr * CSSTRIDE + c4, src + 384);
        }
        asm volatile("cp.async.commit_group;\n" ::: "memory");
    };

    load_tile(0, 0);

    for (int ti = 0; ti < 7; ti++) {
        int cur = ti & 1;
        if (ti < 6) {
            load_tile(ti + 1, cur ^ 1);
            asm volatile("cp.async.wait_group 1;\n" ::: "memory");
        } else {
            asm volatile("cp.async.wait_group 0;\n" ::: "memory");
        }
        __syncthreads();

        float s[7][4];
#pragma unroll
        for (int nt = 0; nt < 7; nt++) {
            s[nt][0] = s[nt][1] = s[nt][2] = s[nt][3] = 0.f;
            const float* kb = &Ksm[cur][(nt * 8 + g) * CSSTRIDE];
#pragma unroll
            for (int kc = 0; kc < 6; kc++) {
                unsigned b0 = __float_as_uint(kb[kc * 8 + t]);
                unsigned b1 = __float_as_uint(kb[kc * 8 + t + 4]);
                mma_tf32(s[nt], qa[kc], b0, b1);
            }
        }

        float rmax0 = s[0][0], rmax1 = s[0][2];
#pragma unroll
        for (int nt = 0; nt < 7; nt++) {
            rmax0 = fmaxf(rmax0, fmaxf(s[nt][0], s[nt][1]));
            rmax1 = fmaxf(rmax1, fmaxf(s[nt][2], s[nt][3]));
        }
        rmax0 = fmaxf(rmax0, __shfl_xor_sync(0xffffffffu, rmax0, 1));
        rmax0 = fmaxf(rmax0, __shfl_xor_sync(0xffffffffu, rmax0, 2));
        rmax1 = fmaxf(rmax1, __shfl_xor_sync(0xffffffffu, rmax1, 1));
        rmax1 = fmaxf(rmax1, __shfl_xor_sync(0xffffffffu, rmax1, 2));

        float mn0 = fmaxf(m0, rmax0), mn1 = fmaxf(m1, rmax1);
        float rs0 = exp2f(m0 - mn0),  rs1 = exp2f(m1 - mn1);
        l0 *= rs0; l1 *= rs1;

        float psum0 = 0.f, psum1 = 0.f;
#pragma unroll
        for (int nt = 0; nt < 7; nt++) {
            float p0 = exp2f(s[nt][0] - mn0);
            float p1 = exp2f(s[nt][1] - mn0);
            float p2 = exp2f(s[nt][2] - mn1);
            float p3 = exp2f(s[nt][3] - mn1);
            psum0 += p0 + p1; psum1 += p2 + p3;
            P[g * CSPSTRIDE + nt * 8 + 2 * t]           = f2tf32(p0);
            P[g * CSPSTRIDE + nt * 8 + 2 * t + 1]       = f2tf32(p1);
            P[(g + 8) * CSPSTRIDE + nt * 8 + 2 * t]     = f2tf32(p2);
            P[(g + 8) * CSPSTRIDE + nt * 8 + 2 * t + 1] = f2tf32(p3);
        }
        l0 += psum0; l1 += psum1;
#pragma unroll
        for (int nt = 0; nt < 6; nt++) {
            o[nt][0] *= rs0; o[nt][1] *= rs0;
            o[nt][2] *= rs1; o[nt][3] *= rs1;
        }
        m0 = mn0; m1 = mn1;
        __syncwarp();

#pragma unroll
        for (int kc = 0; kc < 7; kc++) {
            unsigned pa[4];
            pa[0] = P[g * CSPSTRIDE + kc * 8 + t];
            pa[1] = P[(g + 8) * CSPSTRIDE + kc * 8 + t];
            pa[2] = P[g * CSPSTRIDE + kc * 8 + t + 4];
            pa[3] = P[(g + 8) * CSPSTRIDE + kc * 8 + t + 4];
            const float* vb0 = &Vsm[cur][(kc * 8 + t) * CSSTRIDE];
            const float* vb1 = &Vsm[cur][(kc * 8 + t + 4) * CSSTRIDE];
#pragma unroll
            for (int nt = 0; nt < 6; nt++) {
                unsigned b0 = __float_as_uint(vb0[nt * 8 + g]);
                unsigned b1 = __float_as_uint(vb1[nt * 8 + g]);
                mma_tf32(o[nt], pa, b0, b1);
            }
        }
        __syncthreads();
    }

    l0 += __shfl_xor_sync(0xffffffffu, l0, 1);
    l0 += __shfl_xor_sync(0xffffffffu, l0, 2);
    l1 += __shfl_xor_sync(0xffffffffu, l1, 1);
    l1 += __shfl_xor_sync(0xffffffffu, l1, 2);
    float inv0 = 1.f / l0, inv1 = 1.f / l1;

    float* ob = out + ((size_t)bb * DIMC + choff) * NTOK;
    int tok0 = row0 + g, tok1 = row0 + g + 8;
    if (tok0 < 392) {
        int n = tok2n(tok0);
#pragma unroll
        for (int nt = 0; nt < 6; nt++) {
            int d0 = nt * 8 + 2 * t;
            ob[(size_t)d0 * NTOK + n]       = o[nt][0] * inv0;
            ob[(size_t)(d0 + 1) * NTOK + n] = o[nt][1] * inv0;
        }
    }
    if (tok1 < 392) {
        int n = tok2n(tok1);
#pragma unroll
        for (int nt = 0; nt < 6; nt++) {
            int d0 = nt * 8 + 2 * t;
            ob[(size_t)d0 * NTOK + n]       = o[nt][2] * inv1;
            ob[(size_t)(d0 + 1) * NTOK + n] = o[nt][3] * inv1;
        }
    }
}

// ---------------------------------------------------------------------------
// Kernel 3b: LePE (depthwise 3x3 on V) -- ADDS into out.  (R10-passing)
// ---------------------------------------------------------------------------
#define LEPE_SMEM (392 * 48 * 4)

__global__ void __launch_bounds__(256) lepe_kernel(const float* __restrict__ lw0,
                                                   const float* __restrict__ lb0,
                                                   const float* __restrict__ lw1,
                                                   const float* __restrict__ lb1,
                                                   float* __restrict__ out) {
    extern __shared__ float Vs[];   // [392][48]
    __shared__ float wsh[48][9];
    __shared__ float bsh[48];

    int win = blockIdx.x;
    int hh  = blockIdx.y;
    int bb  = blockIdx.z >> 1, br = blockIdx.z & 1;
    int SW = br ? 56 : 7;
    int SH = br ? 7 : 56;
    int choff = br * CSC + hh * 48;
    const float* qkv = g_qkv[0] + (size_t)bb * NTOK * 576;
    int tid = threadIdx.x;

    for (int e = tid; e < 392 * 12; e += 256) {
        int tk = e / 12, d4 = (e % 12) * 4;
        int hl, wl;
        if (br) { hl = tk / 56; wl = tk - hl * 56; }
        else    { hl = tk / 7;  wl = tk - hl * 7;  }
        int h = br ? win * 7 + hl : hl;
        int w = br ? wl : win * 7 + wl;
        int n = h * RES + w;
        *(float4*)&Vs[tk * 48 + d4] = *(const float4*)&qkv[(size_t)n * 576 + choff + 384 + d4];
    }
    const float* lw = br ? lw1 : lw0;
    const float* lb = br ? lb1 : lb0;
    for (int e = tid; e < 48 * 9; e += 256) {
        int d = e / 9, k = e % 9;
        wsh[d][k] = lw[(hh * 48 + d) * 9 + k];
    }
    if (tid < 48) bsh[tid] = lb[hh * 48 + tid];
    __syncthreads();

    for (int e = tid; e < 48 * 392; e += 256) {
        int d = e / 392, r = e - d * 392;
        int hl, wl;
        if (br) { hl = r / 56; wl = r - hl * 56; }
        else    { hl = r / 7;  wl = r - hl * 7;  }
        float lep = bsh[d];
#pragma unroll
        for (int dy = -1; dy <= 1; dy++) {
#pragma unroll
            for (int dx = -1; dx <= 1; dx++) {
                int h2 = hl + dy, w2 = wl + dx;
                if (h2 < 0 || h2 >= SH || w2 < 0 || w2 >= SW) continue;
                lep += Vs[(h2 * SW + w2) * 48 + d] * wsh[d][(dy + 1) * 3 + (dx + 1)];
            }
        }
        int h = br ? win * 7 + hl : hl;
        int w = br ? wl : win * 7 + wl;
        int n = h * RES + w;
        out[((size_t)bb * DIMC + choff + d) * NTOK + n] += lep;
    }
}

// ---------------------------------------------------------------------------
// Kernel 4: global attention (lower line) -- tensor-core flash (R9-passing)
// ---------------------------------------------------------------------------
#define KT 32
#define KSTRIDE 72
#define PSTRIDE 36

__global__ void __launch_bounds__(128) attn_dn_kernel(float* __restrict__ out) {
    __shared__ float    Ksm[2][KT * KSTRIDE];
    __shared__ float    Vsm[2][KT * KSTRIDE];
    __shared__ unsigned Psm[4][16 * PSTRIDE];

    int qt = blockIdx.x, hh = blockIdx.y, bb = blockIdx.z;
    const float* qkv = g_qkv[1] + (size_t)bb * NTOK * 576;
    int tid = threadIdx.x;
    int warp = tid >> 5, lane = tid & 31;
    int g = lane >> 2, t = lane & 3;
    int row0 = qt * 64 + warp * 16;

    unsigned qa[8][4];
    {
        const float qscale = DN_SCALE * LOG2E;
        const float* q0 = qkv + (size_t)(row0 + g) * 576 + hh * 64;
        const float* q8 = qkv + (size_t)(row0 + g + 8) * 576 + hh * 64;
#pragma unroll
        for (int kc = 0; kc < 8; kc++) {
            qa[kc][0] = f2tf32(q0[kc * 8 + t] * qscale);
            qa[kc][1] = f2tf32(q8[kc * 8 + t] * qscale);
            qa[kc][2] = f2tf32(q0[kc * 8 + t + 4] * qscale);
            qa[kc][3] = f2tf32(q8[kc * 8 + t + 4] * qscale);
        }
    }

    float o[8][4];
#pragma unroll
    for (int nt = 0; nt < 8; nt++)
        o[nt][0] = o[nt][1] = o[nt][2] = o[nt][3] = 0.f;
    float m0 = -1e30f, m1 = -1e30f, l0 = 0.f, l1 = 0.f;

    auto load_tile = [&](int kt, int buf) {
#pragma unroll
        for (int i = 0; i < 4; i++) {
            int task = tid * 4 + i;
            int rrow = task >> 4, chunk = task & 15;
            const float* src = qkv + (size_t)(kt * KT + rrow) * 576 + hh * 64 + chunk * 4;
            cp_async16(&Ksm[buf][rrow * KSTRIDE + chunk * 4], src + 192);
            cp_async16(&Vsm[buf][rrow * KSTRIDE + chunk * 4], src + 384);
        }
        asm volatile("cp.async.commit_group;\n" ::: "memory");
    };

    load_tile(0, 0);

    for (int kt = 0; kt < 98; kt++) {
        int cur = kt & 1;
        if (kt < 97) {
            load_tile(kt + 1, cur ^ 1);
            asm volatile("cp.async.wait_group 1;\n" ::: "memory");
        } else {
            asm volatile("cp.async.wait_group 0;\n" ::: "memory");
        }
        __syncthreads();

        float s[4][4];
#pragma unroll
        for (int nt = 0; nt < 4; nt++) {
            s[nt][0] = s[nt][1] = s[nt][2] = s[nt][3] = 0.f;
            const float* kb = &Ksm[cur][(nt * 8 + g) * KSTRIDE];
#pragma unroll
            for (int kc = 0; kc < 8; kc++) {
                unsigned b0 = __float_as_uint(kb[kc * 8 + t]);
                unsigned b1 = __float_as_uint(kb[kc * 8 + t + 4]);
                mma_tf32(s[nt], qa[kc], b0, b1);
            }
        }

        float rmax0 = fmaxf(fmaxf(s[0][0], s[0][1]), fmaxf(s[1][0], s[1][1]));
        rmax0 = fmaxf(rmax0, fmaxf(fmaxf(s[2][0], s[2][1]), fmaxf(s[3][0], s[3][1])));
        float rmax1 = fmaxf(fmaxf(s[0][2], s[0][3]), fmaxf(s[1][2], s[1][3]));
        rmax1 = fmaxf(rmax1, fmaxf(fmaxf(s[2][2], s[2][3]), fmaxf(s[3][2], s[3][3])));
        rmax0 = fmaxf(rmax0, __shfl_xor_sync(0xffffffffu, rmax0, 1));
        rmax0 = fmaxf(rmax0, __shfl_xor_sync(0xffffffffu, rmax0, 2));
        rmax1 = fmaxf(rmax1, __shfl_xor_sync(0xffffffffu, rmax1, 1));
        rmax1 = fmaxf(rmax1, __shfl_xor_sync(0xffffffffu, rmax1, 2));

        float mn0 = fmaxf(m0, rmax0), mn1 = fmaxf(m1, rmax1);
        float rs0 = exp2f(m0 - mn0),  rs1 = exp2f(m1 - mn1);
        l0 *= rs0; l1 *= rs1;

        unsigned* P = Psm[warp];
        float psum0 = 0.f, psum1 = 0.f;
#pragma unroll
        for (int nt = 0; nt < 4; nt++) {
            float p0 = exp2f(s[nt][0] - mn0);
            float p1 = exp2f(s[nt][1] - mn0);
            float p2 = exp2f(s[nt][2] - mn1);
            float p3 = exp2f(s[nt][3] - mn1);
            psum0 += p0 + p1; psum1 += p2 + p3;
            P[g * PSTRIDE + nt * 8 + 2 * t]           = f2tf32(p0);
            P[g * PSTRIDE + nt * 8 + 2 * t + 1]       = f2tf32(p1);
            P[(g + 8) * PSTRIDE + nt * 8 + 2 * t]     = f2tf32(p2);
            P[(g + 8) * PSTRIDE + nt * 8 + 2 * t + 1] = f2tf32(p3);
        }
        l0 += psum0; l1 += psum1;
#pragma unroll
        for (int nt = 0; nt < 8; nt++) {
            o[nt][0] *= rs0; o[nt][1] *= rs0;
            o[nt][2] *= rs1; o[nt][3] *= rs1;
        }
        m0 = mn0; m1 = mn1;
        __syncwarp();

#pragma unroll
        for (int kc = 0; kc < 4; kc++) {
            unsigned pa[4];
            pa[0] = P[g * PSTRIDE + kc * 8 + t];
            pa[1] = P[(g + 8) * PSTRIDE + kc * 8 + t];
            pa[2] = P[g * PSTRIDE + kc * 8 + t + 4];
            pa[3] = P[(g + 8) * PSTRIDE + kc * 8 + t + 4];
            const float* vb0 = &Vsm[cur][(kc * 8 + t) * KSTRIDE];
            const float* vb1 = &Vsm[cur][(kc * 8 + t + 4) * KSTRIDE];
#pragma unroll
            for (int nt = 0; nt < 8; nt++) {
                unsigned b0 = __float_as_uint(vb0[nt * 8 + g]);
                unsigned b1 = __float_as_uint(vb1[nt * 8 + g]);
                mma_tf32(o[nt], pa, b0, b1);
            }
        }
        __syncthreads();
    }

    l0 += __shfl_xor_sync(0xffffffffu, l0, 1);
    l0 += __shfl_xor_sync(0xffffffffu, l0, 2);
    l1 += __shfl_xor_sync(0xffffffffu, l1, 1);
    l1 += __shfl_xor_sync(0xffffffffu, l1, 2);
    float inv0 = 1.f / l0, inv1 = 1.f / l1;

    float* ob = out + ((size_t)bb * DIMC + TD + hh * 64) * NTOK;
    int tok0 = row0 + g, tok1 = row0 + g + 8;
#pragma unroll
    for (int nt = 0; nt < 8; nt++) {
        int d0 = nt * 8 + 2 * t;
        ob[(size_t)d0 * NTOK + tok0]       = o[nt][0] * inv0;
        ob[(size_t)(d0 + 1) * NTOK + tok0] = o[nt][1] * inv0;
        ob[(size_t)d0 * NTOK + tok1]       = o[nt][2] * inv1;
        ob[(size_t)(d0 + 1) * NTOK + tok1] = o[nt][3] * inv1;
    }
}

// ---------------------------------------------------------------------------
// Launch
// ---------------------------------------------------------------------------
extern "C" void kernel_launch(void* const* d_in, const int* in_sizes, int n_in,
                              void* d_out, int out_size) {
    const float* xa      = (const float*)d_in[0];
    const float* proj1_w = (const float*)d_in[1];
    const float* proj2_w = (const float*)d_in[2];
    const float* qkv_u_w = (const float*)d_in[3];
    const float* qkv_d_w = (const float*)d_in[4];
    const float* lepe_w0 = (const float*)d_in[5];
    const float* lepe_b0 = (const float*)d_in[6];
    const float* lepe_w1 = (const float*)d_in[7];
    const float* lepe_b1 = (const float*)d_in[8];
    float* out = (float*)d_out;

    // 1) combined weights (Wqkv @ Wproj), tf32 hi/lo
    combine_w_kernel<<<dim3(576, 2), 384>>>(proj1_w, proj2_w, qkv_u_w, qkv_d_w);

    // 1b) split xa into tf32 hi/lo
    split_xa_kernel<<<(NB * DIMC * NTOK / 4 + 255) / 256, 256>>>(xa);

    // 2) fused proj+qkv GEMM, tensor cores, 3xTF32, occupancy-shaped
    //    (128 thr / 4 CTAs per SM), K/V tf32 rounding fused into epilogue
    cudaFuncSetAttribute(qkv_mma_kernel, cudaFuncAttributeMaxDynamicSharedMemorySize, QKV_SMEM);
    qkv_mma_kernel<<<dim3(49, 6, 8), 128, QKV_SMEM>>>();

    // 3) CSWin upper line, tensor cores (writes channels [0,192))
    cudaFuncSetAttribute(cswin_mma_kernel, cudaFuncAttributeMaxDynamicSharedMemorySize, CSMMA_SMEM);
    cswin_mma_kernel<<<dim3(7, 16, 8), 128, CSMMA_SMEM>>>(out);

    // 3b) LePE adds into channels [0,192)
    cudaFuncSetAttribute(lepe_kernel, cudaFuncAttributeMaxDynamicSharedMemorySize, LEPE_SMEM);
    lepe_kernel<<<dim3(8, 2, 8), 256, LEPE_SMEM>>>(lepe_w0, lepe_b0, lepe_w1, lepe_b1, out);

    // 4) global attention lower line, tensor cores (channels [192,384))
    attn_dn_kernel<<<dim3(49, 3, 4), 128>>>(out);
}

// round 15
// speedup vs baseline: 6.6912x; 1.0342x over previous
#include <cuda_runtime.h>
#include <math.h>

// Problem constants
#define NB    4
#define DIMC  384
#define RES   56
#define NTOK  3136          // 56*56
#define TD    192
#define CSC   96

#define LOG2E 1.4426950408889634f
#define CS_SCALE 0.14433756729740643f   // 1/sqrt(48)
#define DN_SCALE 0.125f                 // 1/sqrt(64)

// ---------------------------------------------------------------------------
// Scratch (static device arrays; no allocation anywhere)
// ---------------------------------------------------------------------------
__device__ float g_wchi[2][576 * 384];               // combined weights, tf32 hi
__device__ float g_wclo[2][576 * 384];               // combined weights, tf32 lo
__device__ float g_xhi[NB * DIMC * NTOK];            // xa tf32 hi  [b][c][n]
__device__ float g_xlo[NB * DIMC * NTOK];            // xa tf32 lo
__device__ float g_qkv[2][NB * NTOK * 576];          // [line][((b*3136)+n)*576 + j]

// ---------------------------------------------------------------------------
// Shared helpers
// ---------------------------------------------------------------------------
__device__ __forceinline__ unsigned f2tf32(float f) {
    unsigned u;
    asm("cvt.rna.tf32.f32 %0, %1;" : "=r"(u) : "f"(f));
    return u;
}

__device__ __forceinline__ void cp_async16(void* smem_dst, const void* gsrc) {
    unsigned s = (unsigned)__cvta_generic_to_shared(smem_dst);
    asm volatile("cp.async.cg.shared.global [%0], [%1], 16;\n" :: "r"(s), "l"(gsrc));
}

__device__ __forceinline__ void mma_tf32(float* c, const unsigned* a, unsigned b0, unsigned b1) {
    asm volatile(
        "mma.sync.aligned.m16n8k8.row.col.f32.tf32.tf32.f32 "
        "{%0,%1,%2,%3}, {%4,%5,%6,%7}, {%8,%9}, {%0,%1,%2,%3};"
        : "+f"(c[0]), "+f"(c[1]), "+f"(c[2]), "+f"(c[3])
        : "r"(a[0]), "r"(a[1]), "r"(a[2]), "r"(a[3]), "r"(b0), "r"(b1));
}

// ---------------------------------------------------------------------------
// Kernel 1: combined weights (tf32 hi/lo).  grid (576, 2), block 384
// ---------------------------------------------------------------------------
__global__ void combine_w_kernel(const float* __restrict__ p1,
                                 const float* __restrict__ p2,
                                 const float* __restrict__ qu,
                                 const float* __restrict__ qd) {
    int j = blockIdx.x;
    int line = blockIdx.y;
    int c = threadIdx.x;
    const float* qw = line ? qd : qu;
    const float* pw = line ? p2 : p1;
    const float* qrow = qw + j * 192;
    float s = 0.f;
#pragma unroll 8
    for (int t = 0; t < 192; t++)
        s += qrow[t] * pw[t * 384 + c];
    float hi = __uint_as_float(f2tf32(s));
    float lo = __uint_as_float(f2tf32(s - hi));
    g_wchi[line][j * 384 + c] = hi;
    g_wclo[line][j * 384 + c] = lo;
}

// ---------------------------------------------------------------------------
// Kernel 1b: split xa into tf32 (hi, lo).
// ---------------------------------------------------------------------------
__global__ void __launch_bounds__(256) split_xa_kernel(const float* __restrict__ xa) {
    int idx = blockIdx.x * 256 + threadIdx.x;
    if (idx >= NB * DIMC * NTOK / 4) return;
    float4 v = ((const float4*)xa)[idx];
    float4 h, l;
    h.x = __uint_as_float(f2tf32(v.x)); l.x = __uint_as_float(f2tf32(v.x - h.x));
    h.y = __uint_as_float(f2tf32(v.y)); l.y = __uint_as_float(f2tf32(v.y - h.y));
    h.z = __uint_as_float(f2tf32(v.z)); l.z = __uint_as_float(f2tf32(v.z - h.z));
    h.w = __uint_as_float(f2tf32(v.w)); l.w = __uint_as_float(f2tf32(v.w - h.w));
    ((float4*)g_xhi)[idx] = h;
    ((float4*)g_xlo)[idx] = l;
}

// ---------------------------------------------------------------------------
// Kernel 2: qkv GEMM, tensor cores, 3xTF32 (R14-passing math, + line param).
// 128 threads / 4 warps, CTA tile 64 tokens x 96 j. K chunks of 16, cp.async
// double buffered. K/V tf32 rounding fused into epilogue.
// grid (49, 6, 4=bb), block 128, dyn smem 49152 B.
// ---------------------------------------------------------------------------
#define GK    16
#define ASTR  72
#define BSTR  20
#define QKV_SMEM ((2 * GK * ASTR * 2 + 2 * 96 * BSTR * 2) * 4)   // 49152

__global__ void __launch_bounds__(128, 4) qkv_mma_kernel(int line) {
    extern __shared__ float qsh[];
    float* Ah = qsh;                          // [2][16*72]
    float* Al = Ah + 2 * GK * ASTR;
    float* Bh = Al + 2 * GK * ASTR;           // [2][96*20]
    float* Bl = Bh + 2 * 96 * BSTR;

    int bb = blockIdx.z;
    int n0 = blockIdx.x * 64;
    int j0 = blockIdx.y * 96;
    const float* Xh = g_xhi + (size_t)bb * DIMC * NTOK;
    const float* Xl = g_xlo + (size_t)bb * DIMC * NTOK;
    const float* Wh = g_wchi[line];
    const float* Wl = g_wclo[line];

    int tid = threadIdx.x;
    int warp = tid >> 5, lane = tid & 31;
    int g = lane >> 2, t = lane & 3;
    int mrow = warp * 16;

    float o[12][4];
#pragma unroll
    for (int nt = 0; nt < 12; nt++)
        o[nt][0] = o[nt][1] = o[nt][2] = o[nt][3] = 0.f;

    auto load_chunk = [&](int ch, int buf) {
        int c0 = ch * GK;
#pragma unroll
        for (int i = 0; i < 2; i++) {
            int task = tid + i * 128;
            int kr = task >> 4, c4 = (task & 15) * 4;
            cp_async16(&Ah[(buf * GK + kr) * ASTR + c4], &Xh[(size_t)(c0 + kr) * NTOK + n0 + c4]);
            cp_async16(&Al[(buf * GK + kr) * ASTR + c4], &Xl[(size_t)(c0 + kr) * NTOK + n0 + c4]);
        }
#pragma unroll
        for (int i = 0; i < 3; i++) {
            int task = tid + i * 128;
            int jr = task >> 2, c4 = (task & 3) * 4;
            cp_async16(&Bh[(buf * 96 + jr) * BSTR + c4], &Wh[(j0 + jr) * 384 + c0 + c4]);
            cp_async16(&Bl[(buf * 96 + jr) * BSTR + c4], &Wl[(j0 + jr) * 384 + c0 + c4]);
        }
        asm volatile("cp.async.commit_group;\n" ::: "memory");
    };

    load_chunk(0, 0);

    for (int ch = 0; ch < 24; ch++) {
        int cur = ch & 1;
        if (ch < 23) {
            load_chunk(ch + 1, cur ^ 1);
            asm volatile("cp.async.wait_group 1;\n" ::: "memory");
        } else {
            asm volatile("cp.async.wait_group 0;\n" ::: "memory");
        }
        __syncthreads();

        const float* Ahc = &Ah[cur * GK * ASTR];
        const float* Alc = &Al[cur * GK * ASTR];
        const float* Bhc = &Bh[cur * 96 * BSTR];
        const float* Blc = &Bl[cur * 96 * BSTR];

#pragma unroll
        for (int kc = 0; kc < 2; kc++) {
            int kb = kc * 8;
            unsigned ah[4], al[4];
            ah[0] = __float_as_uint(Ahc[(kb + t) * ASTR + mrow + g]);
            ah[1] = __float_as_uint(Ahc[(kb + t) * ASTR + mrow + g + 8]);
            ah[2] = __float_as_uint(Ahc[(kb + t + 4) * ASTR + mrow + g]);
            ah[3] = __float_as_uint(Ahc[(kb + t + 4) * ASTR + mrow + g + 8]);
            al[0] = __float_as_uint(Alc[(kb + t) * ASTR + mrow + g]);
            al[1] = __float_as_uint(Alc[(kb + t) * ASTR + mrow + g + 8]);
            al[2] = __float_as_uint(Alc[(kb + t + 4) * ASTR + mrow + g]);
            al[3] = __float_as_uint(Alc[(kb + t + 4) * ASTR + mrow + g + 8]);
#pragma unroll
            for (int nt = 0; nt < 12; nt++) {
                const float* bph = &Bhc[(nt * 8 + g) * BSTR + kb];
                const float* bpl = &Blc[(nt * 8 + g) * BSTR + kb];
                unsigned bh0 = __float_as_uint(bph[t]);
                unsigned bh1 = __float_as_uint(bph[t + 4]);
                unsigned bl0 = __float_as_uint(bpl[t]);
                unsigned bl1 = __float_as_uint(bpl[t + 4]);
                mma_tf32(o[nt], ah, bh0, bh1);
                mma_tf32(o[nt], ah, bl0, bl1);
                mma_tf32(o[nt], al, bh0, bh1);
            }
        }
        __syncthreads();
    }

    bool doRound = (j0 >= 192);
    float* op = g_qkv[line] + (size_t)bb * NTOK * 576;
    int tok0 = n0 + mrow + g, tok1 = tok0 + 8;
#pragma unroll
    for (int nt = 0; nt < 12; nt++) {
        int j = j0 + nt * 8 + 2 * t;
        float v0 = o[nt][0], v1 = o[nt][1], v2 = o[nt][2], v3 = o[nt][3];
        if (doRound) {
            v0 = __uint_as_float(f2tf32(v0));
            v1 = __uint_as_float(f2tf32(v1));
            v2 = __uint_as_float(f2tf32(v2));
            v3 = __uint_as_float(f2tf32(v3));
        }
        *(float2*)&op[(size_t)tok0 * 576 + j] = make_float2(v0, v1);
        *(float2*)&op[(size_t)tok1 * 576 + j] = make_float2(v2, v3);
    }
}

// ---------------------------------------------------------------------------
// Kernel 3: CSWin attention (upper line) -- tensor-core flash (R10-passing)
// ---------------------------------------------------------------------------
#define CSKT 56
#define CSSTRIDE 56
#define CSPSTRIDE 60
#define CSMMA_SMEM (4 * CSKT * CSSTRIDE * 4 + 4 * 16 * CSPSTRIDE * 4)   // 65536

__global__ void __launch_bounds__(128) cswin_mma_kernel(float* __restrict__ out) {
    extern __shared__ float csh[];
    float* Ksm[2] = { csh,                    csh + CSKT * CSSTRIDE };
    float* Vsm[2] = { csh + 2 * CSKT * CSSTRIDE, csh + 3 * CSKT * CSSTRIDE };
    unsigned* Pbase = (unsigned*)(csh + 4 * CSKT * CSSTRIDE);

    int qt = blockIdx.x;
    int win = blockIdx.y >> 1, hh = blockIdx.y & 1;
    int bb = blockIdx.z >> 1, br = blockIdx.z & 1;
    int choff = br * CSC + hh * 48;
    const float* qkv = g_qkv[0] + (size_t)bb * NTOK * 576;
    int tid = threadIdx.x;
    int warp = tid >> 5, lane = tid & 31;
    int g = lane >> 2, t = lane & 3;
    int row0 = qt * 64 + warp * 16;
    unsigned* P = Pbase + warp * 16 * CSPSTRIDE;

    auto tok2n = [&](int c) {
        int hl, wl;
        if (br) { hl = c / 56; wl = c - hl * 56; }
        else    { hl = c / 7;  wl = c - hl * 7;  }
        int h = br ? win * 7 + hl : hl;
        int w = br ? wl : win * 7 + wl;
        return h * RES + w;
    };

    unsigned qa[6][4];
    {
        const float qscale = CS_SCALE * LOG2E;
        int r0c = min(row0 + g, 391), r1c = min(row0 + g + 8, 391);
        const float* q0 = qkv + (size_t)tok2n(r0c) * 576 + choff;
        const float* q8 = qkv + (size_t)tok2n(r1c) * 576 + choff;
#pragma unroll
        for (int kc = 0; kc < 6; kc++) {
            qa[kc][0] = f2tf32(q0[kc * 8 + t] * qscale);
            qa[kc][1] = f2tf32(q8[kc * 8 + t] * qscale);
            qa[kc][2] = f2tf32(q0[kc * 8 + t + 4] * qscale);
            qa[kc][3] = f2tf32(q8[kc * 8 + t + 4] * qscale);
        }
    }

    float o[6][4];
#pragma unroll
    for (int nt = 0; nt < 6; nt++)
        o[nt][0] = o[nt][1] = o[nt][2] = o[nt][3] = 0.f;
    float m0 = -1e30f, m1 = -1e30f, l0 = 0.f, l1 = 0.f;

    auto load_tile = [&](int ti, int buf) {
        float* kd = Ksm[buf];
        float* vd = Vsm[buf];
        for (int i = tid; i < 56 * 12; i += 128) {
            int rr = i / 12, c4 = (i % 12) * 4;
            int n = tok2n(ti * CSKT + rr);
            const float* src = qkv + (size_t)n * 576 + choff + c4;
            cp_async16(kd + rr * CSSTRIDE + c4, src + 192);
            cp_async16(vd + rr * CSSTRIDE + c4, src + 384);
        }
        asm volatile("cp.async.commit_group;\n" ::: "memory");
    };

    load_tile(0, 0);

    for (int ti = 0; ti < 7; ti++) {
        int cur = ti & 1;
        if (ti < 6) {
            load_tile(ti + 1, cur ^ 1);
            asm volatile("cp.async.wait_group 1;\n" ::: "memory");
        } else {
            asm volatile("cp.async.wait_group 0;\n" ::: "memory");
        }
        __syncthreads();

        float s[7][4];
#pragma unroll
        for (int nt = 0; nt < 7; nt++) {
            s[nt][0] = s[nt][1] = s[nt][2] = s[nt][3] = 0.f;
            const float* kb = &Ksm[cur][(nt * 8 + g) * CSSTRIDE];
#pragma unroll
            for (int kc = 0; kc < 6; kc++) {
                unsigned b0 = __float_as_uint(kb[kc * 8 + t]);
                unsigned b1 = __float_as_uint(kb[kc * 8 + t + 4]);
                mma_tf32(s[nt], qa[kc], b0, b1);
            }
        }

        float rmax0 = s[0][0], rmax1 = s[0][2];
#pragma unroll
        for (int nt = 0; nt < 7; nt++) {
            rmax0 = fmaxf(rmax0, fmaxf(s[nt][0], s[nt][1]));
            rmax1 = fmaxf(rmax1, fmaxf(s[nt][2], s[nt][3]));
        }
        rmax0 = fmaxf(rmax0, __shfl_xor_sync(0xffffffffu, rmax0, 1));
        rmax0 = fmaxf(rmax0, __shfl_xor_sync(0xffffffffu, rmax0, 2));
        rmax1 = fmaxf(rmax1, __shfl_xor_sync(0xffffffffu, rmax1, 1));
        rmax1 = fmaxf(rmax1, __shfl_xor_sync(0xffffffffu, rmax1, 2));

        float mn0 = fmaxf(m0, rmax0), mn1 = fmaxf(m1, rmax1);
        float rs0 = exp2f(m0 - mn0),  rs1 = exp2f(m1 - mn1);
        l0 *= rs0; l1 *= rs1;

        float psum0 = 0.f, psum1 = 0.f;
#pragma unroll
        for (int nt = 0; nt < 7; nt++) {
            float p0 = exp2f(s[nt][0] - mn0);
            float p1 = exp2f(s[nt][1] - mn0);
            float p2 = exp2f(s[nt][2] - mn1);
            float p3 = exp2f(s[nt][3] - mn1);
            psum0 += p0 + p1; psum1 += p2 + p3;
            P[g * CSPSTRIDE + nt * 8 + 2 * t]           = f2tf32(p0);
            P[g * CSPSTRIDE + nt * 8 + 2 * t + 1]       = f2tf32(p1);
            P[(g + 8) * CSPSTRIDE + nt * 8 + 2 * t]     = f2tf32(p2);
            P[(g + 8) * CSPSTRIDE + nt * 8 + 2 * t + 1] = f2tf32(p3);
        }
        l0 += psum0; l1 += psum1;
#pragma unroll
        for (int nt = 0; nt < 6; nt++) {
            o[nt][0] *= rs0; o[nt][1] *= rs0;
            o[nt][2] *= rs1; o[nt][3] *= rs1;
        }
        m0 = mn0; m1 = mn1;
        __syncwarp();

#pragma unroll
        for (int kc = 0; kc < 7; kc++) {
            unsigned pa[4];
            pa[0] = P[g * CSPSTRIDE + kc * 8 + t];
            pa[1] = P[(g + 8) * CSPSTRIDE + kc * 8 + t];
            pa[2] = P[g * CSPSTRIDE + kc * 8 + t + 4];
            pa[3] = P[(g + 8) * CSPSTRIDE + kc * 8 + t + 4];
            const float* vb0 = &Vsm[cur][(kc * 8 + t) * CSSTRIDE];
            const float* vb1 = &Vsm[cur][(kc * 8 + t + 4) * CSSTRIDE];
#pragma unroll
            for (int nt = 0; nt < 6; nt++) {
                unsigned b0 = __float_as_uint(vb0[nt * 8 + g]);
                unsigned b1 = __float_as_uint(vb1[nt * 8 + g]);
                mma_tf32(o[nt], pa, b0, b1);
            }
        }
        __syncthreads();
    }

    l0 += __shfl_xor_sync(0xffffffffu, l0, 1);
    l0 += __shfl_xor_sync(0xffffffffu, l0, 2);
    l1 += __shfl_xor_sync(0xffffffffu, l1, 1);
    l1 += __shfl_xor_sync(0xffffffffu, l1, 2);
    float inv0 = 1.f / l0, inv1 = 1.f / l1;

    float* ob = out + ((size_t)bb * DIMC + choff) * NTOK;
    int tok0 = row0 + g, tok1 = row0 + g + 8;
    if (tok0 < 392) {
        int n = tok2n(tok0);
#pragma unroll
        for (int nt = 0; nt < 6; nt++) {
            int d0 = nt * 8 + 2 * t;
            ob[(size_t)d0 * NTOK + n]       = o[nt][0] * inv0;
            ob[(size_t)(d0 + 1) * NTOK + n] = o[nt][1] * inv0;
        }
    }
    if (tok1 < 392) {
        int n = tok2n(tok1);
#pragma unroll
        for (int nt = 0; nt < 6; nt++) {
            int d0 = nt * 8 + 2 * t;
            ob[(size_t)d0 * NTOK + n]       = o[nt][2] * inv1;
            ob[(size_t)(d0 + 1) * NTOK + n] = o[nt][3] * inv1;
        }
    }
}

// ---------------------------------------------------------------------------
// Kernel 3b: LePE (depthwise 3x3 on V) -- ADDS into out.  (R10-passing)
// ---------------------------------------------------------------------------
#define LEPE_SMEM (392 * 48 * 4)

__global__ void __launch_bounds__(256) lepe_kernel(const float* __restrict__ lw0,
                                                   const float* __restrict__ lb0,
                                                   const float* __restrict__ lw1,
                                                   const float* __restrict__ lb1,
                                                   float* __restrict__ out) {
    extern __shared__ float Vs[];   // [392][48]
    __shared__ float wsh[48][9];
    __shared__ float bsh[48];

    int win = blockIdx.x;
    int hh  = blockIdx.y;
    int bb  = blockIdx.z >> 1, br = blockIdx.z & 1;
    int SW = br ? 56 : 7;
    int SH = br ? 7 : 56;
    int choff = br * CSC + hh * 48;
    const float* qkv = g_qkv[0] + (size_t)bb * NTOK * 576;
    int tid = threadIdx.x;

    for (int e = tid; e < 392 * 12; e += 256) {
        int tk = e / 12, d4 = (e % 12) * 4;
        int hl, wl;
        if (br) { hl = tk / 56; wl = tk - hl * 56; }
        else    { hl = tk / 7;  wl = tk - hl * 7;  }
        int h = br ? win * 7 + hl : hl;
        int w = br ? wl : win * 7 + wl;
        int n = h * RES + w;
        *(float4*)&Vs[tk * 48 + d4] = *(const float4*)&qkv[(size_t)n * 576 + choff + 384 + d4];
    }
    const float* lw = br ? lw1 : lw0;
    const float* lb = br ? lb1 : lb0;
    for (int e = tid; e < 48 * 9; e += 256) {
        int d = e / 9, k = e % 9;
        wsh[d][k] = lw[(hh * 48 + d) * 9 + k];
    }
    if (tid < 48) bsh[tid] = lb[hh * 48 + tid];
    __syncthreads();

    for (int e = tid; e < 48 * 392; e += 256) {
        int d = e / 392, r = e - d * 392;
        int hl, wl;
        if (br) { hl = r / 56; wl = r - hl * 56; }
        else    { hl = r / 7;  wl = r - hl * 7;  }
        float lep = bsh[d];
#pragma unroll
        for (int dy = -1; dy <= 1; dy++) {
#pragma unroll
            for (int dx = -1; dx <= 1; dx++) {
                int h2 = hl + dy, w2 = wl + dx;
                if (h2 < 0 || h2 >= SH || w2 < 0 || w2 >= SW) continue;
                lep += Vs[(h2 * SW + w2) * 48 + d] * wsh[d][(dy + 1) * 3 + (dx + 1)];
            }
        }
        int h = br ? win * 7 + hl : hl;
        int w = br ? wl : win * 7 + wl;
        int n = h * RES + w;
        out[((size_t)bb * DIMC + choff + d) * NTOK + n] += lep;
    }
}

// ---------------------------------------------------------------------------
// Kernel 4: global attention (lower line) -- tensor-core flash (R9-passing)
// ---------------------------------------------------------------------------
#define KT 32
#define KSTRIDE 72
#define PSTRIDE 36

__global__ void __launch_bounds__(128) attn_dn_kernel(float* __restrict__ out) {
    __shared__ float    Ksm[2][KT * KSTRIDE];
    __shared__ float    Vsm[2][KT * KSTRIDE];
    __shared__ unsigned Psm[4][16 * PSTRIDE];

    int qt = blockIdx.x, hh = blockIdx.y, bb = blockIdx.z;
    const float* qkv = g_qkv[1] + (size_t)bb * NTOK * 576;
    int tid = threadIdx.x;
    int warp = tid >> 5, lane = tid & 31;
    int g = lane >> 2, t = lane & 3;
    int row0 = qt * 64 + warp * 16;

    unsigned qa[8][4];
    {
        const float qscale = DN_SCALE * LOG2E;
        const float* q0 = qkv + (size_t)(row0 + g) * 576 + hh * 64;
        const float* q8 = qkv + (size_t)(row0 + g + 8) * 576 + hh * 64;
#pragma unroll
        for (int kc = 0; kc < 8; kc++) {
            qa[kc][0] = f2tf32(q0[kc * 8 + t] * qscale);
            qa[kc][1] = f2tf32(q8[kc * 8 + t] * qscale);
            qa[kc][2] = f2tf32(q0[kc * 8 + t + 4] * qscale);
            qa[kc][3] = f2tf32(q8[kc * 8 + t + 4] * qscale);
        }
    }

    float o[8][4];
#pragma unroll
    for (int nt = 0; nt < 8; nt++)
        o[nt][0] = o[nt][1] = o[nt][2] = o[nt][3] = 0.f;
    float m0 = -1e30f, m1 = -1e30f, l0 = 0.f, l1 = 0.f;

    auto load_tile = [&](int kt, int buf) {
#pragma unroll
        for (int i = 0; i < 4; i++) {
            int task = tid * 4 + i;
            int rrow = task >> 4, chunk = task & 15;
            const float* src = qkv + (size_t)(kt * KT + rrow) * 576 + hh * 64 + chunk * 4;
            cp_async16(&Ksm[buf][rrow * KSTRIDE + chunk * 4], src + 192);
            cp_async16(&Vsm[buf][rrow * KSTRIDE + chunk * 4], src + 384);
        }
        asm volatile("cp.async.commit_group;\n" ::: "memory");
    };

    load_tile(0, 0);

    for (int kt = 0; kt < 98; kt++) {
        int cur = kt & 1;
        if (kt < 97) {
            load_tile(kt + 1, cur ^ 1);
            asm volatile("cp.async.wait_group 1;\n" ::: "memory");
        } else {
            asm volatile("cp.async.wait_group 0;\n" ::: "memory");
        }
        __syncthreads();

        float s[4][4];
#pragma unroll
        for (int nt = 0; nt < 4; nt++) {
            s[nt][0] = s[nt][1] = s[nt][2] = s[nt][3] = 0.f;
            const float* kb = &Ksm[cur][(nt * 8 + g) * KSTRIDE];
#pragma unroll
            for (int kc = 0; kc < 8; kc++) {
                unsigned b0 = __float_as_uint(kb[kc * 8 + t]);
                unsigned b1 = __float_as_uint(kb[kc * 8 + t + 4]);
                mma_tf32(s[nt], qa[kc], b0, b1);
            }
        }

        float rmax0 = fmaxf(fmaxf(s[0][0], s[0][1]), fmaxf(s[1][0], s[1][1]));
        rmax0 = fmaxf(rmax0, fmaxf(fmaxf(s[2][0], s[2][1]), fmaxf(s[3][0], s[3][1])));
        float rmax1 = fmaxf(fmaxf(s[0][2], s[0][3]), fmaxf(s[1][2], s[1][3]));
        rmax1 = fmaxf(rmax1, fmaxf(fmaxf(s[2][2], s[2][3]), fmaxf(s[3][2], s[3][3])));
        rmax0 = fmaxf(rmax0, __shfl_xor_sync(0xffffffffu, rmax0, 1));
        rmax0 = fmaxf(rmax0, __shfl_xor_sync(0xffffffffu, rmax0, 2));
        rmax1 = fmaxf(rmax1, __shfl_xor_sync(0xffffffffu, rmax1, 1));
        rmax1 = fmaxf(rmax1, __shfl_xor_sync(0xffffffffu, rmax1, 2));

        float mn0 = fmaxf(m0, rmax0), mn1 = fmaxf(m1, rmax1);
        float rs0 = exp2f(m0 - mn0),  rs1 = exp2f(m1 - mn1);
        l0 *= rs0; l1 *= rs1;

        unsigned* P = Psm[warp];
        float psum0 = 0.f, psum1 = 0.f;
#pragma unroll
        for (int nt = 0; nt < 4; nt++) {
            float p0 = exp2f(s[nt][0] - mn0);
            float p1 = exp2f(s[nt][1] - mn0);
            float p2 = exp2f(s[nt][2] - mn1);
            float p3 = exp2f(s[nt][3] - mn1);
            psum0 += p0 + p1; psum1 += p2 + p3;
            P[g * PSTRIDE + nt * 8 + 2 * t]           = f2tf32(p0);
            P[g * PSTRIDE + nt * 8 + 2 * t + 1]       = f2tf32(p1);
            P[(g + 8) * PSTRIDE + nt * 8 + 2 * t]     = f2tf32(p2);
            P[(g + 8) * PSTRIDE + nt * 8 + 2 * t + 1] = f2tf32(p3);
        }
        l0 += psum0; l1 += psum1;
#pragma unroll
        for (int nt = 0; nt < 8; nt++) {
            o[nt][0] *= rs0; o[nt][1] *= rs0;
            o[nt][2] *= rs1; o[nt][3] *= rs1;
        }
        m0 = mn0; m1 = mn1;
        __syncwarp();

#pragma unroll
        for (int kc = 0; kc < 4; kc++) {
            unsigned pa[4];
            pa[0] = P[g * PSTRIDE + kc * 8 + t];
            pa[1] = P[(g + 8) * PSTRIDE + kc * 8 + t];
            pa[2] = P[g * PSTRIDE + kc * 8 + t + 4];
            pa[3] = P[(g + 8) * PSTRIDE + kc * 8 + t + 4];
            const float* vb0 = &Vsm[cur][(kc * 8 + t) * KSTRIDE];
            const float* vb1 = &Vsm[cur][(kc * 8 + t + 4) * KSTRIDE];
#pragma unroll
            for (int nt = 0; nt < 8; nt++) {
                unsigned b0 = __float_as_uint(vb0[nt * 8 + g]);
                unsigned b1 = __float_as_uint(vb1[nt * 8 + g]);
                mma_tf32(o[nt], pa, b0, b1);
            }
        }
        __syncthreads();
    }

    l0 += __shfl_xor_sync(0xffffffffu, l0, 1);
    l0 += __shfl_xor_sync(0xffffffffu, l0, 2);
    l1 += __shfl_xor_sync(0xffffffffu, l1, 1);
    l1 += __shfl_xor_sync(0xffffffffu, l1, 2);
    float inv0 = 1.f / l0, inv1 = 1.f / l1;

    float* ob = out + ((size_t)bb * DIMC + TD + hh * 64) * NTOK;
    int tok0 = row0 + g, tok1 = row0 + g + 8;
#pragma unroll
    for (int nt = 0; nt < 8; nt++) {
        int d0 = nt * 8 + 2 * t;
        ob[(size_t)d0 * NTOK + tok0]       = o[nt][0] * inv0;
        ob[(size_t)(d0 + 1) * NTOK + tok0] = o[nt][1] * inv0;
        ob[(size_t)d0 * NTOK + tok1]       = o[nt][2] * inv1;
        ob[(size_t)(d0 + 1) * NTOK + tok1] = o[nt][3] * inv1;
    }
}

// ---------------------------------------------------------------------------
// Launch: 2-stream DAG with capture-safe event fork/join.
//   s0: split ───────────────┐
//   s2: combine ─────────────┤→ gemm(line0) ─┬→ s2: cswin → lepe ───┐
//                            │               └→ s0: gemm(line1) → attn_dn → join
// ---------------------------------------------------------------------------
static cudaStream_t g_s2 = 0;
static cudaEvent_t  g_eB = 0, g_eC = 0, g_e0 = 0, g_eL = 0;

extern "C" void kernel_launch(void* const* d_in, const int* in_sizes, int n_in,
                              void* d_out, int out_size) {
    const float* xa      = (const float*)d_in[0];
    const float* proj1_w = (const float*)d_in[1];
    const float* proj2_w = (const float*)d_in[2];
    const float* qkv_u_w = (const float*)d_in[3];
    const float* qkv_d_w = (const float*)d_in[4];
    const float* lepe_w0 = (const float*)d_in[5];
    const float* lepe_b0 = (const float*)d_in[6];
    const float* lepe_w1 = (const float*)d_in[7];
    const float* lepe_b1 = (const float*)d_in[8];
    float* out = (float*)d_out;

    if (g_s2 == 0) {   // one-time host-side resource setup (no device memory)
        cudaStreamCreateWithFlags(&g_s2, cudaStreamNonBlocking);
        cudaEventCreateWithFlags(&g_eB, cudaEventDisableTiming);
        cudaEventCreateWithFlags(&g_eC, cudaEventDisableTiming);
        cudaEventCreateWithFlags(&g_e0, cudaEventDisableTiming);
        cudaEventCreateWithFlags(&g_eL, cudaEventDisableTiming);
        cudaFuncSetAttribute(qkv_mma_kernel, cudaFuncAttributeMaxDynamicSharedMemorySize, QKV_SMEM);
        cudaFuncSetAttribute(cswin_mma_kernel, cudaFuncAttributeMaxDynamicSharedMemorySize, CSMMA_SMEM);
        cudaFuncSetAttribute(lepe_kernel, cudaFuncAttributeMaxDynamicSharedMemorySize, LEPE_SMEM);
    }

    // fork s2 from the main (capturing) stream
    cudaEventRecord(g_eB, 0);
    cudaStreamWaitEvent(g_s2, g_eB, 0);

    // s0: split xa;  s2: combined weights (independent)
    split_xa_kernel<<<(NB * DIMC * NTOK / 4 + 255) / 256, 256>>>(xa);
    combine_w_kernel<<<dim3(576, 2), 384, 0, g_s2>>>(proj1_w, proj2_w, qkv_u_w, qkv_d_w);
    cudaEventRecord(g_eC, g_s2);
    cudaStreamWaitEvent(0, g_eC, 0);

    // s0: gemm line 0 (feeds upper line)
    qkv_mma_kernel<<<dim3(49, 6, 4), 128, QKV_SMEM>>>(0);
    cudaEventRecord(g_e0, 0);

    // s2: cswin + lepe on line-0 results, concurrent with line-1 work on s0
    cudaStreamWaitEvent(g_s2, g_e0, 0);
    cswin_mma_kernel<<<dim3(7, 16, 8), 128, CSMMA_SMEM, g_s2>>>(out);
    lepe_kernel<<<dim3(8, 2, 8), 256, LEPE_SMEM, g_s2>>>(lepe_w0, lepe_b0, lepe_w1, lepe_b1, out);
    cudaEventRecord(g_eL, g_s2);

    // s0: gemm line 1 -> global attention
    qkv_mma_kernel<<<dim3(49, 6, 4), 128, QKV_SMEM>>>(1);
    attn_dn_kernel<<<dim3(49, 3, 4), 128>>>(out);

    // join s2 back into the main stream
    cudaStreamWaitEvent(0, g_eL, 0);
}

// round 16
// speedup vs baseline: 7.7756x; 1.1621x over previous
#include <cuda_runtime.h>
#include <cuda_bf16.h>
#include <math.h>

// Problem constants
#define NB    4
#define DIMC  384
#define RES   56
#define NTOK  3136          // 56*56
#define TD    192
#define CSC   96

#define LOG2E 1.4426950408889634f
#define CS_SCALE 0.14433756729740643f   // 1/sqrt(48)
#define DN_SCALE 0.125f                 // 1/sqrt(64)

// ---------------------------------------------------------------------------
// Scratch (static device arrays; no allocation anywhere)
// ---------------------------------------------------------------------------
__device__ unsigned g_xph[NB * 192 * NTOK];     // xa packed bf16-hi  [b][c2][n], word={c_even|c_odd<<16}
__device__ unsigned g_xpl[NB * 192 * NTOK];     // xa packed bf16-lo
__device__ unsigned g_wph[2][576 * 192];        // combined weights packed bf16-hi [j][c2]
__device__ unsigned g_wpl[2][576 * 192];        // combined weights packed bf16-lo
__device__ float    g_qkv[2][NB * NTOK * 576];  // [line][((b*3136)+n)*576 + j]

// ---------------------------------------------------------------------------
// Shared helpers
// ---------------------------------------------------------------------------
__device__ __forceinline__ unsigned f2tf32(float f) {
    unsigned u;
    asm("cvt.rna.tf32.f32 %0, %1;" : "=r"(u) : "f"(f));
    return u;
}

__device__ __forceinline__ void cp_async16(void* smem_dst, const void* gsrc) {
    unsigned s = (unsigned)__cvta_generic_to_shared(smem_dst);
    asm volatile("cp.async.cg.shared.global [%0], [%1], 16;\n" :: "r"(s), "l"(gsrc));
}

__device__ __forceinline__ void mma_tf32(float* c, const unsigned* a, unsigned b0, unsigned b1) {
    asm volatile(
        "mma.sync.aligned.m16n8k8.row.col.f32.tf32.tf32.f32 "
        "{%0,%1,%2,%3}, {%4,%5,%6,%7}, {%8,%9}, {%0,%1,%2,%3};"
        : "+f"(c[0]), "+f"(c[1]), "+f"(c[2]), "+f"(c[3])
        : "r"(a[0]), "r"(a[1]), "r"(a[2]), "r"(a[3]), "r"(b0), "r"(b1));
}

__device__ __forceinline__ void mma_bf16(float* c, const unsigned* a, unsigned b0, unsigned b1) {
    asm volatile(
        "mma.sync.aligned.m16n8k16.row.col.f32.bf16.bf16.f32 "
        "{%0,%1,%2,%3}, {%4,%5,%6,%7}, {%8,%9}, {%0,%1,%2,%3};"
        : "+f"(c[0]), "+f"(c[1]), "+f"(c[2]), "+f"(c[3])
        : "r"(a[0]), "r"(a[1]), "r"(a[2]), "r"(a[3]), "r"(b0), "r"(b1));
}

// split fp32 pair (even,odd channel) into packed bf16 hi/lo words
__device__ __forceinline__ void split_pack(float x0, float x1, unsigned& wh, unsigned& wl) {
    __nv_bfloat16 h0 = __float2bfloat16_rn(x0), h1 = __float2bfloat16_rn(x1);
    float r0 = x0 - __bfloat162float(h0);
    float r1 = x1 - __bfloat162float(h1);
    __nv_bfloat16 l0 = __float2bfloat16_rn(r0), l1 = __float2bfloat16_rn(r1);
    wh = ((unsigned)__bfloat16_as_ushort(h1) << 16) | (unsigned)__bfloat16_as_ushort(h0);
    wl = ((unsigned)__bfloat16_as_ushort(l1) << 16) | (unsigned)__bfloat16_as_ushort(l0);
}

// ---------------------------------------------------------------------------
// Kernel 1: combined weights -> packed bf16 hi/lo.  grid (576, 2), block 192
// thread c2 computes channels 2*c2 and 2*c2+1 of Wc[j][:]
// ---------------------------------------------------------------------------
__global__ void combine_w_kernel(const float* __restrict__ p1,
                                 const float* __restrict__ p2,
                                 const float* __restrict__ qu,
                                 const float* __restrict__ qd) {
    int j = blockIdx.x;
    int line = blockIdx.y;
    int c2 = threadIdx.x;               // 0..191
    const float* qw = line ? qd : qu;
    const float* pw = line ? p2 : p1;
    const float* qrow = qw + j * 192;
    float s0 = 0.f, s1 = 0.f;
#pragma unroll 8
    for (int t = 0; t < 192; t++) {
        float q = qrow[t];
        s0 += q * pw[t * 384 + 2 * c2];
        s1 += q * pw[t * 384 + 2 * c2 + 1];
    }
    unsigned wh, wl;
    split_pack(s0, s1, wh, wl);
    g_wph[line][j * 192 + c2] = wh;
    g_wpl[line][j * 192 + c2] = wl;
}

// ---------------------------------------------------------------------------
// Kernel 1b: split xa into packed bf16 hi/lo words [b][c2][n].
// One thread handles 4 tokens of one channel-pair.
// total = NB*192*(NTOK/4) = 602112 threads
// ---------------------------------------------------------------------------
__global__ void __launch_bounds__(256) split_xa_kernel(const float* __restrict__ xa) {
    int idx = blockIdx.x * 256 + threadIdx.x;
    if (idx >= NB * 192 * (NTOK / 4)) return;
    int n4 = idx % (NTOK / 4);
    int rem = idx / (NTOK / 4);
    int c2 = rem % 192;
    int b  = rem / 192;
    int n = n4 * 4;
    const float* r0 = xa + ((size_t)(b * DIMC + 2 * c2) * NTOK) + n;
    const float* r1 = r0 + NTOK;
    float4 v0 = *(const float4*)r0;
    float4 v1 = *(const float4*)r1;
    unsigned wh[4], wl[4];
    split_pack(v0.x, v1.x, wh[0], wl[0]);
    split_pack(v0.y, v1.y, wh[1], wl[1]);
    split_pack(v0.z, v1.z, wh[2], wl[2]);
    split_pack(v0.w, v1.w, wh[3], wl[3]);
    size_t o = (size_t)(b * 192 + c2) * NTOK + n;
    *(uint4*)&g_xph[o] = make_uint4(wh[0], wh[1], wh[2], wh[3]);
    *(uint4*)&g_xpl[o] = make_uint4(wl[0], wl[1], wl[2], wl[3]);
}

// ---------------------------------------------------------------------------
// Kernel 2: qkv GEMM, tensor cores, 3x bf16 (m16n8k16) -- half the HMMA
// count and half the operand traffic of the 3xTF32 version.
// 128 threads / 4 warps, CTA tile 64 tokens x 96 j (warp 16 x 96).
// K chunk = 32 channels = 16 packed c2-rows = 2 k16-steps. 12 chunks.
// cp.async double buffered. K/V tf32 rounding fused into epilogue.
// grid (49, 6, 4=bb), block 128, dyn smem 49152 B.
// ---------------------------------------------------------------------------
#define GC2   16      // packed c2-rows per chunk (= 32 channels)
#define ASTR  72      // A smem [c2=16][m=64] row stride (words)
#define BSTR  20      // B smem [j=96][c2=16] row stride (words)
#define QKV_SMEM ((2 * GC2 * ASTR * 2 + 2 * 96 * BSTR * 2) * 4)   // 49152

__global__ void __launch_bounds__(128, 4) qkv_mma_kernel(int line) {
    extern __shared__ unsigned qsh[];
    unsigned* Ah = qsh;                        // [2][16*72]
    unsigned* Al = Ah + 2 * GC2 * ASTR;
    unsigned* Bh = Al + 2 * GC2 * ASTR;        // [2][96*20]
    unsigned* Bl = Bh + 2 * 96 * BSTR;

    int bb = blockIdx.z;
    int n0 = blockIdx.x * 64;
    int j0 = blockIdx.y * 96;
    const unsigned* Xh = g_xph + (size_t)bb * 192 * NTOK;
    const unsigned* Xl = g_xpl + (size_t)bb * 192 * NTOK;
    const unsigned* Wh = g_wph[line];
    const unsigned* Wl = g_wpl[line];

    int tid = threadIdx.x;
    int warp = tid >> 5, lane = tid & 31;
    int g = lane >> 2, t = lane & 3;
    int mrow = warp * 16;

    float o[12][4];
#pragma unroll
    for (int nt = 0; nt < 12; nt++)
        o[nt][0] = o[nt][1] = o[nt][2] = o[nt][3] = 0.f;

    auto load_chunk = [&](int ch, int buf) {
        int c0 = ch * GC2;
        // A: 16 c2-rows x 64 tokens, hi+lo (256 uint4 each -> 2 per thread)
#pragma unroll
        for (int i = 0; i < 2; i++) {
            int task = tid + i * 128;               // 0..255
            int kr = task >> 4, c4 = (task & 15) * 4;
            cp_async16(&Ah[(buf * GC2 + kr) * ASTR + c4], &Xh[(size_t)(c0 + kr) * NTOK + n0 + c4]);
            cp_async16(&Al[(buf * GC2 + kr) * ASTR + c4], &Xl[(size_t)(c0 + kr) * NTOK + n0 + c4]);
        }
        // B: 96 j-rows x 16 c2-words, hi+lo (384 uint4 each -> 3 per thread)
#pragma unroll
        for (int i = 0; i < 3; i++) {
            int task = tid + i * 128;               // 0..383
            int jr = task >> 2, c4 = (task & 3) * 4;
            cp_async16(&Bh[(buf * 96 + jr) * BSTR + c4], &Wh[(j0 + jr) * 192 + c0 + c4]);
            cp_async16(&Bl[(buf * 96 + jr) * BSTR + c4], &Wl[(j0 + jr) * 192 + c0 + c4]);
        }
        asm volatile("cp.async.commit_group;\n" ::: "memory");
    };

    load_chunk(0, 0);

    for (int ch = 0; ch < 12; ch++) {
        int cur = ch & 1;
        if (ch < 11) {
            load_chunk(ch + 1, cur ^ 1);
            asm volatile("cp.async.wait_group 1;\n" ::: "memory");
        } else {
            asm volatile("cp.async.wait_group 0;\n" ::: "memory");
        }
        __syncthreads();

        const unsigned* Ahc = &Ah[cur * GC2 * ASTR];
        const unsigned* Alc = &Al[cur * GC2 * ASTR];
        const unsigned* Bhc = &Bh[cur * 96 * BSTR];
        const unsigned* Blc = &Bl[cur * 96 * BSTR];

#pragma unroll
        for (int kc = 0; kc < 2; kc++) {            // two k16 steps per chunk
            int kb = kc * 8;                        // c2 base within chunk
            unsigned ah[4], al[4];
            ah[0] = Ahc[(kb + t) * ASTR + mrow + g];
            ah[1] = Ahc[(kb + t) * ASTR + mrow + g + 8];
            ah[2] = Ahc[(kb + t + 4) * ASTR + mrow + g];
            ah[3] = Ahc[(kb + t + 4) * ASTR + mrow + g + 8];
            al[0] = Alc[(kb + t) * ASTR + mrow + g];
            al[1] = Alc[(kb + t) * ASTR + mrow + g + 8];
            al[2] = Alc[(kb + t + 4) * ASTR + mrow + g];
            al[3] = Alc[(kb + t + 4) * ASTR + mrow + g + 8];
#pragma unroll
            for (int nt = 0; nt < 12; nt++) {
                const unsigned* bph = &Bhc[(nt * 8 + g) * BSTR + kb];
                const unsigned* bpl = &Blc[(nt * 8 + g) * BSTR + kb];
                unsigned bh0 = bph[t], bh1 = bph[t + 4];
                unsigned bl0 = bpl[t], bl1 = bpl[t + 4];
                mma_bf16(o[nt], ah, bh0, bh1);
                mma_bf16(o[nt], ah, bl0, bl1);
                mma_bf16(o[nt], al, bh0, bh1);
            }
        }
        __syncthreads();
    }

    // epilogue: j < 192 is Q (store raw); j >= 192 is K/V (round to tf32)
    bool doRound = (j0 >= 192);
    float* op = g_qkv[line] + (size_t)bb * NTOK * 576;
    int tok0 = n0 + mrow + g, tok1 = tok0 + 8;
#pragma unroll
    for (int nt = 0; nt < 12; nt++) {
        int j = j0 + nt * 8 + 2 * t;
        float v0 = o[nt][0], v1 = o[nt][1], v2 = o[nt][2], v3 = o[nt][3];
        if (doRound) {
            v0 = __uint_as_float(f2tf32(v0));
            v1 = __uint_as_float(f2tf32(v1));
            v2 = __uint_as_float(f2tf32(v2));
            v3 = __uint_as_float(f2tf32(v3));
        }
        *(float2*)&op[(size_t)tok0 * 576 + j] = make_float2(v0, v1);
        *(float2*)&op[(size_t)tok1 * 576 + j] = make_float2(v2, v3);
    }
}

// ---------------------------------------------------------------------------
// Kernel 3: CSWin attention (upper line) -- tensor-core flash (R10-passing)
// ---------------------------------------------------------------------------
#define CSKT 56
#define CSSTRIDE 56
#define CSPSTRIDE 60
#define CSMMA_SMEM (4 * CSKT * CSSTRIDE * 4 + 4 * 16 * CSPSTRIDE * 4)   // 65536

__global__ void __launch_bounds__(128) cswin_mma_kernel(float* __restrict__ out) {
    extern __shared__ float csh[];
    float* Ksm[2] = { csh,                    csh + CSKT * CSSTRIDE };
    float* Vsm[2] = { csh + 2 * CSKT * CSSTRIDE, csh + 3 * CSKT * CSSTRIDE };
    unsigned* Pbase = (unsigned*)(csh + 4 * CSKT * CSSTRIDE);

    int qt = blockIdx.x;
    int win = blockIdx.y >> 1, hh = blockIdx.y & 1;
    int bb = blockIdx.z >> 1, br = blockIdx.z & 1;
    int choff = br * CSC + hh * 48;
    const float* qkv = g_qkv[0] + (size_t)bb * NTOK * 576;
    int tid = threadIdx.x;
    int warp = tid >> 5, lane = tid & 31;
    int g = lane >> 2, t = lane & 3;
    int row0 = qt * 64 + warp * 16;
    unsigned* P = Pbase + warp * 16 * CSPSTRIDE;

    auto tok2n = [&](int c) {
        int hl, wl;
        if (br) { hl = c / 56; wl = c - hl * 56; }
        else    { hl = c / 7;  wl = c - hl * 7;  }
        int h = br ? win * 7 + hl : hl;
        int w = br ? wl : win * 7 + wl;
        return h * RES + w;
    };

    unsigned qa[6][4];
    {
        const float qscale = CS_SCALE * LOG2E;
        int r0c = min(row0 + g, 391), r1c = min(row0 + g + 8, 391);
        const float* q0 = qkv + (size_t)tok2n(r0c) * 576 + choff;
        const float* q8 = qkv + (size_t)tok2n(r1c) * 576 + choff;
#pragma unroll
        for (int kc = 0; kc < 6; kc++) {
            qa[kc][0] = f2tf32(q0[kc * 8 + t] * qscale);
            qa[kc][1] = f2tf32(q8[kc * 8 + t] * qscale);
            qa[kc][2] = f2tf32(q0[kc * 8 + t + 4] * qscale);
            qa[kc][3] = f2tf32(q8[kc * 8 + t + 4] * qscale);
        }
    }

    float o[6][4];
#pragma unroll
    for (int nt = 0; nt < 6; nt++)
        o[nt][0] = o[nt][1] = o[nt][2] = o[nt][3] = 0.f;
    float m0 = -1e30f, m1 = -1e30f, l0 = 0.f, l1 = 0.f;

    auto load_tile = [&](int ti, int buf) {
        float* kd = Ksm[buf];
        float* vd = Vsm[buf];
        for (int i = tid; i < 56 * 12; i += 128) {
            int rr = i / 12, c4 = (i % 12) * 4;
            int n = tok2n(ti * CSKT + rr);
            const float* src = qkv + (size_t)n * 576 + choff + c4;
            cp_async16(kd + rr * CSSTRIDE + c4, src + 192);
            cp_async16(vd + rr * CSSTRIDE + c4, src + 384);
        }
        asm volatile("cp.async.commit_group;\n" ::: "memory");
    };

    load_tile(0, 0);

    for (int ti = 0; ti < 7; ti++) {
        int cur = ti & 1;
        if (ti < 6) {
            load_tile(ti + 1, cur ^ 1);
            asm volatile("cp.async.wait_group 1;\n" ::: "memory");
        } else {
            asm volatile("cp.async.wait_group 0;\n" ::: "memory");
        }
        __syncthreads();

        float s[7][4];
#pragma unroll
        for (int nt = 0; nt < 7; nt++) {
            s[nt][0] = s[nt][1] = s[nt][2] = s[nt][3] = 0.f;
            const float* kb = &Ksm[cur][(nt * 8 + g) * CSSTRIDE];
#pragma unroll
            for (int kc = 0; kc < 6; kc++) {
                unsigned b0 = __float_as_uint(kb[kc * 8 + t]);
                unsigned b1 = __float_as_uint(kb[kc * 8 + t + 4]);
                mma_tf32(s[nt], qa[kc], b0, b1);
            }
        }

        float rmax0 = s[0][0], rmax1 = s[0][2];
#pragma unroll
        for (int nt = 0; nt < 7; nt++) {
            rmax0 = fmaxf(rmax0, fmaxf(s[nt][0], s[nt][1]));
            rmax1 = fmaxf(rmax1, fmaxf(s[nt][2], s[nt][3]));
        }
        rmax0 = fmaxf(rmax0, __shfl_xor_sync(0xffffffffu, rmax0, 1));
        rmax0 = fmaxf(rmax0, __shfl_xor_sync(0xffffffffu, rmax0, 2));
        rmax1 = fmaxf(rmax1, __shfl_xor_sync(0xffffffffu, rmax1, 1));
        rmax1 = fmaxf(rmax1, __shfl_xor_sync(0xffffffffu, rmax1, 2));

        float mn0 = fmaxf(m0, rmax0), mn1 = fmaxf(m1, rmax1);
        float rs0 = exp2f(m0 - mn0),  rs1 = exp2f(m1 - mn1);
        l0 *= rs0; l1 *= rs1;

        float psum0 = 0.f, psum1 = 0.f;
#pragma unroll
        for (int nt = 0; nt < 7; nt++) {
            float p0 = exp2f(s[nt][0] - mn0);
            float p1 = exp2f(s[nt][1] - mn0);
            float p2 = exp2f(s[nt][2] - mn1);
            float p3 = exp2f(s[nt][3] - mn1);
            psum0 += p0 + p1; psum1 += p2 + p3;
            P[g * CSPSTRIDE + nt * 8 + 2 * t]           = f2tf32(p0);
            P[g * CSPSTRIDE + nt * 8 + 2 * t + 1]       = f2tf32(p1);
            P[(g + 8) * CSPSTRIDE + nt * 8 + 2 * t]     = f2tf32(p2);
            P[(g + 8) * CSPSTRIDE + nt * 8 + 2 * t + 1] = f2tf32(p3);
        }
        l0 += psum0; l1 += psum1;
#pragma unroll
        for (int nt = 0; nt < 6; nt++) {
            o[nt][0] *= rs0; o[nt][1] *= rs0;
            o[nt][2] *= rs1; o[nt][3] *= rs1;
        }
        m0 = mn0; m1 = mn1;
        __syncwarp();

#pragma unroll
        for (int kc = 0; kc < 7; kc++) {
            unsigned pa[4];
            pa[0] = P[g * CSPSTRIDE + kc * 8 + t];
            pa[1] = P[(g + 8) * CSPSTRIDE + kc * 8 + t];
            pa[2] = P[g * CSPSTRIDE + kc * 8 + t + 4];
            pa[3] = P[(g + 8) * CSPSTRIDE + kc * 8 + t + 4];
            const float* vb0 = &Vsm[cur][(kc * 8 + t) * CSSTRIDE];
            const float* vb1 = &Vsm[cur][(kc * 8 + t + 4) * CSSTRIDE];
#pragma unroll
            for (int nt = 0; nt < 6; nt++) {
                unsigned b0 = __float_as_uint(vb0[nt * 8 + g]);
                unsigned b1 = __float_as_uint(vb1[nt * 8 + g]);
                mma_tf32(o[nt], pa, b0, b1);
            }
        }
        __syncthreads();
    }

    l0 += __shfl_xor_sync(0xffffffffu, l0, 1);
    l0 += __shfl_xor_sync(0xffffffffu, l0, 2);
    l1 += __shfl_xor_sync(0xffffffffu, l1, 1);
    l1 += __shfl_xor_sync(0xffffffffu, l1, 2);
    float inv0 = 1.f / l0, inv1 = 1.f / l1;

    float* ob = out + ((size_t)bb * DIMC + choff) * NTOK;
    int tok0 = row0 + g, tok1 = row0 + g + 8;
    if (tok0 < 392) {
        int n = tok2n(tok0);
#pragma unroll
        for (int nt = 0; nt < 6; nt++) {
            int d0 = nt * 8 + 2 * t;
            ob[(size_t)d0 * NTOK + n]       = o[nt][0] * inv0;
            ob[(size_t)(d0 + 1) * NTOK + n] = o[nt][1] * inv0;
        }
    }
    if (tok1 < 392) {
        int n = tok2n(tok1);
#pragma unroll
        for (int nt = 0; nt < 6; nt++) {
            int d0 = nt * 8 + 2 * t;
            ob[(size_t)d0 * NTOK + n]       = o[nt][2] * inv1;
            ob[(size_t)(d0 + 1) * NTOK + n] = o[nt][3] * inv1;
        }
    }
}

// ---------------------------------------------------------------------------
// Kernel 3b: LePE (depthwise 3x3 on V) -- ADDS into out.  (R10-passing)
// ---------------------------------------------------------------------------
#define LEPE_SMEM (392 * 48 * 4)

__global__ void __launch_bounds__(256) lepe_kernel(const float* __restrict__ lw0,
                                                   const float* __restrict__ lb0,
                                                   const float* __restrict__ lw1,
                                                   const float* __restrict__ lb1,
                                                   float* __restrict__ out) {
    extern __shared__ float Vs[];   // [392][48]
    __shared__ float wsh[48][9];
    __shared__ float bsh[48];

    int win = blockIdx.x;
    int hh  = blockIdx.y;
    int bb  = blockIdx.z >> 1, br = blockIdx.z & 1;
    int SW = br ? 56 : 7;
    int SH = br ? 7 : 56;
    int choff = br * CSC + hh * 48;
    const float* qkv = g_qkv[0] + (size_t)bb * NTOK * 576;
    int tid = threadIdx.x;

    for (int e = tid; e < 392 * 12; e += 256) {
        int tk = e / 12, d4 = (e % 12) * 4;
        int hl, wl;
        if (br) { hl = tk / 56; wl = tk - hl * 56; }
        else    { hl = tk / 7;  wl = tk - hl * 7;  }
        int h = br ? win * 7 + hl : hl;
        int w = br ? wl : win * 7 + wl;
        int n = h * RES + w;
        *(float4*)&Vs[tk * 48 + d4] = *(const float4*)&qkv[(size_t)n * 576 + choff + 384 + d4];
    }
    const float* lw = br ? lw1 : lw0;
    const float* lb = br ? lb1 : lb0;
    for (int e = tid; e < 48 * 9; e += 256) {
        int d = e / 9, k = e % 9;
        wsh[d][k] = lw[(hh * 48 + d) * 9 + k];
    }
    if (tid < 48) bsh[tid] = lb[hh * 48 + tid];
    __syncthreads();

    for (int e = tid; e < 48 * 392; e += 256) {
        int d = e / 392, r = e - d * 392;
        int hl, wl;
        if (br) { hl = r / 56; wl = r - hl * 56; }
        else    { hl = r / 7;  wl = r - hl * 7;  }
        float lep = bsh[d];
#pragma unroll
        for (int dy = -1; dy <= 1; dy++) {
#pragma unroll
            for (int dx = -1; dx <= 1; dx++) {
                int h2 = hl + dy, w2 = wl + dx;
                if (h2 < 0 || h2 >= SH || w2 < 0 || w2 >= SW) continue;
                lep += Vs[(h2 * SW + w2) * 48 + d] * wsh[d][(dy + 1) * 3 + (dx + 1)];
            }
        }
        int h = br ? win * 7 + hl : hl;
        int w = br ? wl : win * 7 + wl;
        int n = h * RES + w;
        out[((size_t)bb * DIMC + choff + d) * NTOK + n] += lep;
    }
}

// ---------------------------------------------------------------------------
// Kernel 4: global attention (lower line) -- tensor-core flash (R9-passing)
// ---------------------------------------------------------------------------
#define KT 32
#define KSTRIDE 72
#define PSTRIDE 36

__global__ void __launch_bounds__(128) attn_dn_kernel(float* __restrict__ out) {
    __shared__ float    Ksm[2][KT * KSTRIDE];
    __shared__ float    Vsm[2][KT * KSTRIDE];
    __shared__ unsigned Psm[4][16 * PSTRIDE];

    int qt = blockIdx.x, hh = blockIdx.y, bb = blockIdx.z;
    const float* qkv = g_qkv[1] + (size_t)bb * NTOK * 576;
    int tid = threadIdx.x;
    int warp = tid >> 5, lane = tid & 31;
    int g = lane >> 2, t = lane & 3;
    int row0 = qt * 64 + warp * 16;

    unsigned qa[8][4];
    {
        const float qscale = DN_SCALE * LOG2E;
        const float* q0 = qkv + (size_t)(row0 + g) * 576 + hh * 64;
        const float* q8 = qkv + (size_t)(row0 + g + 8) * 576 + hh * 64;
#pragma unroll
        for (int kc = 0; kc < 8; kc++) {
            qa[kc][0] = f2tf32(q0[kc * 8 + t] * qscale);
            qa[kc][1] = f2tf32(q8[kc * 8 + t] * qscale);
            qa[kc][2] = f2tf32(q0[kc * 8 + t + 4] * qscale);
            qa[kc][3] = f2tf32(q8[kc * 8 + t + 4] * qscale);
        }
    }

    float o[8][4];
#pragma unroll
    for (int nt = 0; nt < 8; nt++)
        o[nt][0] = o[nt][1] = o[nt][2] = o[nt][3] = 0.f;
    float m0 = -1e30f, m1 = -1e30f, l0 = 0.f, l1 = 0.f;

    auto load_tile = [&](int kt, int buf) {
#pragma unroll
        for (int i = 0; i < 4; i++) {
            int task = tid * 4 + i;
            int rrow = task >> 4, chunk = task & 15;
            const float* src = qkv + (size_t)(kt * KT + rrow) * 576 + hh * 64 + chunk * 4;
            cp_async16(&Ksm[buf][rrow * KSTRIDE + chunk * 4], src + 192);
            cp_async16(&Vsm[buf][rrow * KSTRIDE + chunk * 4], src + 384);
        }
        asm volatile("cp.async.commit_group;\n" ::: "memory");
    };

    load_tile(0, 0);

    for (int kt = 0; kt < 98; kt++) {
        int cur = kt & 1;
        if (kt < 97) {
            load_tile(kt + 1, cur ^ 1);
            asm volatile("cp.async.wait_group 1;\n" ::: "memory");
        } else {
            asm volatile("cp.async.wait_group 0;\n" ::: "memory");
        }
        __syncthreads();

        float s[4][4];
#pragma unroll
        for (int nt = 0; nt < 4; nt++) {
            s[nt][0] = s[nt][1] = s[nt][2] = s[nt][3] = 0.f;
            const float* kb = &Ksm[cur][(nt * 8 + g) * KSTRIDE];
#pragma unroll
            for (int kc = 0; kc < 8; kc++) {
                unsigned b0 = __float_as_uint(kb[kc * 8 + t]);
                unsigned b1 = __float_as_uint(kb[kc * 8 + t + 4]);
                mma_tf32(s[nt], qa[kc], b0, b1);
            }
        }

        float rmax0 = fmaxf(fmaxf(s[0][0], s[0][1]), fmaxf(s[1][0], s[1][1]));
        rmax0 = fmaxf(rmax0, fmaxf(fmaxf(s[2][0], s[2][1]), fmaxf(s[3][0], s[3][1])));
        float rmax1 = fmaxf(fmaxf(s[0][2], s[0][3]), fmaxf(s[1][2], s[1][3]));
        rmax1 = fmaxf(rmax1, fmaxf(fmaxf(s[2][2], s[2][3]), fmaxf(s[3][2], s[3][3])));
        rmax0 = fmaxf(rmax0, __shfl_xor_sync(0xffffffffu, rmax0, 1));
        rmax0 = fmaxf(rmax0, __shfl_xor_sync(0xffffffffu, rmax0, 2));
        rmax1 = fmaxf(rmax1, __shfl_xor_sync(0xffffffffu, rmax1, 1));
        rmax1 = fmaxf(rmax1, __shfl_xor_sync(0xffffffffu, rmax1, 2));

        float mn0 = fmaxf(m0, rmax0), mn1 = fmaxf(m1, rmax1);
        float rs0 = exp2f(m0 - mn0),  rs1 = exp2f(m1 - mn1);
        l0 *= rs0; l1 *= rs1;

        unsigned* P = Psm[warp];
        float psum0 = 0.f, psum1 = 0.f;
#pragma unroll
        for (int nt = 0; nt < 4; nt++) {
            float p0 = exp2f(s[nt][0] - mn0);
            float p1 = exp2f(s[nt][1] - mn0);
            float p2 = exp2f(s[nt][2] - mn1);
            float p3 = exp2f(s[nt][3] - mn1);
            psum0 += p0 + p1; psum1 += p2 + p3;
            P[g * PSTRIDE + nt * 8 + 2 * t]           = f2tf32(p0);
            P[g * PSTRIDE + nt * 8 + 2 * t + 1]       = f2tf32(p1);
            P[(g + 8) * PSTRIDE + nt * 8 + 2 * t]     = f2tf32(p2);
            P[(g + 8) * PSTRIDE + nt * 8 + 2 * t + 1] = f2tf32(p3);
        }
        l0 += psum0; l1 += psum1;
#pragma unroll
        for (int nt = 0; nt < 8; nt++) {
            o[nt][0] *= rs0; o[nt][1] *= rs0;
            o[nt][2] *= rs1; o[nt][3] *= rs1;
        }
        m0 = mn0; m1 = mn1;
        __syncwarp();

#pragma unroll
        for (int kc = 0; kc < 4; kc++) {
            unsigned pa[4];
            pa[0] = P[g * PSTRIDE + kc * 8 + t];
            pa[1] = P[(g + 8) * PSTRIDE + kc * 8 + t];
            pa[2] = P[g * PSTRIDE + kc * 8 + t + 4];
            pa[3] = P[(g + 8) * PSTRIDE + kc * 8 + t + 4];
            const float* vb0 = &Vsm[cur][(kc * 8 + t) * KSTRIDE];
            const float* vb1 = &Vsm[cur][(kc * 8 + t + 4) * KSTRIDE];
#pragma unroll
            for (int nt = 0; nt < 8; nt++) {
                unsigned b0 = __float_as_uint(vb0[nt * 8 + g]);
                unsigned b1 = __float_as_uint(vb1[nt * 8 + g]);
                mma_tf32(o[nt], pa, b0, b1);
            }
        }
        __syncthreads();
    }

    l0 += __shfl_xor_sync(0xffffffffu, l0, 1);
    l0 += __shfl_xor_sync(0xffffffffu, l0, 2);
    l1 += __shfl_xor_sync(0xffffffffu, l1, 1);
    l1 += __shfl_xor_sync(0xffffffffu, l1, 2);
    float inv0 = 1.f / l0, inv1 = 1.f / l1;

    float* ob = out + ((size_t)bb * DIMC + TD + hh * 64) * NTOK;
    int tok0 = row0 + g, tok1 = row0 + g + 8;
#pragma unroll
    for (int nt = 0; nt < 8; nt++) {
        int d0 = nt * 8 + 2 * t;
        ob[(size_t)d0 * NTOK + tok0]       = o[nt][0] * inv0;
        ob[(size_t)(d0 + 1) * NTOK + tok0] = o[nt][1] * inv0;
        ob[(size_t)d0 * NTOK + tok1]       = o[nt][2] * inv1;
        ob[(size_t)(d0 + 1) * NTOK + tok1] = o[nt][3] * inv1;
    }
}

// ---------------------------------------------------------------------------
// Launch: 2-stream DAG with capture-safe event fork/join (R15-passing).
// ---------------------------------------------------------------------------
static cudaStream_t g_s2 = 0;
static cudaEvent_t  g_eB = 0, g_eC = 0, g_e0 = 0, g_eL = 0;

extern "C" void kernel_launch(void* const* d_in, const int* in_sizes, int n_in,
                              void* d_out, int out_size) {
    const float* xa      = (const float*)d_in[0];
    const float* proj1_w = (const float*)d_in[1];
    const float* proj2_w = (const float*)d_in[2];
    const float* qkv_u_w = (const float*)d_in[3];
    const float* qkv_d_w = (const float*)d_in[4];
    const float* lepe_w0 = (const float*)d_in[5];
    const float* lepe_b0 = (const float*)d_in[6];
    const float* lepe_w1 = (const float*)d_in[7];
    const float* lepe_b1 = (const float*)d_in[8];
    float* out = (float*)d_out;

    if (g_s2 == 0) {   // one-time host-side resource setup (no device memory)
        cudaStreamCreateWithFlags(&g_s2, cudaStreamNonBlocking);
        cudaEventCreateWithFlags(&g_eB, cudaEventDisableTiming);
        cudaEventCreateWithFlags(&g_eC, cudaEventDisableTiming);
        cudaEventCreateWithFlags(&g_e0, cudaEventDisableTiming);
        cudaEventCreateWithFlags(&g_eL, cudaEventDisableTiming);
        cudaFuncSetAttribute(qkv_mma_kernel, cudaFuncAttributeMaxDynamicSharedMemorySize, QKV_SMEM);
        cudaFuncSetAttribute(cswin_mma_kernel, cudaFuncAttributeMaxDynamicSharedMemorySize, CSMMA_SMEM);
        cudaFuncSetAttribute(lepe_kernel, cudaFuncAttributeMaxDynamicSharedMemorySize, LEPE_SMEM);
    }

    // fork s2 from the main (capturing) stream
    cudaEventRecord(g_eB, 0);
    cudaStreamWaitEvent(g_s2, g_eB, 0);

    // s0: split xa;  s2: combined weights (independent)
    split_xa_kernel<<<(NB * 192 * (NTOK / 4) + 255) / 256, 256>>>(xa);
    combine_w_kernel<<<dim3(576, 2), 192, 0, g_s2>>>(proj1_w, proj2_w, qkv_u_w, qkv_d_w);
    cudaEventRecord(g_eC, g_s2);
    cudaStreamWaitEvent(0, g_eC, 0);

    // s0: gemm line 0 (feeds upper line)
    qkv_mma_kernel<<<dim3(49, 6, 4), 128, QKV_SMEM>>>(0);
    cudaEventRecord(g_e0, 0);

    // s2: cswin + lepe on line-0 results, concurrent with line-1 work on s0
    cudaStreamWaitEvent(g_s2, g_e0, 0);
    cswin_mma_kernel<<<dim3(7, 16, 8), 128, CSMMA_SMEM, g_s2>>>(out);
    lepe_kernel<<<dim3(8, 2, 8), 256, LEPE_SMEM, g_s2>>>(lepe_w0, lepe_b0, lepe_w1, lepe_b1, out);
    cudaEventRecord(g_eL, g_s2);

    // s0: gemm line 1 -> global attention
    qkv_mma_kernel<<<dim3(49, 6, 4), 128, QKV_SMEM>>>(1);
    attn_dn_kernel<<<dim3(49, 3, 4), 128>>>(out);

    // join s2 back into the main stream
    cudaStreamWaitEvent(0, g_eL, 0);
}

// round 17
// speedup vs baseline: 8.2651x; 1.0630x over previous
#include <cuda_runtime.h>
#include <cuda_bf16.h>
#include <math.h>

// Problem constants
#define NB    4
#define DIMC  384
#define RES   56
#define NTOK  3136          // 56*56
#define TD    192
#define CSC   96

#define LOG2E 1.4426950408889634f
#define CS_SCALE 0.14433756729740643f   // 1/sqrt(48)
#define DN_SCALE 0.125f                 // 1/sqrt(64)

// ---------------------------------------------------------------------------
// Scratch (static device arrays; no allocation anywhere)
// ---------------------------------------------------------------------------
__device__ unsigned g_xph[NB * 192 * NTOK];     // xa packed bf16-hi  [b][c2][n]
__device__ unsigned g_xpl[NB * 192 * NTOK];     // xa packed bf16-lo
__device__ unsigned g_wph[2][576 * 192];        // combined weights packed bf16-hi
__device__ unsigned g_wpl[2][576 * 192];        // combined weights packed bf16-lo
__device__ float    g_qkv[2][NB * NTOK * 576];  // [line][((b*3136)+n)*576 + j]

// ---------------------------------------------------------------------------
// Shared helpers
// ---------------------------------------------------------------------------
__device__ __forceinline__ unsigned f2tf32(float f) {
    unsigned u;
    asm("cvt.rna.tf32.f32 %0, %1;" : "=r"(u) : "f"(f));
    return u;
}

__device__ __forceinline__ void cp_async16(void* smem_dst, const void* gsrc) {
    unsigned s = (unsigned)__cvta_generic_to_shared(smem_dst);
    asm volatile("cp.async.cg.shared.global [%0], [%1], 16;\n" :: "r"(s), "l"(gsrc));
}

__device__ __forceinline__ void mma_tf32(float* c, const unsigned* a, unsigned b0, unsigned b1) {
    asm volatile(
        "mma.sync.aligned.m16n8k8.row.col.f32.tf32.tf32.f32 "
        "{%0,%1,%2,%3}, {%4,%5,%6,%7}, {%8,%9}, {%0,%1,%2,%3};"
        : "+f"(c[0]), "+f"(c[1]), "+f"(c[2]), "+f"(c[3])
        : "r"(a[0]), "r"(a[1]), "r"(a[2]), "r"(a[3]), "r"(b0), "r"(b1));
}

__device__ __forceinline__ void mma_bf16(float* c, const unsigned* a, unsigned b0, unsigned b1) {
    asm volatile(
        "mma.sync.aligned.m16n8k16.row.col.f32.bf16.bf16.f32 "
        "{%0,%1,%2,%3}, {%4,%5,%6,%7}, {%8,%9}, {%0,%1,%2,%3};"
        : "+f"(c[0]), "+f"(c[1]), "+f"(c[2]), "+f"(c[3])
        : "r"(a[0]), "r"(a[1]), "r"(a[2]), "r"(a[3]), "r"(b0), "r"(b1));
}

// split fp32 pair (even,odd channel) into packed bf16 hi/lo words
__device__ __forceinline__ void split_pack(float x0, float x1, unsigned& wh, unsigned& wl) {
    __nv_bfloat16 h0 = __float2bfloat16_rn(x0), h1 = __float2bfloat16_rn(x1);
    float r0 = x0 - __bfloat162float(h0);
    float r1 = x1 - __bfloat162float(h1);
    __nv_bfloat16 l0 = __float2bfloat16_rn(r0), l1 = __float2bfloat16_rn(r1);
    wh = ((unsigned)__bfloat16_as_ushort(h1) << 16) | (unsigned)__bfloat16_as_ushort(h0);
    wl = ((unsigned)__bfloat16_as_ushort(l1) << 16) | (unsigned)__bfloat16_as_ushort(l0);
}

// ---------------------------------------------------------------------------
// Kernel 1: combined weights -> packed bf16 hi/lo.  grid (576, 2), block 192
// ---------------------------------------------------------------------------
__global__ void combine_w_kernel(const float* __restrict__ p1,
                                 const float* __restrict__ p2,
                                 const float* __restrict__ qu,
                                 const float* __restrict__ qd) {
    int j = blockIdx.x;
    int line = blockIdx.y;
    int c2 = threadIdx.x;               // 0..191
    const float* qw = line ? qd : qu;
    const float* pw = line ? p2 : p1;
    const float* qrow = qw + j * 192;
    float s0 = 0.f, s1 = 0.f;
#pragma unroll 8
    for (int t = 0; t < 192; t++) {
        float q = qrow[t];
        s0 += q * pw[t * 384 + 2 * c2];
        s1 += q * pw[t * 384 + 2 * c2 + 1];
    }
    unsigned wh, wl;
    split_pack(s0, s1, wh, wl);
    g_wph[line][j * 192 + c2] = wh;
    g_wpl[line][j * 192 + c2] = wl;
}

// ---------------------------------------------------------------------------
// Kernel 1b: split xa into packed bf16 hi/lo words [b][c2][n].
// ---------------------------------------------------------------------------
__global__ void __launch_bounds__(256) split_xa_kernel(const float* __restrict__ xa) {
    int idx = blockIdx.x * 256 + threadIdx.x;
    if (idx >= NB * 192 * (NTOK / 4)) return;
    int n4 = idx % (NTOK / 4);
    int rem = idx / (NTOK / 4);
    int c2 = rem % 192;
    int b  = rem / 192;
    int n = n4 * 4;
    const float* r0 = xa + ((size_t)(b * DIMC + 2 * c2) * NTOK) + n;
    const float* r1 = r0 + NTOK;
    float4 v0 = *(const float4*)r0;
    float4 v1 = *(const float4*)r1;
    unsigned wh[4], wl[4];
    split_pack(v0.x, v1.x, wh[0], wl[0]);
    split_pack(v0.y, v1.y, wh[1], wl[1]);
    split_pack(v0.z, v1.z, wh[2], wl[2]);
    split_pack(v0.w, v1.w, wh[3], wl[3]);
    size_t o = (size_t)(b * 192 + c2) * NTOK + n;
    *(uint4*)&g_xph[o] = make_uint4(wh[0], wh[1], wh[2], wh[3]);
    *(uint4*)&g_xpl[o] = make_uint4(wl[0], wl[1], wl[2], wl[3]);
}

// ---------------------------------------------------------------------------
// Kernel 2: qkv GEMM, tensor cores, 3x bf16 (m16n8k16).  (R16-passing)
// grid (49, 6, 4=bb), block 128, dyn smem 49152 B.
// ---------------------------------------------------------------------------
#define GC2   16
#define ASTR  72
#define BSTR  20
#define QKV_SMEM ((2 * GC2 * ASTR * 2 + 2 * 96 * BSTR * 2) * 4)   // 49152

__global__ void __launch_bounds__(128, 4) qkv_mma_kernel(int line) {
    extern __shared__ unsigned qsh[];
    unsigned* Ah = qsh;
    unsigned* Al = Ah + 2 * GC2 * ASTR;
    unsigned* Bh = Al + 2 * GC2 * ASTR;
    unsigned* Bl = Bh + 2 * 96 * BSTR;

    int bb = blockIdx.z;
    int n0 = blockIdx.x * 64;
    int j0 = blockIdx.y * 96;
    const unsigned* Xh = g_xph + (size_t)bb * 192 * NTOK;
    const unsigned* Xl = g_xpl + (size_t)bb * 192 * NTOK;
    const unsigned* Wh = g_wph[line];
    const unsigned* Wl = g_wpl[line];

    int tid = threadIdx.x;
    int warp = tid >> 5, lane = tid & 31;
    int g = lane >> 2, t = lane & 3;
    int mrow = warp * 16;

    float o[12][4];
#pragma unroll
    for (int nt = 0; nt < 12; nt++)
        o[nt][0] = o[nt][1] = o[nt][2] = o[nt][3] = 0.f;

    auto load_chunk = [&](int ch, int buf) {
        int c0 = ch * GC2;
#pragma unroll
        for (int i = 0; i < 2; i++) {
            int task = tid + i * 128;
            int kr = task >> 4, c4 = (task & 15) * 4;
            cp_async16(&Ah[(buf * GC2 + kr) * ASTR + c4], &Xh[(size_t)(c0 + kr) * NTOK + n0 + c4]);
            cp_async16(&Al[(buf * GC2 + kr) * ASTR + c4], &Xl[(size_t)(c0 + kr) * NTOK + n0 + c4]);
        }
#pragma unroll
        for (int i = 0; i < 3; i++) {
            int task = tid + i * 128;
            int jr = task >> 2, c4 = (task & 3) * 4;
            cp_async16(&Bh[(buf * 96 + jr) * BSTR + c4], &Wh[(j0 + jr) * 192 + c0 + c4]);
            cp_async16(&Bl[(buf * 96 + jr) * BSTR + c4], &Wl[(j0 + jr) * 192 + c0 + c4]);
        }
        asm volatile("cp.async.commit_group;\n" ::: "memory");
    };

    load_chunk(0, 0);

    for (int ch = 0; ch < 12; ch++) {
        int cur = ch & 1;
        if (ch < 11) {
            load_chunk(ch + 1, cur ^ 1);
            asm volatile("cp.async.wait_group 1;\n" ::: "memory");
        } else {
            asm volatile("cp.async.wait_group 0;\n" ::: "memory");
        }
        __syncthreads();

        const unsigned* Ahc = &Ah[cur * GC2 * ASTR];
        const unsigned* Alc = &Al[cur * GC2 * ASTR];
        const unsigned* Bhc = &Bh[cur * 96 * BSTR];
        const unsigned* Blc = &Bl[cur * 96 * BSTR];

#pragma unroll
        for (int kc = 0; kc < 2; kc++) {
            int kb = kc * 8;
            unsigned ah[4], al[4];
            ah[0] = Ahc[(kb + t) * ASTR + mrow + g];
            ah[1] = Ahc[(kb + t) * ASTR + mrow + g + 8];
            ah[2] = Ahc[(kb + t + 4) * ASTR + mrow + g];
            ah[3] = Ahc[(kb + t + 4) * ASTR + mrow + g + 8];
            al[0] = Alc[(kb + t) * ASTR + mrow + g];
            al[1] = Alc[(kb + t) * ASTR + mrow + g + 8];
            al[2] = Alc[(kb + t + 4) * ASTR + mrow + g];
            al[3] = Alc[(kb + t + 4) * ASTR + mrow + g + 8];
#pragma unroll
            for (int nt = 0; nt < 12; nt++) {
                const unsigned* bph = &Bhc[(nt * 8 + g) * BSTR + kb];
                const unsigned* bpl = &Blc[(nt * 8 + g) * BSTR + kb];
                unsigned bh0 = bph[t], bh1 = bph[t + 4];
                unsigned bl0 = bpl[t], bl1 = bpl[t + 4];
                mma_bf16(o[nt], ah, bh0, bh1);
                mma_bf16(o[nt], ah, bl0, bl1);
                mma_bf16(o[nt], al, bh0, bh1);
            }
        }
        __syncthreads();
    }

    bool doRound = (j0 >= 192);
    float* op = g_qkv[line] + (size_t)bb * NTOK * 576;
    int tok0 = n0 + mrow + g, tok1 = tok0 + 8;
#pragma unroll
    for (int nt = 0; nt < 12; nt++) {
        int j = j0 + nt * 8 + 2 * t;
        float v0 = o[nt][0], v1 = o[nt][1], v2 = o[nt][2], v3 = o[nt][3];
        if (doRound) {
            v0 = __uint_as_float(f2tf32(v0));
            v1 = __uint_as_float(f2tf32(v1));
            v2 = __uint_as_float(f2tf32(v2));
            v3 = __uint_as_float(f2tf32(v3));
        }
        *(float2*)&op[(size_t)tok0 * 576 + j] = make_float2(v0, v1);
        *(float2*)&op[(size_t)tok1 * 576 + j] = make_float2(v2, v3);
    }
}

// ---------------------------------------------------------------------------
// Kernel 3: CSWin attention (upper line) -- tensor-core flash (R10-passing)
// ---------------------------------------------------------------------------
#define CSKT 56
#define CSSTRIDE 56
#define CSPSTRIDE 60
#define CSMMA_SMEM (4 * CSKT * CSSTRIDE * 4 + 4 * 16 * CSPSTRIDE * 4)   // 65536

__global__ void __launch_bounds__(128) cswin_mma_kernel(float* __restrict__ out) {
    extern __shared__ float csh[];
    float* Ksm[2] = { csh,                    csh + CSKT * CSSTRIDE };
    float* Vsm[2] = { csh + 2 * CSKT * CSSTRIDE, csh + 3 * CSKT * CSSTRIDE };
    unsigned* Pbase = (unsigned*)(csh + 4 * CSKT * CSSTRIDE);

    int qt = blockIdx.x;
    int win = blockIdx.y >> 1, hh = blockIdx.y & 1;
    int bb = blockIdx.z >> 1, br = blockIdx.z & 1;
    int choff = br * CSC + hh * 48;
    const float* qkv = g_qkv[0] + (size_t)bb * NTOK * 576;
    int tid = threadIdx.x;
    int warp = tid >> 5, lane = tid & 31;
    int g = lane >> 2, t = lane & 3;
    int row0 = qt * 64 + warp * 16;
    unsigned* P = Pbase + warp * 16 * CSPSTRIDE;

    auto tok2n = [&](int c) {
        int hl, wl;
        if (br) { hl = c / 56; wl = c - hl * 56; }
        else    { hl = c / 7;  wl = c - hl * 7;  }
        int h = br ? win * 7 + hl : hl;
        int w = br ? wl : win * 7 + wl;
        return h * RES + w;
    };

    unsigned qa[6][4];
    {
        const float qscale = CS_SCALE * LOG2E;
        int r0c = min(row0 + g, 391), r1c = min(row0 + g + 8, 391);
        const float* q0 = qkv + (size_t)tok2n(r0c) * 576 + choff;
        const float* q8 = qkv + (size_t)tok2n(r1c) * 576 + choff;
#pragma unroll
        for (int kc = 0; kc < 6; kc++) {
            qa[kc][0] = f2tf32(q0[kc * 8 + t] * qscale);
            qa[kc][1] = f2tf32(q8[kc * 8 + t] * qscale);
            qa[kc][2] = f2tf32(q0[kc * 8 + t + 4] * qscale);
            qa[kc][3] = f2tf32(q8[kc * 8 + t + 4] * qscale);
        }
    }

    float o[6][4];
#pragma unroll
    for (int nt = 0; nt < 6; nt++)
        o[nt][0] = o[nt][1] = o[nt][2] = o[nt][3] = 0.f;
    float m0 = -1e30f, m1 = -1e30f, l0 = 0.f, l1 = 0.f;

    auto load_tile = [&](int ti, int buf) {
        float* kd = Ksm[buf];
        float* vd = Vsm[buf];
        for (int i = tid; i < 56 * 12; i += 128) {
            int rr = i / 12, c4 = (i % 12) * 4;
            int n = tok2n(ti * CSKT + rr);
            const float* src = qkv + (size_t)n * 576 + choff + c4;
            cp_async16(kd + rr * CSSTRIDE + c4, src + 192);
            cp_async16(vd + rr * CSSTRIDE + c4, src + 384);
        }
        asm volatile("cp.async.commit_group;\n" ::: "memory");
    };

    load_tile(0, 0);

    for (int ti = 0; ti < 7; ti++) {
        int cur = ti & 1;
        if (ti < 6) {
            load_tile(ti + 1, cur ^ 1);
            asm volatile("cp.async.wait_group 1;\n" ::: "memory");
        } else {
            asm volatile("cp.async.wait_group 0;\n" ::: "memory");
        }
        __syncthreads();

        float s[7][4];
#pragma unroll
        for (int nt = 0; nt < 7; nt++) {
            s[nt][0] = s[nt][1] = s[nt][2] = s[nt][3] = 0.f;
            const float* kb = &Ksm[cur][(nt * 8 + g) * CSSTRIDE];
#pragma unroll
            for (int kc = 0; kc < 6; kc++) {
                unsigned b0 = __float_as_uint(kb[kc * 8 + t]);
                unsigned b1 = __float_as_uint(kb[kc * 8 + t + 4]);
                mma_tf32(s[nt], qa[kc], b0, b1);
            }
        }

        float rmax0 = s[0][0], rmax1 = s[0][2];
#pragma unroll
        for (int nt = 0; nt < 7; nt++) {
            rmax0 = fmaxf(rmax0, fmaxf(s[nt][0], s[nt][1]));
            rmax1 = fmaxf(rmax1, fmaxf(s[nt][2], s[nt][3]));
        }
        rmax0 = fmaxf(rmax0, __shfl_xor_sync(0xffffffffu, rmax0, 1));
        rmax0 = fmaxf(rmax0, __shfl_xor_sync(0xffffffffu, rmax0, 2));
        rmax1 = fmaxf(rmax1, __shfl_xor_sync(0xffffffffu, rmax1, 1));
        rmax1 = fmaxf(rmax1, __shfl_xor_sync(0xffffffffu, rmax1, 2));

        float mn0 = fmaxf(m0, rmax0), mn1 = fmaxf(m1, rmax1);
        float rs0 = exp2f(m0 - mn0),  rs1 = exp2f(m1 - mn1);
        l0 *= rs0; l1 *= rs1;

        float psum0 = 0.f, psum1 = 0.f;
#pragma unroll
        for (int nt = 0; nt < 7; nt++) {
            float p0 = exp2f(s[nt][0] - mn0);
            float p1 = exp2f(s[nt][1] - mn0);
            float p2 = exp2f(s[nt][2] - mn1);
            float p3 = exp2f(s[nt][3] - mn1);
            psum0 += p0 + p1; psum1 += p2 + p3;
            P[g * CSPSTRIDE + nt * 8 + 2 * t]           = f2tf32(p0);
            P[g * CSPSTRIDE + nt * 8 + 2 * t + 1]       = f2tf32(p1);
            P[(g + 8) * CSPSTRIDE + nt * 8 + 2 * t]     = f2tf32(p2);
            P[(g + 8) * CSPSTRIDE + nt * 8 + 2 * t + 1] = f2tf32(p3);
        }
        l0 += psum0; l1 += psum1;
#pragma unroll
        for (int nt = 0; nt < 6; nt++) {
            o[nt][0] *= rs0; o[nt][1] *= rs0;
            o[nt][2] *= rs1; o[nt][3] *= rs1;
        }
        m0 = mn0; m1 = mn1;
        __syncwarp();

#pragma unroll
        for (int kc = 0; kc < 7; kc++) {
            unsigned pa[4];
            pa[0] = P[g * CSPSTRIDE + kc * 8 + t];
            pa[1] = P[(g + 8) * CSPSTRIDE + kc * 8 + t];
            pa[2] = P[g * CSPSTRIDE + kc * 8 + t + 4];
            pa[3] = P[(g + 8) * CSPSTRIDE + kc * 8 + t + 4];
            const float* vb0 = &Vsm[cur][(kc * 8 + t) * CSSTRIDE];
            const float* vb1 = &Vsm[cur][(kc * 8 + t + 4) * CSSTRIDE];
#pragma unroll
            for (int nt = 0; nt < 6; nt++) {
                unsigned b0 = __float_as_uint(vb0[nt * 8 + g]);
                unsigned b1 = __float_as_uint(vb1[nt * 8 + g]);
                mma_tf32(o[nt], pa, b0, b1);
            }
        }
        __syncthreads();
    }

    l0 += __shfl_xor_sync(0xffffffffu, l0, 1);
    l0 += __shfl_xor_sync(0xffffffffu, l0, 2);
    l1 += __shfl_xor_sync(0xffffffffu, l1, 1);
    l1 += __shfl_xor_sync(0xffffffffu, l1, 2);
    float inv0 = 1.f / l0, inv1 = 1.f / l1;

    float* ob = out + ((size_t)bb * DIMC + choff) * NTOK;
    int tok0 = row0 + g, tok1 = row0 + g + 8;
    if (tok0 < 392) {
        int n = tok2n(tok0);
#pragma unroll
        for (int nt = 0; nt < 6; nt++) {
            int d0 = nt * 8 + 2 * t;
            ob[(size_t)d0 * NTOK + n]       = o[nt][0] * inv0;
            ob[(size_t)(d0 + 1) * NTOK + n] = o[nt][1] * inv0;
        }
    }
    if (tok1 < 392) {
        int n = tok2n(tok1);
#pragma unroll
        for (int nt = 0; nt < 6; nt++) {
            int d0 = nt * 8 + 2 * t;
            ob[(size_t)d0 * NTOK + n]       = o[nt][2] * inv1;
            ob[(size_t)(d0 + 1) * NTOK + n] = o[nt][3] * inv1;
        }
    }
}

// ---------------------------------------------------------------------------
// Kernel 3b: LePE (depthwise 3x3 on V) -- ADDS into out.  (R10-passing)
// ---------------------------------------------------------------------------
#define LEPE_SMEM (392 * 48 * 4)

__global__ void __launch_bounds__(256) lepe_kernel(const float* __restrict__ lw0,
                                                   const float* __restrict__ lb0,
                                                   const float* __restrict__ lw1,
                                                   const float* __restrict__ lb1,
                                                   float* __restrict__ out) {
    extern __shared__ float Vs[];   // [392][48]
    __shared__ float wsh[48][9];
    __shared__ float bsh[48];

    int win = blockIdx.x;
    int hh  = blockIdx.y;
    int bb  = blockIdx.z >> 1, br = blockIdx.z & 1;
    int SW = br ? 56 : 7;
    int SH = br ? 7 : 56;
    int choff = br * CSC + hh * 48;
    const float* qkv = g_qkv[0] + (size_t)bb * NTOK * 576;
    int tid = threadIdx.x;

    for (int e = tid; e < 392 * 12; e += 256) {
        int tk = e / 12, d4 = (e % 12) * 4;
        int hl, wl;
        if (br) { hl = tk / 56; wl = tk - hl * 56; }
        else    { hl = tk / 7;  wl = tk - hl * 7;  }
        int h = br ? win * 7 + hl : hl;
        int w = br ? wl : win * 7 + wl;
        int n = h * RES + w;
        *(float4*)&Vs[tk * 48 + d4] = *(const float4*)&qkv[(size_t)n * 576 + choff + 384 + d4];
    }
    const float* lw = br ? lw1 : lw0;
    const float* lb = br ? lb1 : lb0;
    for (int e = tid; e < 48 * 9; e += 256) {
        int d = e / 9, k = e % 9;
        wsh[d][k] = lw[(hh * 48 + d) * 9 + k];
    }
    if (tid < 48) bsh[tid] = lb[hh * 48 + tid];
    __syncthreads();

    for (int e = tid; e < 48 * 392; e += 256) {
        int d = e / 392, r = e - d * 392;
        int hl, wl;
        if (br) { hl = r / 56; wl = r - hl * 56; }
        else    { hl = r / 7;  wl = r - hl * 7;  }
        float lep = bsh[d];
#pragma unroll
        for (int dy = -1; dy <= 1; dy++) {
#pragma unroll
            for (int dx = -1; dx <= 1; dx++) {
                int h2 = hl + dy, w2 = wl + dx;
                if (h2 < 0 || h2 >= SH || w2 < 0 || w2 >= SW) continue;
                lep += Vs[(h2 * SW + w2) * 48 + d] * wsh[d][(dy + 1) * 3 + (dx + 1)];
            }
        }
        int h = br ? win * 7 + hl : hl;
        int w = br ? wl : win * 7 + wl;
        int n = h * RES + w;
        out[((size_t)bb * DIMC + choff + d) * NTOK + n] += lep;
    }
}

// ---------------------------------------------------------------------------
// Kernel 4: global attention (lower line), tensor-core flash.
// KT 32 -> 64: halves per-key softmax overhead (shfl chains, rescale,
// syncs).  K stride 68 (conflict-free 4g+t pattern), V stride 72
// (conflict-free 8t+g pattern).  grid (49, 3, 4), block 128,
// dyn smem = (2*64*68 + 2*64*72)*4 = 71680 B.  49 loop iterations.
// ---------------------------------------------------------------------------
#define DKT 64
#define KSTR_K 68
#define KSTR_V 72
#define DPSTR 68
#define DN_SMEM ((2 * DKT * KSTR_K + 2 * DKT * KSTR_V) * 4)   // 71680

__global__ void __launch_bounds__(128) attn_dn_kernel(float* __restrict__ out) {
    extern __shared__ float dnsh[];
    float* Ksb[2] = { dnsh,                 dnsh + DKT * KSTR_K };
    float* Vsb[2] = { dnsh + 2 * DKT * KSTR_K, dnsh + 2 * DKT * KSTR_K + DKT * KSTR_V };
    __shared__ unsigned Psm[4][16 * DPSTR];

    int qt = blockIdx.x, hh = blockIdx.y, bb = blockIdx.z;
    const float* qkv = g_qkv[1] + (size_t)bb * NTOK * 576;
    int tid = threadIdx.x;
    int warp = tid >> 5, lane = tid & 31;
    int g = lane >> 2, t = lane & 3;
    int row0 = qt * 64 + warp * 16;

    unsigned qa[8][4];
    {
        const float qscale = DN_SCALE * LOG2E;
        const float* q0 = qkv + (size_t)(row0 + g) * 576 + hh * 64;
        const float* q8 = qkv + (size_t)(row0 + g + 8) * 576 + hh * 64;
#pragma unroll
        for (int kc = 0; kc < 8; kc++) {
            qa[kc][0] = f2tf32(q0[kc * 8 + t] * qscale);
            qa[kc][1] = f2tf32(q8[kc * 8 + t] * qscale);
            qa[kc][2] = f2tf32(q0[kc * 8 + t + 4] * qscale);
            qa[kc][3] = f2tf32(q8[kc * 8 + t + 4] * qscale);
        }
    }

    float o[8][4];
#pragma unroll
    for (int nt = 0; nt < 8; nt++)
        o[nt][0] = o[nt][1] = o[nt][2] = o[nt][3] = 0.f;
    float m0 = -1e30f, m1 = -1e30f, l0 = 0.f, l1 = 0.f;

    // 64 keys x 16 float4 of K and V = 1024 tasks each; 8 K + 8 V per thread
    auto load_tile = [&](int kt, int buf) {
        float* kd = Ksb[buf];
        float* vd = Vsb[buf];
#pragma unroll
        for (int i = 0; i < 8; i++) {
            int task = tid + i * 128;               // 0..1023
            int rr = task >> 4, chunk = (task & 15) * 4;
            const float* src = qkv + (size_t)(kt * DKT + rr) * 576 + hh * 64 + chunk;
            cp_async16(kd + rr * KSTR_K + chunk, src + 192);
            cp_async16(vd + rr * KSTR_V + chunk, src + 384);
        }
        asm volatile("cp.async.commit_group;\n" ::: "memory");
    };

    load_tile(0, 0);

    for (int kt = 0; kt < 49; kt++) {
        int cur = kt & 1;
        if (kt < 48) {
            load_tile(kt + 1, cur ^ 1);
            asm volatile("cp.async.wait_group 1;\n" ::: "memory");
        } else {
            asm volatile("cp.async.wait_group 0;\n" ::: "memory");
        }
        __syncthreads();

        // S = Q K^T : 8 n-tiles (8 keys) x 8 k-chunks
        float s[8][4];
#pragma unroll
        for (int nt = 0; nt < 8; nt++) {
            s[nt][0] = s[nt][1] = s[nt][2] = s[nt][3] = 0.f;
            const float* kb = &Ksb[cur][(nt * 8 + g) * KSTR_K];
#pragma unroll
            for (int kc = 0; kc < 8; kc++) {
                unsigned b0 = __float_as_uint(kb[kc * 8 + t]);
                unsigned b1 = __float_as_uint(kb[kc * 8 + t + 4]);
                mma_tf32(s[nt], qa[kc], b0, b1);
            }
        }

        float rmax0 = s[0][0], rmax1 = s[0][2];
#pragma unroll
        for (int nt = 0; nt < 8; nt++) {
            rmax0 = fmaxf(rmax0, fmaxf(s[nt][0], s[nt][1]));
            rmax1 = fmaxf(rmax1, fmaxf(s[nt][2], s[nt][3]));
        }
        rmax0 = fmaxf(rmax0, __shfl_xor_sync(0xffffffffu, rmax0, 1));
        rmax0 = fmaxf(rmax0, __shfl_xor_sync(0xffffffffu, rmax0, 2));
        rmax1 = fmaxf(rmax1, __shfl_xor_sync(0xffffffffu, rmax1, 1));
        rmax1 = fmaxf(rmax1, __shfl_xor_sync(0xffffffffu, rmax1, 2));

        float mn0 = fmaxf(m0, rmax0), mn1 = fmaxf(m1, rmax1);
        float rs0 = exp2f(m0 - mn0),  rs1 = exp2f(m1 - mn1);
        l0 *= rs0; l1 *= rs1;

        unsigned* P = Psm[warp];
        float psum0 = 0.f, psum1 = 0.f;
#pragma unroll
        for (int nt = 0; nt < 8; nt++) {
            float p0 = exp2f(s[nt][0] - mn0);
            float p1 = exp2f(s[nt][1] - mn0);
            float p2 = exp2f(s[nt][2] - mn1);
            float p3 = exp2f(s[nt][3] - mn1);
            psum0 += p0 + p1; psum1 += p2 + p3;
            P[g * DPSTR + nt * 8 + 2 * t]           = f2tf32(p0);
            P[g * DPSTR + nt * 8 + 2 * t + 1]       = f2tf32(p1);
            P[(g + 8) * DPSTR + nt * 8 + 2 * t]     = f2tf32(p2);
            P[(g + 8) * DPSTR + nt * 8 + 2 * t + 1] = f2tf32(p3);
        }
        l0 += psum0; l1 += psum1;
#pragma unroll
        for (int nt = 0; nt < 8; nt++) {
            o[nt][0] *= rs0; o[nt][1] *= rs0;
            o[nt][2] *= rs1; o[nt][3] *= rs1;
        }
        m0 = mn0; m1 = mn1;
        __syncwarp();

        // O += P V : 8 k-chunks (8 keys) x 8 n-tiles (8 dims)
#pragma unroll
        for (int kc = 0; kc < 8; kc++) {
            unsigned pa[4];
            pa[0] = P[g * DPSTR + kc * 8 + t];
            pa[1] = P[(g + 8) * DPSTR + kc * 8 + t];
            pa[2] = P[g * DPSTR + kc * 8 + t + 4];
            pa[3] = P[(g + 8) * DPSTR + kc * 8 + t + 4];
            const float* vb0 = &Vsb[cur][(kc * 8 + t) * KSTR_V];
            const float* vb1 = &Vsb[cur][(kc * 8 + t + 4) * KSTR_V];
#pragma unroll
            for (int nt = 0; nt < 8; nt++) {
                unsigned b0 = __float_as_uint(vb0[nt * 8 + g]);
                unsigned b1 = __float_as_uint(vb1[nt * 8 + g]);
                mma_tf32(o[nt], pa, b0, b1);
            }
        }
        __syncthreads();
    }

    l0 += __shfl_xor_sync(0xffffffffu, l0, 1);
    l0 += __shfl_xor_sync(0xffffffffu, l0, 2);
    l1 += __shfl_xor_sync(0xffffffffu, l1, 1);
    l1 += __shfl_xor_sync(0xffffffffu, l1, 2);
    float inv0 = 1.f / l0, inv1 = 1.f / l1;

    float* ob = out + ((size_t)bb * DIMC + TD + hh * 64) * NTOK;
    int tok0 = row0 + g, tok1 = row0 + g + 8;
#pragma unroll
    for (int nt = 0; nt < 8; nt++) {
        int d0 = nt * 8 + 2 * t;
        ob[(size_t)d0 * NTOK + tok0]       = o[nt][0] * inv0;
        ob[(size_t)(d0 + 1) * NTOK + tok0] = o[nt][1] * inv0;
        ob[(size_t)d0 * NTOK + tok1]       = o[nt][2] * inv1;
        ob[(size_t)(d0 + 1) * NTOK + tok1] = o[nt][3] * inv1;
    }
}

// ---------------------------------------------------------------------------
// Launch: 2-stream DAG with capture-safe event fork/join (R15-passing).
// ---------------------------------------------------------------------------
static cudaStream_t g_s2 = 0;
static cudaEvent_t  g_eB = 0, g_eC = 0, g_e0 = 0, g_eL = 0;

extern "C" void kernel_launch(void* const* d_in, const int* in_sizes, int n_in,
                              void* d_out, int out_size) {
    const float* xa      = (const float*)d_in[0];
    const float* proj1_w = (const float*)d_in[1];
    const float* proj2_w = (const float*)d_in[2];
    const float* qkv_u_w = (const float*)d_in[3];
    const float* qkv_d_w = (const float*)d_in[4];
    const float* lepe_w0 = (const float*)d_in[5];
    const float* lepe_b0 = (const float*)d_in[6];
    const float* lepe_w1 = (const float*)d_in[7];
    const float* lepe_b1 = (const float*)d_in[8];
    float* out = (float*)d_out;

    if (g_s2 == 0) {   // one-time host-side resource setup (no device memory)
        cudaStreamCreateWithFlags(&g_s2, cudaStreamNonBlocking);
        cudaEventCreateWithFlags(&g_eB, cudaEventDisableTiming);
        cudaEventCreateWithFlags(&g_eC, cudaEventDisableTiming);
        cudaEventCreateWithFlags(&g_e0, cudaEventDisableTiming);
        cudaEventCreateWithFlags(&g_eL, cudaEventDisableTiming);
        cudaFuncSetAttribute(qkv_mma_kernel, cudaFuncAttributeMaxDynamicSharedMemorySize, QKV_SMEM);
        cudaFuncSetAttribute(cswin_mma_kernel, cudaFuncAttributeMaxDynamicSharedMemorySize, CSMMA_SMEM);
        cudaFuncSetAttribute(lepe_kernel, cudaFuncAttributeMaxDynamicSharedMemorySize, LEPE_SMEM);
        cudaFuncSetAttribute(attn_dn_kernel, cudaFuncAttributeMaxDynamicSharedMemorySize, DN_SMEM);
    }

    // fork s2 from the main (capturing) stream
    cudaEventRecord(g_eB, 0);
    cudaStreamWaitEvent(g_s2, g_eB, 0);

    // s0: split xa;  s2: combined weights (independent)
    split_xa_kernel<<<(NB * 192 * (NTOK / 4) + 255) / 256, 256>>>(xa);
    combine_w_kernel<<<dim3(576, 2), 192, 0, g_s2>>>(proj1_w, proj2_w, qkv_u_w, qkv_d_w);
    cudaEventRecord(g_eC, g_s2);
    cudaStreamWaitEvent(0, g_eC, 0);

    // s0: gemm line 0 (feeds upper line)
    qkv_mma_kernel<<<dim3(49, 6, 4), 128, QKV_SMEM>>>(0);
    cudaEventRecord(g_e0, 0);

    // s2: cswin + lepe on line-0 results, concurrent with line-1 work on s0
    cudaStreamWaitEvent(g_s2, g_e0, 0);
    cswin_mma_kernel<<<dim3(7, 16, 8), 128, CSMMA_SMEM, g_s2>>>(out);
    lepe_kernel<<<dim3(8, 2, 8), 256, LEPE_SMEM, g_s2>>>(lepe_w0, lepe_b0, lepe_w1, lepe_b1, out);
    cudaEventRecord(g_eL, g_s2);

    // s0: gemm line 1 -> global attention (KT=64)
    qkv_mma_kernel<<<dim3(49, 6, 4), 128, QKV_SMEM>>>(1);
    attn_dn_kernel<<<dim3(49, 3, 4), 128, DN_SMEM>>>(out);

    // join s2 back into the main stream
    cudaStreamWaitEvent(0, g_eL, 0);
}